// round 4
// baseline (speedup 1.0000x reference)
#include <cuda_runtime.h>
#include <math.h>
#include <stdint.h>

#define B    512
#define NP   200
#define EPG  2000
#define E_TOT (B*EPG)      // 1,024,000
#define N0   (B*NP)        // 102,400
#define HID  128
#define EMB  9
#define K1   160
#define K2   128
#define K3   103

#define INV_E 0xFFFFu

// ---------------- static device scratch --------------------------------------
__device__ float g_a1[N0*18];      // level-1 [mean(9) | x(9)] interleaved
__device__ float g_x[N0*HID];      // conv1 output
__device__ float g_sdot[N0];       // conv1 fused score dot

// ---------------- embedding gather -------------------------------------------
__global__ void gather_kernel(const int* __restrict__ node_ids,
                              const float* __restrict__ emb) {
    int t = blockIdx.x * blockDim.x + threadIdx.x;
    if (t < N0*EMB) {
        int i = t / EMB, e = t % EMB;
        g_a1[i*18 + 9 + e] = emb[node_ids[i]*EMB + e];
    }
}

// ---------------- level-1 aggregation (one block per graph) ------------------
__global__ void aggE_kernel(const int* __restrict__ edge_index) {
    __shared__ int hist[NP];
    __shared__ int off[NP+1];
    __shared__ int cur[NP];
    __shared__ unsigned short ssrc[EPG];

    int b = blockIdx.x, tid = threadIdx.x;   // 256 threads
    int ebase = b * EPG;
    int nbase = b * NP;

    for (int i = tid; i < NP; i += 256) hist[i] = 0;
    __syncthreads();
    for (int e = tid; e < EPG; e += 256)
        atomicAdd(&hist[edge_index[E_TOT + ebase + e] - nbase], 1);
    __syncthreads();
    if (tid == 0) {
        int a = 0;
        for (int v = 0; v < NP; v++) { off[v] = a; a += hist[v]; }
        off[NP] = a;
    }
    __syncthreads();
    for (int i = tid; i < NP; i += 256) cur[i] = off[i];
    __syncthreads();
    for (int e = tid; e < EPG; e += 256) {
        int dl = edge_index[E_TOT + ebase + e] - nbase;
        int sl = edge_index[ebase + e] - nbase;
        int p  = atomicAdd(&cur[dl], 1);
        ssrc[p] = (unsigned short)sl;
    }
    __syncthreads();

    int warp = tid >> 5, lane = tid & 31;
    for (int v = warp; v < NP; v += 8) {
        int e0 = off[v], e1 = off[v+1];
        float inv = (e1 > e0) ? 1.0f / (float)(e1 - e0) : 0.0f;
        if (lane < EMB) {
            float a = 0.0f;
            for (int e = e0; e < e1; e++)
                a += g_a1[(size_t)(nbase + ssrc[e]) * 18 + 9 + lane];
            g_a1[(size_t)(nbase + v) * 18 + lane] = a * inv;
        }
    }
}

// ---------------- tf32 mma primitive -----------------------------------------
__device__ __forceinline__ void mma_tf32(float c[4], uint32_t a0, uint32_t a1,
                                         uint32_t a2, uint32_t a3,
                                         uint32_t b0, uint32_t b1) {
    asm volatile(
        "mma.sync.aligned.m16n8k8.row.col.f32.tf32.tf32.f32 "
        "{%0,%1,%2,%3}, {%4,%5,%6,%7}, {%8,%9}, {%0,%1,%2,%3};"
        : "+f"(c[0]), "+f"(c[1]), "+f"(c[2]), "+f"(c[3])
        : "r"(a0), "r"(a1), "r"(a2), "r"(a3), "r"(b0), "r"(b1));
}

// ---------------- conv1 GEMM: K=18 (padded 24) -------------------------------
__global__ __launch_bounds__(256) void conv1_gemm(
        const float* __restrict__ w1n,
        const float* __restrict__ w1r,
        const float* __restrict__ b1,
        const float* __restrict__ pvec) {
    __shared__ float As[128][36];
    __shared__ float Ws[128][36];
    __shared__ float bb[128];
    __shared__ float ps[128];
    __shared__ float sdot[128];

    int tid  = threadIdx.x;
    int lane = tid & 31;
    int wid  = tid >> 5;
    int wm   = wid & 3;
    int wn_  = wid >> 2;
    int row0 = blockIdx.x * 128;

    if (tid < 128) { bb[tid] = b1[tid]; ps[tid] = pvec[tid]; sdot[tid] = 0.0f; }

    // branch-light staging: A rows contiguous 18 floats, pad cols 18-23 with 0
    for (int idx = tid; idx < 128*24; idx += 256) {
        int r = idx / 24, c = idx - r*24;
        As[r][c] = (c < 18) ? g_a1[(size_t)(row0 + r) * 18 + c] : 0.0f;
        float wv = 0.0f;
        if (c < 9)       wv = w1n[r*9 + c];
        else if (c < 18) wv = w1r[r*9 + (c - 9)];
        Ws[r][c] = wv;
    }
    __syncthreads();

    float acc[2][8][4];
#pragma unroll
    for (int mt = 0; mt < 2; mt++)
#pragma unroll
        for (int nt = 0; nt < 8; nt++)
#pragma unroll
            for (int i = 0; i < 4; i++) acc[mt][nt][i] = 0.0f;

#pragma unroll
    for (int ks = 0; ks < 24; ks += 8) {
        uint32_t a[2][4];
#pragma unroll
        for (int mt = 0; mt < 2; mt++) {
            int r = wm * 32 + mt * 16 + (lane >> 2);
            int c = ks + (lane & 3);
            a[mt][0] = __float_as_uint(As[r][c]);
            a[mt][1] = __float_as_uint(As[r + 8][c]);
            a[mt][2] = __float_as_uint(As[r][c + 4]);
            a[mt][3] = __float_as_uint(As[r + 8][c + 4]);
        }
#pragma unroll
        for (int nt = 0; nt < 8; nt++) {
            int n = wn_ * 64 + nt * 8 + (lane >> 2);
            int c = ks + (lane & 3);
            uint32_t b0 = __float_as_uint(Ws[n][c]);
            uint32_t b1 = __float_as_uint(Ws[n][c + 4]);
            mma_tf32(acc[0][nt], a[0][0], a[0][1], a[0][2], a[0][3], b0, b1);
            mma_tf32(acc[1][nt], a[1][0], a[1][1], a[1][2], a[1][3], b0, b1);
        }
    }
    __syncthreads();

    // epilogue: bias+relu -> g_x, fused score dot -> g_sdot (2 contributions/row,
    // float add is commutative so smem atomic order doesn't change the result)
#pragma unroll
    for (int mt = 0; mt < 2; mt++) {
        float pd0 = 0.0f, pd1 = 0.0f;
        int rr = wm * 32 + mt * 16 + (lane >> 2);
#pragma unroll
        for (int nt = 0; nt < 8; nt++) {
            int col = wn_ * 64 + nt * 8 + 2 * (lane & 3);
            float v00 = fmaxf(acc[mt][nt][0] + bb[col],     0.0f);
            float v01 = fmaxf(acc[mt][nt][1] + bb[col + 1], 0.0f);
            float v10 = fmaxf(acc[mt][nt][2] + bb[col],     0.0f);
            float v11 = fmaxf(acc[mt][nt][3] + bb[col + 1], 0.0f);
            *(float2*)&g_x[(size_t)(row0 + rr) * 128 + col]     = make_float2(v00, v01);
            *(float2*)&g_x[(size_t)(row0 + rr + 8) * 128 + col] = make_float2(v10, v11);
            pd0 += v00 * ps[col] + v01 * ps[col + 1];
            pd1 += v10 * ps[col] + v11 * ps[col + 1];
        }
        pd0 += __shfl_xor_sync(0xffffffffu, pd0, 1);
        pd0 += __shfl_xor_sync(0xffffffffu, pd0, 2);
        pd1 += __shfl_xor_sync(0xffffffffu, pd1, 1);
        pd1 += __shfl_xor_sync(0xffffffffu, pd1, 2);
        if ((lane & 3) == 0) {
            atomicAdd(&sdot[rr], pd0);
            atomicAdd(&sdot[rr + 8], pd1);
        }
    }
    __syncthreads();
    if (tid < 128) g_sdot[row0 + tid] = sdot[tid];
}

// ---------------- mega kernel: one block per graph ---------------------------
// topk1 -> [agg -> gemm -> topk] x2 -> mlp head. All state in smem.
struct MegaSm {
    float xs[160][132];      // current pooled features
    float ms[160][132];      // mean / gemm output
    float wst[128][36];      // W k-chunk stage
    float s[200];            // scores
    float sdot[160];
    float bb[128];
    float ps[128];
    float harr[256];         // readout accumulator x1+x2+x3
    float pmax[2][128];
    float psum[2][128];
    float h1[128];
    float h2[64];
    float rns[3];
    int   hist[161];
    int   off[161];
    int   cur[161];
    unsigned short esrc[EPG];
    unsigned short edst[EPG];
    unsigned short eord[EPG];
    short newloc[200];
    short kept[160];
};

__device__ __forceinline__ void level_agg(MegaSm* S, int n) {
    int tid = threadIdx.x;
    for (int i = tid; i < n; i += 320) S->hist[i] = 0;
    __syncthreads();
    for (int e = tid; e < EPG; e += 320)
        if (S->esrc[e] != INV_E) atomicAdd(&S->hist[S->edst[e]], 1);
    __syncthreads();
    if (tid == 0) {
        int a = 0;
        for (int v = 0; v < n; v++) { S->off[v] = a; a += S->hist[v]; }
        S->off[n] = a;
    }
    __syncthreads();
    for (int i = tid; i < n; i += 320) S->cur[i] = S->off[i];
    __syncthreads();
    for (int e = tid; e < EPG; e += 320)
        if (S->esrc[e] != INV_E) {
            int p = atomicAdd(&S->cur[S->edst[e]], 1);
            S->eord[p] = S->esrc[e];
        }
    __syncthreads();
    int w = tid >> 5, lane = tid & 31;
    for (int v = w; v < n; v += 10) {
        int e0 = S->off[v], e1 = S->off[v+1];
        float inv = (e1 > e0) ? 1.0f / (float)(e1 - e0) : 0.0f;
        float a0 = 0.f, a1 = 0.f, a2 = 0.f, a3 = 0.f;
        for (int e = e0; e < e1; e++) {
            const float* xp = S->xs[S->eord[e]];
            a0 += xp[lane];      a1 += xp[lane + 32];
            a2 += xp[lane + 64]; a3 += xp[lane + 96];
        }
        S->ms[v][lane]      = a0 * inv; S->ms[v][lane + 32] = a1 * inv;
        S->ms[v][lane + 64] = a2 * inv; S->ms[v][lane + 96] = a3 * inv;
    }
    __syncthreads();
}

// GEMM: ms(out rows) = relu([ms | xs](n x 256) @ [Wn|Wr]^T + bb); sdot = rows . ps
__device__ __forceinline__ void level_gemm(MegaSm* S, int n,
                                           const float* __restrict__ Wn,
                                           const float* __restrict__ Wr) {
    int tid = threadIdx.x, lane = tid & 31, w = tid >> 5;
    bool active = (w * 16 < n);
    float acc[16][4];
#pragma unroll
    for (int nt = 0; nt < 16; nt++)
#pragma unroll
        for (int i = 0; i < 4; i++) acc[nt][i] = 0.0f;

    for (int kc = 0; kc < 256; kc += 32) {
        const float* Wg = (kc < 128) ? Wn : Wr;
        int kg = kc & 127;
        for (int idx = tid; idx < 1024; idx += 320) {
            int r = idx >> 3, q = idx & 7;
            *(float4*)&S->wst[r][q*4] = *(const float4*)&Wg[r*128 + kg + q*4];
        }
        __syncthreads();
        if (active) {
            const float (*Asrc)[132] = (kc < 128) ? S->ms : S->xs;
#pragma unroll
            for (int ks = 0; ks < 32; ks += 8) {
                int r = w * 16 + (lane >> 2);
                int c = kg + ks + (lane & 3);
                uint32_t a0 = __float_as_uint(Asrc[r][c]);
                uint32_t a1 = __float_as_uint(Asrc[r + 8][c]);
                uint32_t a2 = __float_as_uint(Asrc[r][c + 4]);
                uint32_t a3 = __float_as_uint(Asrc[r + 8][c + 4]);
#pragma unroll
                for (int nt = 0; nt < 16; nt++) {
                    int nr = nt * 8 + (lane >> 2);
                    int cc = ks + (lane & 3);
                    uint32_t b0 = __float_as_uint(S->wst[nr][cc]);
                    uint32_t b1 = __float_as_uint(S->wst[nr][cc + 4]);
                    mma_tf32(acc[nt], a0, a1, a2, a3, b0, b1);
                }
            }
        }
        __syncthreads();
    }

    if (active) {
        float pd0 = 0.0f, pd1 = 0.0f;
        int r = w * 16 + (lane >> 2);
#pragma unroll
        for (int nt = 0; nt < 16; nt++) {
            int col = nt * 8 + 2 * (lane & 3);
            float v00 = fmaxf(acc[nt][0] + S->bb[col],     0.0f);
            float v01 = fmaxf(acc[nt][1] + S->bb[col + 1], 0.0f);
            float v10 = fmaxf(acc[nt][2] + S->bb[col],     0.0f);
            float v11 = fmaxf(acc[nt][3] + S->bb[col + 1], 0.0f);
            *(float2*)&S->ms[r][col]     = make_float2(v00, v01);
            *(float2*)&S->ms[r + 8][col] = make_float2(v10, v11);
            pd0 += v00 * S->ps[col] + v01 * S->ps[col + 1];
            pd1 += v10 * S->ps[col] + v11 * S->ps[col + 1];
        }
        pd0 += __shfl_xor_sync(0xffffffffu, pd0, 1);
        pd0 += __shfl_xor_sync(0xffffffffu, pd0, 2);
        pd1 += __shfl_xor_sync(0xffffffffu, pd1, 1);
        pd1 += __shfl_xor_sync(0xffffffffu, pd1, 2);
        if ((lane & 3) == 0) { S->sdot[r] = pd0; S->sdot[r + 8] = pd1; }
    }
    __syncthreads();
}

__device__ __forceinline__ void level_rank(MegaSm* S, int n, int k) {
    int tid = threadIdx.x;
    for (int v = tid; v < n; v += 320) {
        float sv = S->s[v];
        int r = 0;
        for (int u = 0; u < n; u++) {
            float su = S->s[u];
            r += (su > sv) || (su == sv && u < v);
        }
        S->newloc[v] = (r < k) ? (short)r : (short)-1;
        if (r < k) S->kept[r] = (short)v;
    }
    __syncthreads();
}

__device__ __forceinline__ void level_remap(MegaSm* S) {
    int tid = threadIdx.x;
    for (int e = tid; e < EPG; e += 320) {
        unsigned short sv = S->esrc[e];
        if (sv != INV_E) {
            short ns = S->newloc[sv];
            short nd = S->newloc[S->edst[e]];
            if (ns < 0 || nd < 0) S->esrc[e] = INV_E;
            else { S->esrc[e] = (unsigned short)ns; S->edst[e] = (unsigned short)nd; }
        }
    }
    __syncthreads();
}

__device__ __forceinline__ void pool_from_ms(MegaSm* S, int k) {
    int tid = threadIdx.x;
    if (tid < 128) {
        float mx = -INFINITY, sm = 0.0f;
        for (int r = 0; r < k; r++) {
            int v = S->kept[r];
            float val = S->ms[v][tid] * S->s[v];
            S->xs[r][tid] = val;
            mx = fmaxf(mx, val);
            sm += val;
        }
        S->harr[tid]       += mx;
        S->harr[128 + tid] += sm / (float)k;
    }
    __syncthreads();
}

__global__ __launch_bounds__(320, 1) void mega_kernel(
        const int* __restrict__ edge_index,
        const float* __restrict__ p1,
        const float* __restrict__ w2n, const float* __restrict__ w2r,
        const float* __restrict__ b2,  const float* __restrict__ p2,
        const float* __restrict__ w3n, const float* __restrict__ w3r,
        const float* __restrict__ b3,  const float* __restrict__ p3,
        const float* __restrict__ lw1, const float* __restrict__ lb1,
        const float* __restrict__ lw2, const float* __restrict__ lb2,
        const float* __restrict__ lw3, const float* __restrict__ lb3,
        float* __restrict__ out) {
    extern __shared__ char raw[];
    MegaSm* S = (MegaSm*)raw;

    int b = blockIdx.x, tid = threadIdx.x;
    int w = tid >> 5, lane = tid & 31;

    // load edges local
    for (int e = tid; e < EPG; e += 320) {
        S->esrc[e] = (unsigned short)(edge_index[b*EPG + e] - b*NP);
        S->edst[e] = (unsigned short)(edge_index[E_TOT + b*EPG + e] - b*NP);
    }
    // 1/||p|| for the three pool vectors
    if (w < 3) {
        const float* pv = (w == 0) ? p1 : ((w == 1) ? p2 : p3);
        float v = pv[lane]*pv[lane] + pv[lane+32]*pv[lane+32]
                + pv[lane+64]*pv[lane+64] + pv[lane+96]*pv[lane+96];
#pragma unroll
        for (int o = 16; o; o >>= 1) v += __shfl_down_sync(0xffffffffu, v, o);
        if (lane == 0) S->rns[w] = 1.0f / sqrtf(v);
    }
    if (tid < 256) S->harr[tid] = 0.0f;
    __syncthreads();

    // ---------- topk1 ----------
    for (int v = tid; v < NP; v += 320)
        S->s[v] = tanhf(g_sdot[b*NP + v] * S->rns[0]);
    __syncthreads();
    level_rank(S, NP, K1);

    // x_new1 from global g_x + pool1 (split over 256 threads)
    if (tid < 256) {
        int d = tid & 127, half = tid >> 7;
        float mx = -INFINITY, sm = 0.0f;
        for (int r = half; r < K1; r += 2) {
            int v = S->kept[r];
            float val = g_x[(size_t)(b*NP + v) * 128 + d] * S->s[v];
            S->xs[r][d] = val;
            mx = fmaxf(mx, val);
            sm += val;
        }
        S->pmax[half][d] = mx;
        S->psum[half][d] = sm;
    }
    __syncthreads();
    if (tid < 128) {
        S->harr[tid]       += fmaxf(S->pmax[0][tid], S->pmax[1][tid]);
        S->harr[128 + tid] += (S->psum[0][tid] + S->psum[1][tid]) / (float)K1;
    }
    level_remap(S);

    // ---------- level 2 ----------
    if (tid < 128) { S->bb[tid] = b2[tid]; S->ps[tid] = p2[tid]; }
    __syncthreads();
    level_agg(S, K1);
    level_gemm(S, K1, w2n, w2r);
    for (int v = tid; v < K1; v += 320)
        S->s[v] = tanhf(S->sdot[v] * S->rns[1]);
    __syncthreads();
    level_rank(S, K1, K2);
    pool_from_ms(S, K2);
    level_remap(S);

    // ---------- level 3 ----------
    if (tid < 128) { S->bb[tid] = b3[tid]; S->ps[tid] = p3[tid]; }
    __syncthreads();
    level_agg(S, K2);
    level_gemm(S, K2, w3n, w3r);
    for (int v = tid; v < K2; v += 320)
        S->s[v] = tanhf(S->sdot[v] * S->rns[2]);
    __syncthreads();
    level_rank(S, K2, K3);
    pool_from_ms(S, K3);

    // ---------- MLP head ----------
    if (tid < 128) {
        float acc = lb1[tid];
        const float* wrow = lw1 + tid * 256;
#pragma unroll 8
        for (int k = 0; k < 256; k++) acc += S->harr[k] * wrow[k];
        S->h1[tid] = fmaxf(acc, 0.0f);
    }
    __syncthreads();
    if (tid < 64) {
        float acc = lb2[tid];
        const float* wrow = lw2 + tid * 128;
#pragma unroll 8
        for (int k = 0; k < 128; k++) acc += S->h1[k] * wrow[k];
        S->h2[tid] = fmaxf(acc, 0.0f);
    }
    __syncthreads();
    if (tid == 0) {
        float acc = lb3[0];
#pragma unroll 8
        for (int k = 0; k < 64; k++) acc += S->h2[k] * lw3[k];
        out[b] = 1.0f / (1.0f + expf(-acc));
    }
}

// ---------------- launch ------------------------------------------------------
extern "C" void kernel_launch(void* const* d_in, const int* in_sizes, int n_in,
                              void* d_out, int out_size) {
    const int*   node_ids   = (const int*)d_in[0];
    const int*   edge_index = (const int*)d_in[1];
    const float* emb  = (const float*)d_in[3];
    const float* w1n  = (const float*)d_in[4];
    const float* w1r  = (const float*)d_in[5];
    const float* b1   = (const float*)d_in[6];
    const float* w2n  = (const float*)d_in[7];
    const float* w2r  = (const float*)d_in[8];
    const float* b2   = (const float*)d_in[9];
    const float* w3n  = (const float*)d_in[10];
    const float* w3r  = (const float*)d_in[11];
    const float* b3   = (const float*)d_in[12];
    const float* p1   = (const float*)d_in[13];
    const float* p2   = (const float*)d_in[14];
    const float* p3   = (const float*)d_in[15];
    const float* lw1  = (const float*)d_in[16];
    const float* lb1  = (const float*)d_in[17];
    const float* lw2  = (const float*)d_in[18];
    const float* lb2  = (const float*)d_in[19];
    const float* lw3  = (const float*)d_in[20];
    const float* lb3  = (const float*)d_in[21];
    float* out = (float*)d_out;

    static int smem_set = 0;
    if (!smem_set) {
        cudaFuncSetAttribute(mega_kernel,
                             cudaFuncAttributeMaxDynamicSharedMemorySize,
                             (int)sizeof(MegaSm));
        smem_set = 1;
    }

    gather_kernel<<<(N0*EMB + 255)/256, 256>>>(node_ids, emb);
    aggE_kernel<<<B, 256>>>(edge_index);
    conv1_gemm<<<N0/128, 256>>>(w1n, w1r, b1, p1);
    mega_kernel<<<B, 320, sizeof(MegaSm)>>>(
        edge_index, p1,
        w2n, w2r, b2, p2,
        w3n, w3r, b3, p3,
        lw1, lb1, lw2, lb2, lw3, lb3, out);
}

// round 5
// speedup vs baseline: 1.3805x; 1.3805x over previous
#include <cuda_runtime.h>
#include <math.h>
#include <stdint.h>

#define B    512
#define NP   200
#define EPG  2000
#define E_TOT (B*EPG)      // 1,024,000
#define N0   (B*NP)        // 102,400
#define HID  128
#define EMB  9
#define K1   160
#define K2   128
#define K3   103

#define NT   384           // mega threads
#define NW   12            // mega warps
#define INV_E 0xFFFFu

// ---------------- static device scratch --------------------------------------
__device__ float g_a1[N0*18];      // level-1 [mean(9) | x(9)] interleaved
__device__ float g_x[N0*HID];      // conv1 output
__device__ float g_sdot[N0];       // conv1 fused score dot

// ---------------- embedding gather -------------------------------------------
__global__ void gather_kernel(const int* __restrict__ node_ids,
                              const float* __restrict__ emb) {
    int t = blockIdx.x * blockDim.x + threadIdx.x;
    if (t < N0*EMB) {
        int i = t / EMB, e = t % EMB;
        g_a1[i*18 + 9 + e] = emb[node_ids[i]*EMB + e];
    }
}

// ---------------- level-1 aggregation (one block per graph) ------------------
__global__ void aggE_kernel(const int* __restrict__ edge_index) {
    __shared__ int hist[NP];
    __shared__ int off[NP+1];
    __shared__ int cur[NP];
    __shared__ unsigned short ssrc[EPG];

    int b = blockIdx.x, tid = threadIdx.x;   // 256 threads
    int ebase = b * EPG;
    int nbase = b * NP;

    for (int i = tid; i < NP; i += 256) hist[i] = 0;
    __syncthreads();
    for (int e = tid; e < EPG; e += 256)
        atomicAdd(&hist[edge_index[E_TOT + ebase + e] - nbase], 1);
    __syncthreads();
    if (tid == 0) {
        int a = 0;
        for (int v = 0; v < NP; v++) { off[v] = a; a += hist[v]; }
        off[NP] = a;
    }
    __syncthreads();
    for (int i = tid; i < NP; i += 256) cur[i] = off[i];
    __syncthreads();
    for (int e = tid; e < EPG; e += 256) {
        int dl = edge_index[E_TOT + ebase + e] - nbase;
        int sl = edge_index[ebase + e] - nbase;
        int p  = atomicAdd(&cur[dl], 1);
        ssrc[p] = (unsigned short)sl;
    }
    __syncthreads();

    int warp = tid >> 5, lane = tid & 31;
    for (int v = warp; v < NP; v += 8) {
        int e0 = off[v], e1 = off[v+1];
        float inv = (e1 > e0) ? 1.0f / (float)(e1 - e0) : 0.0f;
        if (lane < EMB) {
            float a = 0.0f;
            for (int e = e0; e < e1; e++)
                a += g_a1[(size_t)(nbase + ssrc[e]) * 18 + 9 + lane];
            g_a1[(size_t)(nbase + v) * 18 + lane] = a * inv;
        }
    }
}

// ---------------- tf32 mma primitive -----------------------------------------
__device__ __forceinline__ void mma_tf32(float c[4], uint32_t a0, uint32_t a1,
                                         uint32_t a2, uint32_t a3,
                                         uint32_t b0, uint32_t b1) {
    asm volatile(
        "mma.sync.aligned.m16n8k8.row.col.f32.tf32.tf32.f32 "
        "{%0,%1,%2,%3}, {%4,%5,%6,%7}, {%8,%9}, {%0,%1,%2,%3};"
        : "+f"(c[0]), "+f"(c[1]), "+f"(c[2]), "+f"(c[3])
        : "r"(a0), "r"(a1), "r"(a2), "r"(a3), "r"(b0), "r"(b1));
}

// ---------------- conv1 GEMM: K=18 (padded 24) -------------------------------
__global__ __launch_bounds__(256) void conv1_gemm(
        const float* __restrict__ w1n,
        const float* __restrict__ w1r,
        const float* __restrict__ b1,
        const float* __restrict__ pvec) {
    __shared__ float As[128][36];
    __shared__ float Ws[128][36];
    __shared__ float bb[128];
    __shared__ float ps[128];
    __shared__ float sdot[128];

    int tid  = threadIdx.x;
    int lane = tid & 31;
    int wid  = tid >> 5;
    int wm   = wid & 3;
    int wn_  = wid >> 2;
    int row0 = blockIdx.x * 128;

    if (tid < 128) { bb[tid] = b1[tid]; ps[tid] = pvec[tid]; sdot[tid] = 0.0f; }

    for (int idx = tid; idx < 128*24; idx += 256) {
        int r = idx / 24, c = idx - r*24;
        As[r][c] = (c < 18) ? g_a1[(size_t)(row0 + r) * 18 + c] : 0.0f;
        float wv = 0.0f;
        if (c < 9)       wv = w1n[r*9 + c];
        else if (c < 18) wv = w1r[r*9 + (c - 9)];
        Ws[r][c] = wv;
    }
    __syncthreads();

    float acc[2][8][4];
#pragma unroll
    for (int mt = 0; mt < 2; mt++)
#pragma unroll
        for (int nt = 0; nt < 8; nt++)
#pragma unroll
            for (int i = 0; i < 4; i++) acc[mt][nt][i] = 0.0f;

#pragma unroll
    for (int ks = 0; ks < 24; ks += 8) {
        uint32_t a[2][4];
#pragma unroll
        for (int mt = 0; mt < 2; mt++) {
            int r = wm * 32 + mt * 16 + (lane >> 2);
            int c = ks + (lane & 3);
            a[mt][0] = __float_as_uint(As[r][c]);
            a[mt][1] = __float_as_uint(As[r + 8][c]);
            a[mt][2] = __float_as_uint(As[r][c + 4]);
            a[mt][3] = __float_as_uint(As[r + 8][c + 4]);
        }
#pragma unroll
        for (int nt = 0; nt < 8; nt++) {
            int n = wn_ * 64 + nt * 8 + (lane >> 2);
            int c = ks + (lane & 3);
            uint32_t b0 = __float_as_uint(Ws[n][c]);
            uint32_t b1 = __float_as_uint(Ws[n][c + 4]);
            mma_tf32(acc[0][nt], a[0][0], a[0][1], a[0][2], a[0][3], b0, b1);
            mma_tf32(acc[1][nt], a[1][0], a[1][1], a[1][2], a[1][3], b0, b1);
        }
    }
    __syncthreads();

#pragma unroll
    for (int mt = 0; mt < 2; mt++) {
        float pd0 = 0.0f, pd1 = 0.0f;
        int rr = wm * 32 + mt * 16 + (lane >> 2);
#pragma unroll
        for (int nt = 0; nt < 8; nt++) {
            int col = wn_ * 64 + nt * 8 + 2 * (lane & 3);
            float v00 = fmaxf(acc[mt][nt][0] + bb[col],     0.0f);
            float v01 = fmaxf(acc[mt][nt][1] + bb[col + 1], 0.0f);
            float v10 = fmaxf(acc[mt][nt][2] + bb[col],     0.0f);
            float v11 = fmaxf(acc[mt][nt][3] + bb[col + 1], 0.0f);
            *(float2*)&g_x[(size_t)(row0 + rr) * 128 + col]     = make_float2(v00, v01);
            *(float2*)&g_x[(size_t)(row0 + rr + 8) * 128 + col] = make_float2(v10, v11);
            pd0 += v00 * ps[col] + v01 * ps[col + 1];
            pd1 += v10 * ps[col] + v11 * ps[col + 1];
        }
        pd0 += __shfl_xor_sync(0xffffffffu, pd0, 1);
        pd0 += __shfl_xor_sync(0xffffffffu, pd0, 2);
        pd1 += __shfl_xor_sync(0xffffffffu, pd1, 1);
        pd1 += __shfl_xor_sync(0xffffffffu, pd1, 2);
        if ((lane & 3) == 0) {
            atomicAdd(&sdot[rr], pd0);
            atomicAdd(&sdot[rr + 8], pd1);
        }
    }
    __syncthreads();
    if (tid < 128) g_sdot[row0 + tid] = sdot[tid];
}

// ---------------- mega kernel smem -------------------------------------------
struct MegaSm {
    float xs[160][132];      // current pooled features
    float ms[160][132];      // neighbor means
    float wst[128][36];      // W k-chunk stage
    float s[200];            // scores
    float sdp[2][160];       // deterministic 2-part score dot
    float bb[128];
    float ps[128];
    float harr[256];         // readout accumulator x1+x2+x3
    float pmax[3][128];
    float psum[3][128];
    float h1[128];
    float h2[64];
    float rns[3];
    int   hist[224];
    int   off[225];
    int   cur[224];
    int   wsum[8];
    unsigned short esrc[EPG];
    unsigned short edst[EPG];
    unsigned short eord[EPG];
    short newloc[200];
    short kept[160];
};

// parallel exclusive scan of hist[0..n) -> off/cur, off[n]=total
__device__ __forceinline__ void excl_scan(MegaSm* S, int n) {
    int tid = threadIdx.x, lane = tid & 31, w = tid >> 5;
    int npad = (n + 31) & ~31;
    int h0 = 0, x = 0;
    if (tid < npad) {
        h0 = S->hist[tid];
        x = h0;
#pragma unroll
        for (int o = 1; o < 32; o <<= 1) {
            int y = __shfl_up_sync(0xffffffffu, x, o);
            if (lane >= o) x += y;
        }
        if (lane == 31) S->wsum[w] = x;
        S->off[tid] = x - h0;
    }
    __syncthreads();
    if (tid == 0) {
        int a = 0, nw = npad >> 5;
        for (int i = 0; i < nw; i++) { int t = S->wsum[i]; S->wsum[i] = a; a += t; }
        S->off[n] = a;
    }
    __syncthreads();
    if (tid < n) {
        int o = S->off[tid] + S->wsum[w];
        S->off[tid] = o;
        S->cur[tid] = o;
    }
    __syncthreads();
}

__device__ __forceinline__ void level_agg(MegaSm* S, int n) {
    int tid = threadIdx.x;
    int npad = (n + 31) & ~31;
    for (int i = tid; i < npad; i += NT) S->hist[i] = 0;
    __syncthreads();
    for (int e = tid; e < EPG; e += NT)
        if (S->esrc[e] != INV_E) atomicAdd(&S->hist[S->edst[e]], 1);
    __syncthreads();
    excl_scan(S, n);
    for (int e = tid; e < EPG; e += NT)
        if (S->esrc[e] != INV_E) {
            int p = atomicAdd(&S->cur[S->edst[e]], 1);
            S->eord[p] = S->esrc[e];
        }
    __syncthreads();
    int w = tid >> 5, lane = tid & 31;
    for (int v = w; v < n; v += NW) {
        int e0 = S->off[v], e1 = S->off[v+1];
        float inv = (e1 > e0) ? 1.0f / (float)(e1 - e0) : 0.0f;
        float a0 = 0.f, a1 = 0.f, a2 = 0.f, a3 = 0.f;
        float c0 = 0.f, c1 = 0.f, c2 = 0.f, c3 = 0.f;
        int e = e0;
        for (; e + 1 < e1; e += 2) {
            const float* x0 = S->xs[S->eord[e]];
            const float* x1 = S->xs[S->eord[e+1]];
            a0 += x0[lane];      a1 += x0[lane + 32];
            a2 += x0[lane + 64]; a3 += x0[lane + 96];
            c0 += x1[lane];      c1 += x1[lane + 32];
            c2 += x1[lane + 64]; c3 += x1[lane + 96];
        }
        if (e < e1) {
            const float* x0 = S->xs[S->eord[e]];
            a0 += x0[lane];      a1 += x0[lane + 32];
            a2 += x0[lane + 64]; a3 += x0[lane + 96];
        }
        S->ms[v][lane]      = (a0 + c0) * inv;
        S->ms[v][lane + 32] = (a1 + c1) * inv;
        S->ms[v][lane + 64] = (a2 + c2) * inv;
        S->ms[v][lane + 96] = (a3 + c3) * inv;
    }
    __syncthreads();
}

__device__ __forceinline__ void level_rank(MegaSm* S, int n, int k) {
    int tid = threadIdx.x;
    for (int v = tid; v < n; v += NT) {
        float sv = S->s[v];
        int r = 0;
        for (int u = 0; u < n; u++) {
            float su = S->s[u];
            r += (su > sv) || (su == sv && u < v);
        }
        S->newloc[v] = (r < k) ? (short)r : (short)-1;
        if (r < k) S->kept[r] = (short)v;
    }
    __syncthreads();
}

__device__ __forceinline__ void level_remap(MegaSm* S) {
    int tid = threadIdx.x;
    for (int e = tid; e < EPG; e += NT) {
        unsigned short sv = S->esrc[e];
        if (sv != INV_E) {
            short ns = S->newloc[sv];
            short nd = S->newloc[S->edst[e]];
            if (ns < 0 || nd < 0) S->esrc[e] = INV_E;
            else { S->esrc[e] = (unsigned short)ns; S->edst[e] = (unsigned short)nd; }
        }
    }
    __syncthreads();
}

// pool xs rows [0,k) into harr (3 row-slices across 384 threads)
__device__ __forceinline__ void pool_xs(MegaSm* S, int k) {
    int tid = threadIdx.x;
    int d = tid & 127, sl = tid >> 7;
    float mx = -INFINITY, sm = 0.0f;
    for (int r = sl; r < k; r += 3) {
        float v = S->xs[r][d];
        mx = fmaxf(mx, v);
        sm += v;
    }
    S->pmax[sl][d] = mx;
    S->psum[sl][d] = sm;
    __syncthreads();
    if (tid < 128) {
        S->harr[tid]       += fmaxf(fmaxf(S->pmax[0][tid], S->pmax[1][tid]), S->pmax[2][tid]);
        S->harr[128 + tid] += (S->psum[0][tid] + S->psum[1][tid] + S->psum[2][tid]) / (float)k;
    }
    __syncthreads();
}

// GEMM (relu([ms|xs] @ [Wn|Wr]^T + bb)) with output in regs, fused score,
// topk rank, reg->xs scatter of kept rows (gain applied), pool, optional remap.
__device__ __forceinline__ void level_gemm_topk(
        MegaSm* S, int n, int k, float rn,
        const float* __restrict__ Wn, const float* __restrict__ Wr,
        bool do_remap) {
    int tid = threadIdx.x, lane = tid & 31, w = tid >> 5;
    int ntasks = (n >> 4) << 1;   // (n/16) row-groups x 2 col-halves

    float acc[2][8][4];
#pragma unroll
    for (int ti = 0; ti < 2; ti++)
#pragma unroll
        for (int nt = 0; nt < 8; nt++)
#pragma unroll
            for (int i = 0; i < 4; i++) acc[ti][nt][i] = 0.0f;

    for (int kc = 0; kc < 256; kc += 32) {
        const float* Wg = (kc < 128) ? Wn : Wr;
        int kg = kc & 127;
        for (int idx = tid; idx < 1024; idx += NT) {
            int r = idx >> 3, q = idx & 7;
            *(float4*)&S->wst[r][q*4] = *(const float4*)&Wg[r*128 + kg + q*4];
        }
        __syncthreads();
        const float (*A)[132] = (kc < 128) ? S->ms : S->xs;
#pragma unroll
        for (int ti = 0; ti < 2; ti++) {
            int t = w + ti * NW;
            if (t < ntasks) {
                int rg = t >> 1, hf = t & 1;
                int rb = rg * 16 + (lane >> 2);
#pragma unroll
                for (int ks = 0; ks < 32; ks += 8) {
                    int c = kg + ks + (lane & 3);
                    uint32_t a0 = __float_as_uint(A[rb][c]);
                    uint32_t a1 = __float_as_uint(A[rb + 8][c]);
                    uint32_t a2 = __float_as_uint(A[rb][c + 4]);
                    uint32_t a3 = __float_as_uint(A[rb + 8][c + 4]);
#pragma unroll
                    for (int nt = 0; nt < 8; nt++) {
                        int nr = hf * 64 + nt * 8 + (lane >> 2);
                        int cc = ks + (lane & 3);
                        uint32_t b0 = __float_as_uint(S->wst[nr][cc]);
                        uint32_t b1 = __float_as_uint(S->wst[nr][cc + 4]);
                        mma_tf32(acc[ti][nt], a0, a1, a2, a3, b0, b1);
                    }
                }
            }
        }
        __syncthreads();
    }

    // epilogue: relu into acc, deterministic score-dot halves
#pragma unroll
    for (int ti = 0; ti < 2; ti++) {
        int t = w + ti * NW;
        if (t < ntasks) {
            int rg = t >> 1, hf = t & 1;
            int r = rg * 16 + (lane >> 2);
            float pd0 = 0.0f, pd1 = 0.0f;
#pragma unroll
            for (int nt = 0; nt < 8; nt++) {
                int col = hf * 64 + nt * 8 + 2 * (lane & 3);
                float v00 = fmaxf(acc[ti][nt][0] + S->bb[col],     0.0f);
                float v01 = fmaxf(acc[ti][nt][1] + S->bb[col + 1], 0.0f);
                float v10 = fmaxf(acc[ti][nt][2] + S->bb[col],     0.0f);
                float v11 = fmaxf(acc[ti][nt][3] + S->bb[col + 1], 0.0f);
                acc[ti][nt][0] = v00; acc[ti][nt][1] = v01;
                acc[ti][nt][2] = v10; acc[ti][nt][3] = v11;
                pd0 += v00 * S->ps[col] + v01 * S->ps[col + 1];
                pd1 += v10 * S->ps[col] + v11 * S->ps[col + 1];
            }
            pd0 += __shfl_xor_sync(0xffffffffu, pd0, 1);
            pd0 += __shfl_xor_sync(0xffffffffu, pd0, 2);
            pd1 += __shfl_xor_sync(0xffffffffu, pd1, 1);
            pd1 += __shfl_xor_sync(0xffffffffu, pd1, 2);
            if ((lane & 3) == 0) { S->sdp[hf][r] = pd0; S->sdp[hf][r + 8] = pd1; }
        }
    }
    __syncthreads();

    for (int v = tid; v < n; v += NT)
        S->s[v] = tanhf((S->sdp[0][v] + S->sdp[1][v]) * rn);
    __syncthreads();

    level_rank(S, n, k);

    // scatter kept rows from regs into xs (gain applied)
#pragma unroll
    for (int ti = 0; ti < 2; ti++) {
        int t = w + ti * NW;
        if (t < ntasks) {
            int rg = t >> 1, hf = t & 1;
            int r = rg * 16 + (lane >> 2);
            int nl0 = S->newloc[r], nl1 = S->newloc[r + 8];
            float s0 = S->s[r], s1 = S->s[r + 8];
#pragma unroll
            for (int nt = 0; nt < 8; nt++) {
                int col = hf * 64 + nt * 8 + 2 * (lane & 3);
                if (nl0 >= 0)
                    *(float2*)&S->xs[nl0][col] =
                        make_float2(acc[ti][nt][0] * s0, acc[ti][nt][1] * s0);
                if (nl1 >= 0)
                    *(float2*)&S->xs[nl1][col] =
                        make_float2(acc[ti][nt][2] * s1, acc[ti][nt][3] * s1);
            }
        }
    }
    __syncthreads();

    pool_xs(S, k);
    if (do_remap) level_remap(S);
}

__global__ __launch_bounds__(NT, 1) void mega_kernel(
        const int* __restrict__ edge_index,
        const float* __restrict__ p1,
        const float* __restrict__ w2n, const float* __restrict__ w2r,
        const float* __restrict__ b2,  const float* __restrict__ p2,
        const float* __restrict__ w3n, const float* __restrict__ w3r,
        const float* __restrict__ b3,  const float* __restrict__ p3,
        const float* __restrict__ lw1, const float* __restrict__ lb1,
        const float* __restrict__ lw2, const float* __restrict__ lb2,
        const float* __restrict__ lw3, const float* __restrict__ lb3,
        float* __restrict__ out) {
    extern __shared__ char raw[];
    MegaSm* S = (MegaSm*)raw;

    int b = blockIdx.x, tid = threadIdx.x;
    int w = tid >> 5, lane = tid & 31;

    for (int e = tid; e < EPG; e += NT) {
        S->esrc[e] = (unsigned short)(edge_index[b*EPG + e] - b*NP);
        S->edst[e] = (unsigned short)(edge_index[E_TOT + b*EPG + e] - b*NP);
    }
    if (w < 3) {
        const float* pv = (w == 0) ? p1 : ((w == 1) ? p2 : p3);
        float v = pv[lane]*pv[lane] + pv[lane+32]*pv[lane+32]
                + pv[lane+64]*pv[lane+64] + pv[lane+96]*pv[lane+96];
#pragma unroll
        for (int o = 16; o; o >>= 1) v += __shfl_down_sync(0xffffffffu, v, o);
        if (lane == 0) S->rns[w] = 1.0f / sqrtf(v);
    }
    if (tid < 256) S->harr[tid] = 0.0f;
    __syncthreads();

    // ---------- topk1 ----------
    for (int v = tid; v < NP; v += NT)
        S->s[v] = tanhf(g_sdot[b*NP + v] * S->rns[0]);
    __syncthreads();
    level_rank(S, NP, K1);
    {   // gather kept rows from g_x, apply gain, pool (3 row-slices)
        int d = tid & 127, sl = tid >> 7;
        float mx = -INFINITY, sm = 0.0f;
        for (int r = sl; r < K1; r += 3) {
            int v = S->kept[r];
            float val = g_x[(size_t)(b*NP + v) * 128 + d] * S->s[v];
            S->xs[r][d] = val;
            mx = fmaxf(mx, val);
            sm += val;
        }
        S->pmax[sl][d] = mx;
        S->psum[sl][d] = sm;
    }
    __syncthreads();
    if (tid < 128) {
        S->harr[tid]       += fmaxf(fmaxf(S->pmax[0][tid], S->pmax[1][tid]), S->pmax[2][tid]);
        S->harr[128 + tid] += (S->psum[0][tid] + S->psum[1][tid] + S->psum[2][tid]) / (float)K1;
    }
    level_remap(S);

    // ---------- level 2 ----------
    if (tid < 128) { S->bb[tid] = b2[tid]; S->ps[tid] = p2[tid]; }
    __syncthreads();
    level_agg(S, K1);
    level_gemm_topk(S, K1, K2, S->rns[1], w2n, w2r, true);

    // ---------- level 3 ----------
    if (tid < 128) { S->bb[tid] = b3[tid]; S->ps[tid] = p3[tid]; }
    __syncthreads();
    level_agg(S, K2);
    level_gemm_topk(S, K2, K3, S->rns[2], w3n, w3r, false);

    // ---------- MLP head (coalesced warp-cooperative) ----------
    for (int c = w; c < 128; c += NW) {
        float a = 0.0f;
#pragma unroll
        for (int j = 0; j < 8; j++)
            a += lw1[c*256 + j*32 + lane] * S->harr[j*32 + lane];
#pragma unroll
        for (int o = 16; o; o >>= 1) a += __shfl_xor_sync(0xffffffffu, a, o);
        if (lane == 0) S->h1[c] = fmaxf(a + lb1[c], 0.0f);
    }
    __syncthreads();
    for (int c = w; c < 64; c += NW) {
        float a = 0.0f;
#pragma unroll
        for (int j = 0; j < 4; j++)
            a += lw2[c*128 + j*32 + lane] * S->h1[j*32 + lane];
#pragma unroll
        for (int o = 16; o; o >>= 1) a += __shfl_xor_sync(0xffffffffu, a, o);
        if (lane == 0) S->h2[c] = fmaxf(a + lb2[c], 0.0f);
    }
    __syncthreads();
    if (w == 0) {
        float a = 0.0f;
#pragma unroll
        for (int j = 0; j < 2; j++)
            a += lw3[j*32 + lane] * S->h2[j*32 + lane];
#pragma unroll
        for (int o = 16; o; o >>= 1) a += __shfl_xor_sync(0xffffffffu, a, o);
        if (lane == 0) out[b] = 1.0f / (1.0f + expf(-(a + lb3[0])));
    }
}

// ---------------- launch ------------------------------------------------------
extern "C" void kernel_launch(void* const* d_in, const int* in_sizes, int n_in,
                              void* d_out, int out_size) {
    const int*   node_ids   = (const int*)d_in[0];
    const int*   edge_index = (const int*)d_in[1];
    const float* emb  = (const float*)d_in[3];
    const float* w1n  = (const float*)d_in[4];
    const float* w1r  = (const float*)d_in[5];
    const float* b1   = (const float*)d_in[6];
    const float* w2n  = (const float*)d_in[7];
    const float* w2r  = (const float*)d_in[8];
    const float* b2   = (const float*)d_in[9];
    const float* w3n  = (const float*)d_in[10];
    const float* w3r  = (const float*)d_in[11];
    const float* b3   = (const float*)d_in[12];
    const float* p1   = (const float*)d_in[13];
    const float* p2   = (const float*)d_in[14];
    const float* p3   = (const float*)d_in[15];
    const float* lw1  = (const float*)d_in[16];
    const float* lb1  = (const float*)d_in[17];
    const float* lw2  = (const float*)d_in[18];
    const float* lb2  = (const float*)d_in[19];
    const float* lw3  = (const float*)d_in[20];
    const float* lb3  = (const float*)d_in[21];
    float* out = (float*)d_out;

    static int smem_set = 0;
    if (!smem_set) {
        cudaFuncSetAttribute(mega_kernel,
                             cudaFuncAttributeMaxDynamicSharedMemorySize,
                             (int)sizeof(MegaSm));
        smem_set = 1;
    }

    gather_kernel<<<(N0*EMB + 255)/256, 256>>>(node_ids, emb);
    aggE_kernel<<<B, 256>>>(edge_index);
    conv1_gemm<<<N0/128, 256>>>(w1n, w1r, b1, p1);
    mega_kernel<<<B, NT, sizeof(MegaSm)>>>(
        edge_index, p1,
        w2n, w2r, b2, p2,
        w3n, w3r, b3, p3,
        lw1, lb1, lw2, lb2, lw3, lb3, out);
}

// round 6
// speedup vs baseline: 1.8643x; 1.3505x over previous
#include <cuda_runtime.h>
#include <math.h>
#include <stdint.h>

#define B    512
#define NP   200
#define EPG  2000
#define E_TOT (B*EPG)
#define HID  128
#define EMB  9
#define K1   160
#define K2   128
#define K3   103

#define NT   640           // threads
#define NW   20            // warps
#define INV_E 0xFFFFu

// ---------------- tf32 mma primitive -----------------------------------------
__device__ __forceinline__ void mma_tf32(float c[4], uint32_t a0, uint32_t a1,
                                         uint32_t a2, uint32_t a3,
                                         uint32_t b0, uint32_t b1) {
    asm volatile(
        "mma.sync.aligned.m16n8k8.row.col.f32.tf32.tf32.f32 "
        "{%0,%1,%2,%3}, {%4,%5,%6,%7}, {%8,%9}, {%0,%1,%2,%3};"
        : "+f"(c[0]), "+f"(c[1]), "+f"(c[2]), "+f"(c[3])
        : "r"(a0), "r"(a1), "r"(a2), "r"(a3), "r"(b0), "r"(b1));
}

// ---------------- mega kernel smem -------------------------------------------
struct MegaSm {
    float xs[160][130];      // pooled features (float2-aligned stride)
    float ms[160][130];      // neighbor means
    union {
        struct {             // conv1 phase
            float As1[208][28];   // [mean(9) | x(9) | pad] per node
            float W1s[128][28];   // [w1n | w1r | pad]
        } c1;
        float wst[128][36];  // level-GEMM W k-chunk stage
    } u;
    float s[208];            // scores
    float sdp[2][208];       // 2-part deterministic score dot
    float bb[128];
    float ps[128];
    float harr[256];         // readout accumulator x1+x2+x3
    float pmax[5][128];
    float psum[5][128];
    float h1[128];
    float h2[64];
    float rns[3];
    int   hist[224];
    int   off[225];
    int   cur[224];
    int   wsum[8];
    unsigned short esrc[EPG];
    unsigned short edst[EPG];
    unsigned short eord[EPG];
    short newloc[208];
    short kept[160];
};

// parallel exclusive scan of hist[0..n) -> off/cur, off[n]=total
__device__ __forceinline__ void excl_scan(MegaSm* S, int n) {
    int tid = threadIdx.x, lane = tid & 31, w = tid >> 5;
    int npad = (n + 31) & ~31;
    if (tid < npad) {
        int h0 = S->hist[tid];
        int x = h0;
#pragma unroll
        for (int o = 1; o < 32; o <<= 1) {
            int y = __shfl_up_sync(0xffffffffu, x, o);
            if (lane >= o) x += y;
        }
        if (lane == 31) S->wsum[w] = x;
        S->off[tid] = x - h0;
    }
    __syncthreads();
    if (tid == 0) {
        int a = 0, nw = npad >> 5;
        for (int i = 0; i < nw; i++) { int t = S->wsum[i]; S->wsum[i] = a; a += t; }
        S->off[n] = a;
    }
    __syncthreads();
    if (tid < n) {
        int o = S->off[tid] + S->wsum[w];
        S->off[tid] = o;
        S->cur[tid] = o;
    }
    __syncthreads();
}

// counting sort of valid edges by dst into eord
__device__ __forceinline__ void edge_sort(MegaSm* S, int n) {
    int tid = threadIdx.x;
    int npad = (n + 31) & ~31;
    for (int i = tid; i < npad; i += NT) S->hist[i] = 0;
    __syncthreads();
    for (int e = tid; e < EPG; e += NT)
        if (S->esrc[e] != INV_E) atomicAdd(&S->hist[S->edst[e]], 1);
    __syncthreads();
    excl_scan(S, n);
    for (int e = tid; e < EPG; e += NT)
        if (S->esrc[e] != INV_E) {
            int p = atomicAdd(&S->cur[S->edst[e]], 1);
            S->eord[p] = S->esrc[e];
        }
    __syncthreads();
}

// 128-dim neighbor mean of xs into ms
__device__ __forceinline__ void level_agg(MegaSm* S, int n) {
    edge_sort(S, n);
    int tid = threadIdx.x, w = tid >> 5, lane = tid & 31;
    for (int v = w; v < n; v += NW) {
        int e0 = S->off[v], e1 = S->off[v+1];
        float inv = (e1 > e0) ? 1.0f / (float)(e1 - e0) : 0.0f;
        float a0 = 0.f, a1 = 0.f, a2 = 0.f, a3 = 0.f;
        float c0 = 0.f, c1 = 0.f, c2 = 0.f, c3 = 0.f;
        int e = e0;
        for (; e + 1 < e1; e += 2) {
            const float* x0 = S->xs[S->eord[e]];
            const float* x1 = S->xs[S->eord[e+1]];
            a0 += x0[lane];      a1 += x0[lane + 32];
            a2 += x0[lane + 64]; a3 += x0[lane + 96];
            c0 += x1[lane];      c1 += x1[lane + 32];
            c2 += x1[lane + 64]; c3 += x1[lane + 96];
        }
        if (e < e1) {
            const float* x0 = S->xs[S->eord[e]];
            a0 += x0[lane];      a1 += x0[lane + 32];
            a2 += x0[lane + 64]; a3 += x0[lane + 96];
        }
        S->ms[v][lane]      = (a0 + c0) * inv;
        S->ms[v][lane + 32] = (a1 + c1) * inv;
        S->ms[v][lane + 64] = (a2 + c2) * inv;
        S->ms[v][lane + 96] = (a3 + c3) * inv;
    }
    __syncthreads();
}

__device__ __forceinline__ void level_rank(MegaSm* S, int n, int k) {
    int tid = threadIdx.x;
    for (int v = tid; v < n; v += NT) {
        float sv = S->s[v];
        int r = 0;
        for (int u = 0; u < n; u++) {
            float su = S->s[u];
            r += (su > sv) || (su == sv && u < v);
        }
        S->newloc[v] = (r < k) ? (short)r : (short)-1;
        if (r < k) S->kept[r] = (short)v;
    }
    __syncthreads();
}

__device__ __forceinline__ void level_remap(MegaSm* S) {
    int tid = threadIdx.x;
    for (int e = tid; e < EPG; e += NT) {
        unsigned short sv = S->esrc[e];
        if (sv != INV_E) {
            short ns = S->newloc[sv];
            short nd = S->newloc[S->edst[e]];
            if (ns < 0 || nd < 0) S->esrc[e] = INV_E;
            else { S->esrc[e] = (unsigned short)ns; S->edst[e] = (unsigned short)nd; }
        }
    }
    __syncthreads();
}

// pool xs rows [0,k) into harr (5 row-slices across 640 threads)
__device__ __forceinline__ void pool_xs(MegaSm* S, int k) {
    int tid = threadIdx.x;
    int d = tid & 127, sl = tid >> 7;    // 0..4
    float mx = -INFINITY, sm = 0.0f;
    for (int r = sl; r < k; r += 5) {
        float v = S->xs[r][d];
        mx = fmaxf(mx, v);
        sm += v;
    }
    S->pmax[sl][d] = mx;
    S->psum[sl][d] = sm;
    __syncthreads();
    if (tid < 128) {
        float m = S->pmax[0][tid];
        float t = S->psum[0][tid];
#pragma unroll
        for (int i = 1; i < 5; i++) {
            m = fmaxf(m, S->pmax[i][tid]);
            t += S->psum[i][tid];
        }
        S->harr[tid]       += m;
        S->harr[128 + tid] += t / (float)k;
    }
    __syncthreads();
}

// level GEMM (relu([ms|xs] @ [Wn|Wr]^T + bb)), 1 task/warp, fused score+topk+
// scatter+pool (+optional remap)
__device__ __forceinline__ void level_gemm_topk(
        MegaSm* S, int n, int k, float rn,
        const float* __restrict__ Wn, const float* __restrict__ Wr,
        bool do_remap) {
    int tid = threadIdx.x, lane = tid & 31, w = tid >> 5;
    int ntasks = (n >> 4) << 1;
    int rg = w >> 1, hf = w & 1;
    bool active = (w < ntasks);

    float acc[8][4];
#pragma unroll
    for (int nt = 0; nt < 8; nt++)
#pragma unroll
        for (int i = 0; i < 4; i++) acc[nt][i] = 0.0f;

    for (int kc = 0; kc < 256; kc += 32) {
        const float* Wg = (kc < 128) ? Wn : Wr;
        int kg = kc & 127;
        for (int idx = tid; idx < 1024; idx += NT) {
            int r = idx >> 3, q = idx & 7;
            *(float4*)&S->u.wst[r][q*4] = *(const float4*)&Wg[r*128 + kg + q*4];
        }
        __syncthreads();
        if (active) {
            const float (*A)[130] = (kc < 128) ? S->ms : S->xs;
            int rb = rg * 16 + (lane >> 2);
#pragma unroll
            for (int ks = 0; ks < 32; ks += 8) {
                int c = kg + ks + (lane & 3);
                uint32_t a0 = __float_as_uint(A[rb][c]);
                uint32_t a1 = __float_as_uint(A[rb + 8][c]);
                uint32_t a2 = __float_as_uint(A[rb][c + 4]);
                uint32_t a3 = __float_as_uint(A[rb + 8][c + 4]);
#pragma unroll
                for (int nt = 0; nt < 8; nt++) {
                    int nr = hf * 64 + nt * 8 + (lane >> 2);
                    int cc = ks + (lane & 3);
                    uint32_t b0 = __float_as_uint(S->u.wst[nr][cc]);
                    uint32_t b1 = __float_as_uint(S->u.wst[nr][cc + 4]);
                    mma_tf32(acc[nt], a0, a1, a2, a3, b0, b1);
                }
            }
        }
        __syncthreads();
    }

    if (active) {
        int r = rg * 16 + (lane >> 2);
        float pd0 = 0.0f, pd1 = 0.0f;
#pragma unroll
        for (int nt = 0; nt < 8; nt++) {
            int col = hf * 64 + nt * 8 + 2 * (lane & 3);
            float v00 = fmaxf(acc[nt][0] + S->bb[col],     0.0f);
            float v01 = fmaxf(acc[nt][1] + S->bb[col + 1], 0.0f);
            float v10 = fmaxf(acc[nt][2] + S->bb[col],     0.0f);
            float v11 = fmaxf(acc[nt][3] + S->bb[col + 1], 0.0f);
            acc[nt][0] = v00; acc[nt][1] = v01;
            acc[nt][2] = v10; acc[nt][3] = v11;
            pd0 += v00 * S->ps[col] + v01 * S->ps[col + 1];
            pd1 += v10 * S->ps[col] + v11 * S->ps[col + 1];
        }
        pd0 += __shfl_xor_sync(0xffffffffu, pd0, 1);
        pd0 += __shfl_xor_sync(0xffffffffu, pd0, 2);
        pd1 += __shfl_xor_sync(0xffffffffu, pd1, 1);
        pd1 += __shfl_xor_sync(0xffffffffu, pd1, 2);
        if ((lane & 3) == 0) { S->sdp[hf][r] = pd0; S->sdp[hf][r + 8] = pd1; }
    }
    __syncthreads();

    int tidx = threadIdx.x;
    for (int v = tidx; v < n; v += NT)
        S->s[v] = tanhf((S->sdp[0][v] + S->sdp[1][v]) * rn);
    __syncthreads();

    level_rank(S, n, k);

    if (active) {
        int r = rg * 16 + (lane >> 2);
        int nl0 = S->newloc[r], nl1 = S->newloc[r + 8];
        float s0 = S->s[r], s1 = S->s[r + 8];
#pragma unroll
        for (int nt = 0; nt < 8; nt++) {
            int col = hf * 64 + nt * 8 + 2 * (lane & 3);
            if (nl0 >= 0)
                *(float2*)&S->xs[nl0][col] = make_float2(acc[nt][0] * s0, acc[nt][1] * s0);
            if (nl1 >= 0)
                *(float2*)&S->xs[nl1][col] = make_float2(acc[nt][2] * s1, acc[nt][3] * s1);
        }
    }
    __syncthreads();

    pool_xs(S, k);
    if (do_remap) level_remap(S);
}

// ---------------- the single fused kernel ------------------------------------
__global__ __launch_bounds__(NT, 1) void mega_kernel(
        const int* __restrict__ node_ids,
        const int* __restrict__ edge_index,
        const float* __restrict__ emb,
        const float* __restrict__ w1n, const float* __restrict__ w1r,
        const float* __restrict__ b1,  const float* __restrict__ p1,
        const float* __restrict__ w2n, const float* __restrict__ w2r,
        const float* __restrict__ b2,  const float* __restrict__ p2,
        const float* __restrict__ w3n, const float* __restrict__ w3r,
        const float* __restrict__ b3,  const float* __restrict__ p3,
        const float* __restrict__ lw1, const float* __restrict__ lb1,
        const float* __restrict__ lw2, const float* __restrict__ lb2,
        const float* __restrict__ lw3, const float* __restrict__ lb3,
        float* __restrict__ out) {
    extern __shared__ char raw[];
    MegaSm* S = (MegaSm*)raw;

    int b = blockIdx.x, tid = threadIdx.x;
    int w = tid >> 5, lane = tid & 31;

    // edges -> smem (local indices)
    for (int e = tid; e < EPG; e += NT) {
        S->esrc[e] = (unsigned short)(edge_index[b*EPG + e] - b*NP);
        S->edst[e] = (unsigned short)(edge_index[E_TOT + b*EPG + e] - b*NP);
    }
    // 1/||p|| for the three pool vectors
    if (w < 3) {
        const float* pv = (w == 0) ? p1 : ((w == 1) ? p2 : p3);
        float v = pv[lane]*pv[lane] + pv[lane+32]*pv[lane+32]
                + pv[lane+64]*pv[lane+64] + pv[lane+96]*pv[lane+96];
#pragma unroll
        for (int o = 16; o; o >>= 1) v += __shfl_down_sync(0xffffffffu, v, o);
        if (lane == 0) S->rns[w] = 1.0f / sqrtf(v);
    }
    if (tid < 256) S->harr[tid] = 0.0f;
    if (tid < 128) { S->bb[tid] = b1[tid]; S->ps[tid] = p1[tid]; }

    // As1: zero everything; fill emb features into cols 9..17 for v<200
    for (int idx = tid; idx < 208*28; idx += NT) {
        int r = idx / 28, c = idx - r*28;
        float v = 0.0f;
        if (r < NP && c >= 9 && c < 18)
            v = emb[(size_t)node_ids[b*NP + r] * EMB + (c - 9)];
        S->u.c1.As1[r][c] = v;
    }
    // W1 stage [w1n | w1r | pad]
    for (int idx = tid; idx < 128*28; idx += NT) {
        int r = idx / 28, c = idx - r*28;
        float wv = 0.0f;
        if (c < 9)       wv = w1n[r*9 + c];
        else if (c < 18) wv = w1r[r*9 + (c - 9)];
        S->u.c1.W1s[r][c] = wv;
    }
    __syncthreads();

    // ---------- level-1 9-dim aggregation ----------
    edge_sort(S, NP);
    for (int v = w; v < NP; v += NW) {
        int e0 = S->off[v], e1 = S->off[v+1];
        float inv = (e1 > e0) ? 1.0f / (float)(e1 - e0) : 0.0f;
        if (lane < EMB) {
            float a = 0.0f;
            for (int e = e0; e < e1; e++)
                a += S->u.c1.As1[S->eord[e]][9 + lane];
            S->u.c1.As1[v][lane] = a * inv;
        }
    }
    __syncthreads();

    // ---------- conv1 pass 1: score dot only (26 tasks, K=24) ----------
#pragma unroll
    for (int ti = 0; ti < 2; ti++) {
        int t = w + ti * NW;
        if (t < 26) {
            int rg = t >> 1, hf = t & 1;
            int rb = rg * 16 + (lane >> 2);
            float acc[8][4];
#pragma unroll
            for (int nt = 0; nt < 8; nt++)
#pragma unroll
                for (int i = 0; i < 4; i++) acc[nt][i] = 0.0f;
#pragma unroll
            for (int ks = 0; ks < 24; ks += 8) {
                int c = ks + (lane & 3);
                uint32_t a0 = __float_as_uint(S->u.c1.As1[rb][c]);
                uint32_t a1 = __float_as_uint(S->u.c1.As1[rb + 8][c]);
                uint32_t a2 = __float_as_uint(S->u.c1.As1[rb][c + 4]);
                uint32_t a3 = __float_as_uint(S->u.c1.As1[rb + 8][c + 4]);
#pragma unroll
                for (int nt = 0; nt < 8; nt++) {
                    int nr = hf * 64 + nt * 8 + (lane >> 2);
                    uint32_t b0 = __float_as_uint(S->u.c1.W1s[nr][c]);
                    uint32_t b1 = __float_as_uint(S->u.c1.W1s[nr][c + 4]);
                    mma_tf32(acc[nt], a0, a1, a2, a3, b0, b1);
                }
            }
            int r = rg * 16 + (lane >> 2);
            float pd0 = 0.0f, pd1 = 0.0f;
#pragma unroll
            for (int nt = 0; nt < 8; nt++) {
                int col = hf * 64 + nt * 8 + 2 * (lane & 3);
                pd0 += fmaxf(acc[nt][0] + S->bb[col],     0.0f) * S->ps[col]
                     + fmaxf(acc[nt][1] + S->bb[col + 1], 0.0f) * S->ps[col + 1];
                pd1 += fmaxf(acc[nt][2] + S->bb[col],     0.0f) * S->ps[col]
                     + fmaxf(acc[nt][3] + S->bb[col + 1], 0.0f) * S->ps[col + 1];
            }
            pd0 += __shfl_xor_sync(0xffffffffu, pd0, 1);
            pd0 += __shfl_xor_sync(0xffffffffu, pd0, 2);
            pd1 += __shfl_xor_sync(0xffffffffu, pd1, 1);
            pd1 += __shfl_xor_sync(0xffffffffu, pd1, 2);
            if ((lane & 3) == 0) { S->sdp[hf][r] = pd0; S->sdp[hf][r + 8] = pd1; }
        }
    }
    __syncthreads();

    for (int v = tid; v < NP; v += NT)
        S->s[v] = tanhf((S->sdp[0][v] + S->sdp[1][v]) * S->rns[0]);
    __syncthreads();

    level_rank(S, NP, K1);

    // ---------- conv1 pass 2: recompute kept rows, gain, write xs ----------
    {
        int rg = w >> 1, hf = w & 1;
        int r0 = rg * 16 + (lane >> 2);
        int k0 = S->kept[r0], k1 = S->kept[r0 + 8];
        float s0 = S->s[k0],  s1 = S->s[k1];
        float acc[8][4];
#pragma unroll
        for (int nt = 0; nt < 8; nt++)
#pragma unroll
            for (int i = 0; i < 4; i++) acc[nt][i] = 0.0f;
#pragma unroll
        for (int ks = 0; ks < 24; ks += 8) {
            int c = ks + (lane & 3);
            uint32_t a0 = __float_as_uint(S->u.c1.As1[k0][c]);
            uint32_t a1 = __float_as_uint(S->u.c1.As1[k1][c]);
            uint32_t a2 = __float_as_uint(S->u.c1.As1[k0][c + 4]);
            uint32_t a3 = __float_as_uint(S->u.c1.As1[k1][c + 4]);
#pragma unroll
            for (int nt = 0; nt < 8; nt++) {
                int nr = hf * 64 + nt * 8 + (lane >> 2);
                uint32_t b0 = __float_as_uint(S->u.c1.W1s[nr][c]);
                uint32_t b1 = __float_as_uint(S->u.c1.W1s[nr][c + 4]);
                mma_tf32(acc[nt], a0, a1, a2, a3, b0, b1);
            }
        }
#pragma unroll
        for (int nt = 0; nt < 8; nt++) {
            int col = hf * 64 + nt * 8 + 2 * (lane & 3);
            float v00 = fmaxf(acc[nt][0] + S->bb[col],     0.0f) * s0;
            float v01 = fmaxf(acc[nt][1] + S->bb[col + 1], 0.0f) * s0;
            float v10 = fmaxf(acc[nt][2] + S->bb[col],     0.0f) * s1;
            float v11 = fmaxf(acc[nt][3] + S->bb[col + 1], 0.0f) * s1;
            *(float2*)&S->xs[r0][col]     = make_float2(v00, v01);
            *(float2*)&S->xs[r0 + 8][col] = make_float2(v10, v11);
        }
    }
    __syncthreads();

    pool_xs(S, K1);
    level_remap(S);

    // ---------- level 2 ----------
    if (tid < 128) { S->bb[tid] = b2[tid]; S->ps[tid] = p2[tid]; }
    __syncthreads();
    level_agg(S, K1);
    level_gemm_topk(S, K1, K2, S->rns[1], w2n, w2r, true);

    // ---------- level 3 ----------
    if (tid < 128) { S->bb[tid] = b3[tid]; S->ps[tid] = p3[tid]; }
    __syncthreads();
    level_agg(S, K2);
    level_gemm_topk(S, K2, K3, S->rns[2], w3n, w3r, false);

    // ---------- MLP head (coalesced warp-cooperative) ----------
    for (int c = w; c < 128; c += NW) {
        float a = 0.0f;
#pragma unroll
        for (int j = 0; j < 8; j++)
            a += lw1[c*256 + j*32 + lane] * S->harr[j*32 + lane];
#pragma unroll
        for (int o = 16; o; o >>= 1) a += __shfl_xor_sync(0xffffffffu, a, o);
        if (lane == 0) S->h1[c] = fmaxf(a + lb1[c], 0.0f);
    }
    __syncthreads();
    for (int c = w; c < 64; c += NW) {
        float a = 0.0f;
#pragma unroll
        for (int j = 0; j < 4; j++)
            a += lw2[c*128 + j*32 + lane] * S->h1[j*32 + lane];
#pragma unroll
        for (int o = 16; o; o >>= 1) a += __shfl_xor_sync(0xffffffffu, a, o);
        if (lane == 0) S->h2[c] = fmaxf(a + lb2[c], 0.0f);
    }
    __syncthreads();
    if (w == 0) {
        float a = 0.0f;
#pragma unroll
        for (int j = 0; j < 2; j++)
            a += lw3[j*32 + lane] * S->h2[j*32 + lane];
#pragma unroll
        for (int o = 16; o; o >>= 1) a += __shfl_xor_sync(0xffffffffu, a, o);
        if (lane == 0) out[b] = 1.0f / (1.0f + expf(-(a + lb3[0])));
    }
}

// ---------------- launch ------------------------------------------------------
extern "C" void kernel_launch(void* const* d_in, const int* in_sizes, int n_in,
                              void* d_out, int out_size) {
    const int*   node_ids   = (const int*)d_in[0];
    const int*   edge_index = (const int*)d_in[1];
    const float* emb  = (const float*)d_in[3];
    const float* w1n  = (const float*)d_in[4];
    const float* w1r  = (const float*)d_in[5];
    const float* b1   = (const float*)d_in[6];
    const float* w2n  = (const float*)d_in[7];
    const float* w2r  = (const float*)d_in[8];
    const float* b2   = (const float*)d_in[9];
    const float* w3n  = (const float*)d_in[10];
    const float* w3r  = (const float*)d_in[11];
    const float* b3   = (const float*)d_in[12];
    const float* p1   = (const float*)d_in[13];
    const float* p2   = (const float*)d_in[14];
    const float* p3   = (const float*)d_in[15];
    const float* lw1  = (const float*)d_in[16];
    const float* lb1  = (const float*)d_in[17];
    const float* lw2  = (const float*)d_in[18];
    const float* lb2  = (const float*)d_in[19];
    const float* lw3  = (const float*)d_in[20];
    const float* lb3  = (const float*)d_in[21];
    float* out = (float*)d_out;

    static int smem_set = 0;
    if (!smem_set) {
        cudaFuncSetAttribute(mega_kernel,
                             cudaFuncAttributeMaxDynamicSharedMemorySize,
                             (int)sizeof(MegaSm));
        smem_set = 1;
    }

    mega_kernel<<<B, NT, sizeof(MegaSm)>>>(
        node_ids, edge_index, emb,
        w1n, w1r, b1, p1,
        w2n, w2r, b2, p2,
        w3n, w3r, b3, p3,
        lw1, lb1, lw2, lb2, lw3, lb3, out);
}

// round 7
// speedup vs baseline: 1.9523x; 1.0472x over previous
#include <cuda_runtime.h>
#include <math.h>
#include <stdint.h>

#define B    512
#define NP   200
#define EPG  2000
#define E_TOT (B*EPG)
#define HID  128
#define EMB  9
#define K1   160
#define K2   128
#define K3   103

#define NT   640           // threads
#define NW   20            // warps
#define INV_E 0xFFFFu

// ---------------- async copy helpers -----------------------------------------
__device__ __forceinline__ void cp_async16(void* smem_dst, const void* gsrc) {
    uint32_t s = (uint32_t)__cvta_generic_to_shared(smem_dst);
    asm volatile("cp.async.ca.shared.global [%0], [%1], 16;\n" :: "r"(s), "l"(gsrc));
}
__device__ __forceinline__ void cp_commit() {
    asm volatile("cp.async.commit_group;\n" ::: "memory");
}
template<int N>
__device__ __forceinline__ void cp_wait() {
    asm volatile("cp.async.wait_group %0;\n" :: "n"(N) : "memory");
}

// ---------------- tf32 mma primitive -----------------------------------------
__device__ __forceinline__ void mma_tf32(float c[4], uint32_t a0, uint32_t a1,
                                         uint32_t a2, uint32_t a3,
                                         uint32_t b0, uint32_t b1) {
    asm volatile(
        "mma.sync.aligned.m16n8k8.row.col.f32.tf32.tf32.f32 "
        "{%0,%1,%2,%3}, {%4,%5,%6,%7}, {%8,%9}, {%0,%1,%2,%3};"
        : "+f"(c[0]), "+f"(c[1]), "+f"(c[2]), "+f"(c[3])
        : "r"(a0), "r"(a1), "r"(a2), "r"(a3), "r"(b0), "r"(b1));
}

// ---------------- mega kernel smem -------------------------------------------
struct MegaSm {
    float xs[160][130];      // pooled features (float2-aligned stride)
    float ms[160][130];      // neighbor means
    union {
        struct {             // conv1 phase
            float As1[208][28];   // [mean(9) | x(9) | pad] per node
            float W1s[128][28];   // [w1n | w1r | pad]
        } c1;
        float wst2[2][128][36];  // level-GEMM W k-chunk double buffer
    } u;
    float s[208];            // scores
    float sdp[2][208];       // 2-part deterministic score dot
    float bb[128];
    float ps[128];
    float harr[256];         // readout accumulator x1+x2+x3
    float pmax[5][128];
    float psum[5][128];
    float h1[128];
    float h2[64];
    float rns[3];
    int   hist[224];
    int   off[225];
    int   cur[224];
    int   wsum[8];
    unsigned short esrc[EPG];
    unsigned short edst[EPG];
    unsigned short eord[EPG];
    short newloc[208];
    short kept[160];
};

// parallel exclusive scan of hist[0..n) -> off/cur, off[n]=total
__device__ __forceinline__ void excl_scan(MegaSm* S, int n) {
    int tid = threadIdx.x, lane = tid & 31, w = tid >> 5;
    int npad = (n + 31) & ~31;
    if (tid < npad) {
        int h0 = S->hist[tid];
        int x = h0;
#pragma unroll
        for (int o = 1; o < 32; o <<= 1) {
            int y = __shfl_up_sync(0xffffffffu, x, o);
            if (lane >= o) x += y;
        }
        if (lane == 31) S->wsum[w] = x;
        S->off[tid] = x - h0;
    }
    __syncthreads();
    if (tid == 0) {
        int a = 0, nw = npad >> 5;
        for (int i = 0; i < nw; i++) { int t = S->wsum[i]; S->wsum[i] = a; a += t; }
        S->off[n] = a;
    }
    __syncthreads();
    if (tid < n) {
        int o = S->off[tid] + S->wsum[w];
        S->off[tid] = o;
        S->cur[tid] = o;
    }
    __syncthreads();
}

// counting sort of valid edges by dst into eord
__device__ __forceinline__ void edge_sort(MegaSm* S, int n) {
    int tid = threadIdx.x;
    int npad = (n + 31) & ~31;
    for (int i = tid; i < npad; i += NT) S->hist[i] = 0;
    __syncthreads();
    for (int e = tid; e < EPG; e += NT)
        if (S->esrc[e] != INV_E) atomicAdd(&S->hist[S->edst[e]], 1);
    __syncthreads();
    excl_scan(S, n);
    for (int e = tid; e < EPG; e += NT)
        if (S->esrc[e] != INV_E) {
            int p = atomicAdd(&S->cur[S->edst[e]], 1);
            S->eord[p] = S->esrc[e];
        }
    __syncthreads();
}

// 128-dim neighbor mean of xs into ms (float2 per-lane dims)
__device__ __forceinline__ void level_agg(MegaSm* S, int n) {
    edge_sort(S, n);
    int tid = threadIdx.x, w = tid >> 5, lane = tid & 31;
    for (int v = w; v < n; v += NW) {
        int e0 = S->off[v], e1 = S->off[v+1];
        float inv = (e1 > e0) ? 1.0f / (float)(e1 - e0) : 0.0f;
        float a0x = 0.f, a0y = 0.f, a1x = 0.f, a1y = 0.f;
        float b0x = 0.f, b0y = 0.f, b1x = 0.f, b1y = 0.f;
        int e = e0;
        for (; e + 1 < e1; e += 2) {
            const float2* x0 = (const float2*)S->xs[S->eord[e]];
            const float2* x1 = (const float2*)S->xs[S->eord[e+1]];
            float2 p0 = x0[lane], p1 = x0[lane + 32];
            float2 q0 = x1[lane], q1 = x1[lane + 32];
            a0x += p0.x; a0y += p0.y; a1x += p1.x; a1y += p1.y;
            b0x += q0.x; b0y += q0.y; b1x += q1.x; b1y += q1.y;
        }
        if (e < e1) {
            const float2* x0 = (const float2*)S->xs[S->eord[e]];
            float2 p0 = x0[lane], p1 = x0[lane + 32];
            a0x += p0.x; a0y += p0.y; a1x += p1.x; a1y += p1.y;
        }
        *(float2*)&S->ms[v][2*lane] =
            make_float2((a0x + b0x) * inv, (a0y + b0y) * inv);
        *(float2*)&S->ms[v][2*lane + 64] =
            make_float2((a1x + b1x) * inv, (a1y + b1y) * inv);
    }
    __syncthreads();
}

__device__ __forceinline__ void level_rank(MegaSm* S, int n, int k) {
    int tid = threadIdx.x;
    for (int v = tid; v < n; v += NT) {
        float sv = S->s[v];
        int r = 0;
        for (int u = 0; u < n; u++) {
            float su = S->s[u];
            r += (su > sv) || (su == sv && u < v);
        }
        S->newloc[v] = (r < k) ? (short)r : (short)-1;
        if (r < k) S->kept[r] = (short)v;
    }
    __syncthreads();
}

__device__ __forceinline__ void level_remap(MegaSm* S) {
    int tid = threadIdx.x;
    for (int e = tid; e < EPG; e += NT) {
        unsigned short sv = S->esrc[e];
        if (sv != INV_E) {
            short ns = S->newloc[sv];
            short nd = S->newloc[S->edst[e]];
            if (ns < 0 || nd < 0) S->esrc[e] = INV_E;
            else { S->esrc[e] = (unsigned short)ns; S->edst[e] = (unsigned short)nd; }
        }
    }
    __syncthreads();
}

// pool xs rows [0,k) into harr (5 row-slices across 640 threads)
__device__ __forceinline__ void pool_xs(MegaSm* S, int k) {
    int tid = threadIdx.x;
    int d = tid & 127, sl = tid >> 7;    // 0..4
    float mx = -INFINITY, sm = 0.0f;
    for (int r = sl; r < k; r += 5) {
        float v = S->xs[r][d];
        mx = fmaxf(mx, v);
        sm += v;
    }
    S->pmax[sl][d] = mx;
    S->psum[sl][d] = sm;
    __syncthreads();
    if (tid < 128) {
        float m = S->pmax[0][tid];
        float t = S->psum[0][tid];
#pragma unroll
        for (int i = 1; i < 5; i++) {
            m = fmaxf(m, S->pmax[i][tid]);
            t += S->psum[i][tid];
        }
        S->harr[tid]       += m;
        S->harr[128 + tid] += t / (float)k;
    }
    __syncthreads();
}

// stage one 32-k chunk of W into buffer buf via cp.async
__device__ __forceinline__ void stage_w_async(
        MegaSm* S, int buf, const float* __restrict__ Wg, int kg) {
    int tid = threadIdx.x;
    for (int idx = tid; idx < 1024; idx += NT) {
        int r = idx >> 3, q = idx & 7;
        cp_async16(&S->u.wst2[buf][r][q * 4], &Wg[r * 128 + kg + q * 4]);
    }
}

// level GEMM (relu([ms|xs] @ [Wn|Wr]^T + bb)), double-buffered cp.async weight
// staging, fused score+topk+scatter+pool (+optional remap)
__device__ __forceinline__ void level_gemm_topk(
        MegaSm* S, int n, int k, float rn,
        const float* __restrict__ Wn, const float* __restrict__ Wr,
        bool do_remap) {
    int tid = threadIdx.x, lane = tid & 31, w = tid >> 5;
    int ntasks = (n >> 4) << 1;
    int rg = w >> 1, hf = w & 1;
    bool active = (w < ntasks);

    float acc[8][4];
#pragma unroll
    for (int nt = 0; nt < 8; nt++)
#pragma unroll
        for (int i = 0; i < 4; i++) acc[nt][i] = 0.0f;

    // prologue: prefetch chunk 0
    stage_w_async(S, 0, Wn, 0);
    cp_commit();

#pragma unroll 1
    for (int ci = 0; ci < 8; ci++) {
        int nb = ci & 1;
        if (ci < 7) {
            int kc2 = (ci + 1) * 32;
            const float* Wg2 = (kc2 < 128) ? Wn : Wr;
            stage_w_async(S, nb ^ 1, Wg2, kc2 & 127);
            cp_commit();
            cp_wait<1>();
        } else {
            cp_wait<0>();
        }
        __syncthreads();

        if (active) {
            int kc = ci * 32;
            const float (*A)[130] = (kc < 128) ? S->ms : S->xs;
            int kg = kc & 127;
            int rb = rg * 16 + (lane >> 2);
#pragma unroll
            for (int ks = 0; ks < 32; ks += 8) {
                int c = kg + ks + (lane & 3);
                uint32_t a0 = __float_as_uint(A[rb][c]);
                uint32_t a1 = __float_as_uint(A[rb + 8][c]);
                uint32_t a2 = __float_as_uint(A[rb][c + 4]);
                uint32_t a3 = __float_as_uint(A[rb + 8][c + 4]);
#pragma unroll
                for (int nt = 0; nt < 8; nt++) {
                    int nr = hf * 64 + nt * 8 + (lane >> 2);
                    int cc = ks + (lane & 3);
                    uint32_t b0 = __float_as_uint(S->u.wst2[nb][nr][cc]);
                    uint32_t b1 = __float_as_uint(S->u.wst2[nb][nr][cc + 4]);
                    mma_tf32(acc[nt], a0, a1, a2, a3, b0, b1);
                }
            }
        }
        __syncthreads();
    }

    if (active) {
        int r = rg * 16 + (lane >> 2);
        float pd0 = 0.0f, pd1 = 0.0f;
#pragma unroll
        for (int nt = 0; nt < 8; nt++) {
            int col = hf * 64 + nt * 8 + 2 * (lane & 3);
            float v00 = fmaxf(acc[nt][0] + S->bb[col],     0.0f);
            float v01 = fmaxf(acc[nt][1] + S->bb[col + 1], 0.0f);
            float v10 = fmaxf(acc[nt][2] + S->bb[col],     0.0f);
            float v11 = fmaxf(acc[nt][3] + S->bb[col + 1], 0.0f);
            acc[nt][0] = v00; acc[nt][1] = v01;
            acc[nt][2] = v10; acc[nt][3] = v11;
            pd0 += v00 * S->ps[col] + v01 * S->ps[col + 1];
            pd1 += v10 * S->ps[col] + v11 * S->ps[col + 1];
        }
        pd0 += __shfl_xor_sync(0xffffffffu, pd0, 1);
        pd0 += __shfl_xor_sync(0xffffffffu, pd0, 2);
        pd1 += __shfl_xor_sync(0xffffffffu, pd1, 1);
        pd1 += __shfl_xor_sync(0xffffffffu, pd1, 2);
        if ((lane & 3) == 0) { S->sdp[hf][r] = pd0; S->sdp[hf][r + 8] = pd1; }
    }
    __syncthreads();

    for (int v = tid; v < n; v += NT)
        S->s[v] = tanhf((S->sdp[0][v] + S->sdp[1][v]) * rn);
    __syncthreads();

    level_rank(S, n, k);

    if (active) {
        int r = rg * 16 + (lane >> 2);
        int nl0 = S->newloc[r], nl1 = S->newloc[r + 8];
        float s0 = S->s[r], s1 = S->s[r + 8];
#pragma unroll
        for (int nt = 0; nt < 8; nt++) {
            int col = hf * 64 + nt * 8 + 2 * (lane & 3);
            if (nl0 >= 0)
                *(float2*)&S->xs[nl0][col] = make_float2(acc[nt][0] * s0, acc[nt][1] * s0);
            if (nl1 >= 0)
                *(float2*)&S->xs[nl1][col] = make_float2(acc[nt][2] * s1, acc[nt][3] * s1);
        }
    }
    __syncthreads();

    pool_xs(S, k);
    if (do_remap) level_remap(S);
}

// ---------------- the single fused kernel ------------------------------------
__global__ __launch_bounds__(NT, 1) void mega_kernel(
        const int* __restrict__ node_ids,
        const int* __restrict__ edge_index,
        const float* __restrict__ emb,
        const float* __restrict__ w1n, const float* __restrict__ w1r,
        const float* __restrict__ b1,  const float* __restrict__ p1,
        const float* __restrict__ w2n, const float* __restrict__ w2r,
        const float* __restrict__ b2,  const float* __restrict__ p2,
        const float* __restrict__ w3n, const float* __restrict__ w3r,
        const float* __restrict__ b3,  const float* __restrict__ p3,
        const float* __restrict__ lw1, const float* __restrict__ lb1,
        const float* __restrict__ lw2, const float* __restrict__ lb2,
        const float* __restrict__ lw3, const float* __restrict__ lb3,
        float* __restrict__ out) {
    extern __shared__ char raw[];
    MegaSm* S = (MegaSm*)raw;

    int b = blockIdx.x, tid = threadIdx.x;
    int w = tid >> 5, lane = tid & 31;

    // edges -> smem (local indices)
    for (int e = tid; e < EPG; e += NT) {
        S->esrc[e] = (unsigned short)(edge_index[b*EPG + e] - b*NP);
        S->edst[e] = (unsigned short)(edge_index[E_TOT + b*EPG + e] - b*NP);
    }
    // 1/||p|| for the three pool vectors
    if (w < 3) {
        const float* pv = (w == 0) ? p1 : ((w == 1) ? p2 : p3);
        float v = pv[lane]*pv[lane] + pv[lane+32]*pv[lane+32]
                + pv[lane+64]*pv[lane+64] + pv[lane+96]*pv[lane+96];
#pragma unroll
        for (int o = 16; o; o >>= 1) v += __shfl_down_sync(0xffffffffu, v, o);
        if (lane == 0) S->rns[w] = 1.0f / sqrtf(v);
    }
    if (tid < 256) S->harr[tid] = 0.0f;
    if (tid < 128) { S->bb[tid] = b1[tid]; S->ps[tid] = p1[tid]; }

    // As1: zero everything; fill emb features into cols 9..17 for v<200
    for (int idx = tid; idx < 208*28; idx += NT) {
        int r = idx / 28, c = idx - r*28;
        float v = 0.0f;
        if (r < NP && c >= 9 && c < 18)
            v = emb[(size_t)node_ids[b*NP + r] * EMB + (c - 9)];
        S->u.c1.As1[r][c] = v;
    }
    // W1 stage [w1n | w1r | pad]
    for (int idx = tid; idx < 128*28; idx += NT) {
        int r = idx / 28, c = idx - r*28;
        float wv = 0.0f;
        if (c < 9)       wv = w1n[r*9 + c];
        else if (c < 18) wv = w1r[r*9 + (c - 9)];
        S->u.c1.W1s[r][c] = wv;
    }
    __syncthreads();

    // ---------- level-1 9-dim aggregation ----------
    edge_sort(S, NP);
    for (int v = w; v < NP; v += NW) {
        int e0 = S->off[v], e1 = S->off[v+1];
        float inv = (e1 > e0) ? 1.0f / (float)(e1 - e0) : 0.0f;
        if (lane < EMB) {
            float a = 0.0f;
            for (int e = e0; e < e1; e++)
                a += S->u.c1.As1[S->eord[e]][9 + lane];
            S->u.c1.As1[v][lane] = a * inv;
        }
    }
    __syncthreads();

    // ---------- conv1 pass 1: score dot only (26 tasks, K=24) ----------
#pragma unroll
    for (int ti = 0; ti < 2; ti++) {
        int t = w + ti * NW;
        if (t < 26) {
            int rg = t >> 1, hf = t & 1;
            int rb = rg * 16 + (lane >> 2);
            float acc[8][4];
#pragma unroll
            for (int nt = 0; nt < 8; nt++)
#pragma unroll
                for (int i = 0; i < 4; i++) acc[nt][i] = 0.0f;
#pragma unroll
            for (int ks = 0; ks < 24; ks += 8) {
                int c = ks + (lane & 3);
                uint32_t a0 = __float_as_uint(S->u.c1.As1[rb][c]);
                uint32_t a1 = __float_as_uint(S->u.c1.As1[rb + 8][c]);
                uint32_t a2 = __float_as_uint(S->u.c1.As1[rb][c + 4]);
                uint32_t a3 = __float_as_uint(S->u.c1.As1[rb + 8][c + 4]);
#pragma unroll
                for (int nt = 0; nt < 8; nt++) {
                    int nr = hf * 64 + nt * 8 + (lane >> 2);
                    uint32_t b0 = __float_as_uint(S->u.c1.W1s[nr][c]);
                    uint32_t b1 = __float_as_uint(S->u.c1.W1s[nr][c + 4]);
                    mma_tf32(acc[nt], a0, a1, a2, a3, b0, b1);
                }
            }
            int r = rg * 16 + (lane >> 2);
            float pd0 = 0.0f, pd1 = 0.0f;
#pragma unroll
            for (int nt = 0; nt < 8; nt++) {
                int col = hf * 64 + nt * 8 + 2 * (lane & 3);
                pd0 += fmaxf(acc[nt][0] + S->bb[col],     0.0f) * S->ps[col]
                     + fmaxf(acc[nt][1] + S->bb[col + 1], 0.0f) * S->ps[col + 1];
                pd1 += fmaxf(acc[nt][2] + S->bb[col],     0.0f) * S->ps[col]
                     + fmaxf(acc[nt][3] + S->bb[col + 1], 0.0f) * S->ps[col + 1];
            }
            pd0 += __shfl_xor_sync(0xffffffffu, pd0, 1);
            pd0 += __shfl_xor_sync(0xffffffffu, pd0, 2);
            pd1 += __shfl_xor_sync(0xffffffffu, pd1, 1);
            pd1 += __shfl_xor_sync(0xffffffffu, pd1, 2);
            if ((lane & 3) == 0) { S->sdp[hf][r] = pd0; S->sdp[hf][r + 8] = pd1; }
        }
    }
    __syncthreads();

    for (int v = tid; v < NP; v += NT)
        S->s[v] = tanhf((S->sdp[0][v] + S->sdp[1][v]) * S->rns[0]);
    __syncthreads();

    level_rank(S, NP, K1);

    // ---------- conv1 pass 2: recompute kept rows, gain, write xs ----------
    {
        int rg = w >> 1, hf = w & 1;
        int r0 = rg * 16 + (lane >> 2);
        int k0 = S->kept[r0], k1 = S->kept[r0 + 8];
        float s0 = S->s[k0],  s1 = S->s[k1];
        float acc[8][4];
#pragma unroll
        for (int nt = 0; nt < 8; nt++)
#pragma unroll
            for (int i = 0; i < 4; i++) acc[nt][i] = 0.0f;
#pragma unroll
        for (int ks = 0; ks < 24; ks += 8) {
            int c = ks + (lane & 3);
            uint32_t a0 = __float_as_uint(S->u.c1.As1[k0][c]);
            uint32_t a1 = __float_as_uint(S->u.c1.As1[k1][c]);
            uint32_t a2 = __float_as_uint(S->u.c1.As1[k0][c + 4]);
            uint32_t a3 = __float_as_uint(S->u.c1.As1[k1][c + 4]);
#pragma unroll
            for (int nt = 0; nt < 8; nt++) {
                int nr = hf * 64 + nt * 8 + (lane >> 2);
                uint32_t b0 = __float_as_uint(S->u.c1.W1s[nr][c]);
                uint32_t b1 = __float_as_uint(S->u.c1.W1s[nr][c + 4]);
                mma_tf32(acc[nt], a0, a1, a2, a3, b0, b1);
            }
        }
#pragma unroll
        for (int nt = 0; nt < 8; nt++) {
            int col = hf * 64 + nt * 8 + 2 * (lane & 3);
            float v00 = fmaxf(acc[nt][0] + S->bb[col],     0.0f) * s0;
            float v01 = fmaxf(acc[nt][1] + S->bb[col + 1], 0.0f) * s0;
            float v10 = fmaxf(acc[nt][2] + S->bb[col],     0.0f) * s1;
            float v11 = fmaxf(acc[nt][3] + S->bb[col + 1], 0.0f) * s1;
            *(float2*)&S->xs[r0][col]     = make_float2(v00, v01);
            *(float2*)&S->xs[r0 + 8][col] = make_float2(v10, v11);
        }
    }
    __syncthreads();

    pool_xs(S, K1);
    level_remap(S);

    // ---------- level 2 ----------
    if (tid < 128) { S->bb[tid] = b2[tid]; S->ps[tid] = p2[tid]; }
    __syncthreads();
    level_agg(S, K1);
    level_gemm_topk(S, K1, K2, S->rns[1], w2n, w2r, true);

    // ---------- level 3 ----------
    if (tid < 128) { S->bb[tid] = b3[tid]; S->ps[tid] = p3[tid]; }
    __syncthreads();
    level_agg(S, K2);
    level_gemm_topk(S, K2, K3, S->rns[2], w3n, w3r, false);

    // ---------- MLP head (coalesced warp-cooperative) ----------
    for (int c = w; c < 128; c += NW) {
        float a = 0.0f;
#pragma unroll
        for (int j = 0; j < 8; j++)
            a += lw1[c*256 + j*32 + lane] * S->harr[j*32 + lane];
#pragma unroll
        for (int o = 16; o; o >>= 1) a += __shfl_xor_sync(0xffffffffu, a, o);
        if (lane == 0) S->h1[c] = fmaxf(a + lb1[c], 0.0f);
    }
    __syncthreads();
    for (int c = w; c < 64; c += NW) {
        float a = 0.0f;
#pragma unroll
        for (int j = 0; j < 4; j++)
            a += lw2[c*128 + j*32 + lane] * S->h1[j*32 + lane];
#pragma unroll
        for (int o = 16; o; o >>= 1) a += __shfl_xor_sync(0xffffffffu, a, o);
        if (lane == 0) S->h2[c] = fmaxf(a + lb2[c], 0.0f);
    }
    __syncthreads();
    if (w == 0) {
        float a = 0.0f;
#pragma unroll
        for (int j = 0; j < 2; j++)
            a += lw3[j*32 + lane] * S->h2[j*32 + lane];
#pragma unroll
        for (int o = 16; o; o >>= 1) a += __shfl_xor_sync(0xffffffffu, a, o);
        if (lane == 0) out[b] = 1.0f / (1.0f + expf(-(a + lb3[0])));
    }
}

// ---------------- launch ------------------------------------------------------
extern "C" void kernel_launch(void* const* d_in, const int* in_sizes, int n_in,
                              void* d_out, int out_size) {
    const int*   node_ids   = (const int*)d_in[0];
    const int*   edge_index = (const int*)d_in[1];
    const float* emb  = (const float*)d_in[3];
    const float* w1n  = (const float*)d_in[4];
    const float* w1r  = (const float*)d_in[5];
    const float* b1   = (const float*)d_in[6];
    const float* w2n  = (const float*)d_in[7];
    const float* w2r  = (const float*)d_in[8];
    const float* b2   = (const float*)d_in[9];
    const float* w3n  = (const float*)d_in[10];
    const float* w3r  = (const float*)d_in[11];
    const float* b3   = (const float*)d_in[12];
    const float* p1   = (const float*)d_in[13];
    const float* p2   = (const float*)d_in[14];
    const float* p3   = (const float*)d_in[15];
    const float* lw1  = (const float*)d_in[16];
    const float* lb1  = (const float*)d_in[17];
    const float* lw2  = (const float*)d_in[18];
    const float* lb2  = (const float*)d_in[19];
    const float* lw3  = (const float*)d_in[20];
    const float* lb3  = (const float*)d_in[21];
    float* out = (float*)d_out;

    static int smem_set = 0;
    if (!smem_set) {
        cudaFuncSetAttribute(mega_kernel,
                             cudaFuncAttributeMaxDynamicSharedMemorySize,
                             (int)sizeof(MegaSm));
        smem_set = 1;
    }

    mega_kernel<<<B, NT, sizeof(MegaSm)>>>(
        node_ids, edge_index, emb,
        w1n, w1r, b1, p1,
        w2n, w2r, b2, p2,
        w3n, w3r, b3, p3,
        lw1, lb1, lw2, lb2, lw3, lb3, out);
}

// round 8
// speedup vs baseline: 2.1081x; 1.0798x over previous
#include <cuda_runtime.h>
#include <math.h>
#include <stdint.h>

#define B    512
#define NP   200
#define EPG  2000
#define E_TOT (B*EPG)
#define HID  128
#define EMB  9
#define K1   160
#define K2   128
#define K3   103

#define NT   640           // threads
#define NW   20            // warps
#define INV_E 0xFFu
#define XSTR 132           // xs/ms row stride (floats): 132*4=528, 16B-aligned

// ---------------- async copy helpers -----------------------------------------
__device__ __forceinline__ void cp_async16(void* smem_dst, const void* gsrc) {
    uint32_t s = (uint32_t)__cvta_generic_to_shared(smem_dst);
    asm volatile("cp.async.ca.shared.global [%0], [%1], 16;\n" :: "r"(s), "l"(gsrc));
}
__device__ __forceinline__ void cp_commit() {
    asm volatile("cp.async.commit_group;\n" ::: "memory");
}
template<int N>
__device__ __forceinline__ void cp_wait() {
    asm volatile("cp.async.wait_group %0;\n" :: "n"(N) : "memory");
}

// ---------------- tf32 mma primitive -----------------------------------------
__device__ __forceinline__ void mma_tf32(float c[4], uint32_t a0, uint32_t a1,
                                         uint32_t a2, uint32_t a3,
                                         uint32_t b0, uint32_t b1) {
    asm volatile(
        "mma.sync.aligned.m16n8k8.row.col.f32.tf32.tf32.f32 "
        "{%0,%1,%2,%3}, {%4,%5,%6,%7}, {%8,%9}, {%0,%1,%2,%3};"
        : "+f"(c[0]), "+f"(c[1]), "+f"(c[2]), "+f"(c[3])
        : "r"(a0), "r"(a1), "r"(a2), "r"(a3), "r"(b0), "r"(b1));
}

// ---------------- mega kernel smem -------------------------------------------
struct MegaSm {
    float xs[160][XSTR];     // pooled features
    float ms[160][XSTR];     // neighbor means
    union {
        struct {             // conv1 phase
            float As1[208][28];   // [mean(9) | x(9) | pad] per node
            float W1s[128][28];   // [w1n | w1r | pad]
        } c1;
        float wst2[2][128][36];  // level-GEMM W k-chunk double buffer
    } u;
    float s[208];            // scores
    float sdp[4][208];       // deterministic 4-part score dot (conv1 uses 2)
    float bb[128];
    float ps[128];
    float harr[256];         // readout accumulator x1+x2+x3
    float pmax[5][128];
    float psum[5][128];
    float h1[128];
    float h2[64];
    float rns[3];
    int   hist[224];
    int   off[225];
    int   cur[224];
    int   wsum[8];
    short newloc[208];
    short kept[160];
    unsigned char esrc[EPG];
    unsigned char edst[EPG];
    unsigned char eord[EPG];
};

// parallel exclusive scan of hist[0..n) -> off/cur, off[n]=total
__device__ __forceinline__ void excl_scan(MegaSm* S, int n) {
    int tid = threadIdx.x, lane = tid & 31, w = tid >> 5;
    int npad = (n + 31) & ~31;
    if (tid < npad) {
        int h0 = S->hist[tid];
        int x = h0;
#pragma unroll
        for (int o = 1; o < 32; o <<= 1) {
            int y = __shfl_up_sync(0xffffffffu, x, o);
            if (lane >= o) x += y;
        }
        if (lane == 31) S->wsum[w] = x;
        S->off[tid] = x - h0;
    }
    __syncthreads();
    if (tid == 0) {
        int a = 0, nw = npad >> 5;
        for (int i = 0; i < nw; i++) { int t = S->wsum[i]; S->wsum[i] = a; a += t; }
        S->off[n] = a;
    }
    __syncthreads();
    if (tid < n) {
        int o = S->off[tid] + S->wsum[w];
        S->off[tid] = o;
        S->cur[tid] = o;
    }
    __syncthreads();
}

// counting sort of valid edges by dst into eord; optionally fuses the
// newloc remap (from the previous level's rank) into the histogram pass.
__device__ __forceinline__ void edge_sort(MegaSm* S, int n, bool do_remap) {
    int tid = threadIdx.x;
    int npad = (n + 31) & ~31;
    for (int i = tid; i < npad; i += NT) S->hist[i] = 0;
    __syncthreads();
    for (int e = tid; e < EPG; e += NT) {
        unsigned char sv = S->esrc[e];
        if (sv != INV_E) {
            if (do_remap) {
                short ns = S->newloc[sv];
                short nd = S->newloc[S->edst[e]];
                if (ns < 0 || nd < 0) { S->esrc[e] = (unsigned char)INV_E; }
                else {
                    S->esrc[e] = (unsigned char)ns;
                    S->edst[e] = (unsigned char)nd;
                    atomicAdd(&S->hist[nd], 1);
                }
            } else {
                atomicAdd(&S->hist[S->edst[e]], 1);
            }
        }
    }
    __syncthreads();
    excl_scan(S, n);
    for (int e = tid; e < EPG; e += NT) {
        unsigned char sv = S->esrc[e];
        if (sv != INV_E) {
            int p = atomicAdd(&S->cur[S->edst[e]], 1);
            S->eord[p] = sv;
        }
    }
    __syncthreads();
}

// 128-dim neighbor mean of xs into ms (float4 per lane)
__device__ __forceinline__ void level_agg(MegaSm* S, int n, bool do_remap) {
    edge_sort(S, n, do_remap);
    int tid = threadIdx.x, w = tid >> 5, lane = tid & 31;
    for (int v = w; v < n; v += NW) {
        int e0 = S->off[v], e1 = S->off[v+1];
        float inv = (e1 > e0) ? 1.0f / (float)(e1 - e0) : 0.0f;
        float4 a = make_float4(0.f, 0.f, 0.f, 0.f);
        float4 c = make_float4(0.f, 0.f, 0.f, 0.f);
        int e = e0;
        for (; e + 1 < e1; e += 2) {
            float4 p = *(const float4*)&S->xs[S->eord[e]][4*lane];
            float4 q = *(const float4*)&S->xs[S->eord[e+1]][4*lane];
            a.x += p.x; a.y += p.y; a.z += p.z; a.w += p.w;
            c.x += q.x; c.y += q.y; c.z += q.z; c.w += q.w;
        }
        if (e < e1) {
            float4 p = *(const float4*)&S->xs[S->eord[e]][4*lane];
            a.x += p.x; a.y += p.y; a.z += p.z; a.w += p.w;
        }
        *(float4*)&S->ms[v][4*lane] =
            make_float4((a.x + c.x) * inv, (a.y + c.y) * inv,
                        (a.z + c.z) * inv, (a.w + c.w) * inv);
    }
    __syncthreads();
}

__device__ __forceinline__ void level_rank(MegaSm* S, int n, int k) {
    int tid = threadIdx.x;
    for (int v = tid; v < n; v += NT) {
        float sv = S->s[v];
        int r = 0;
        for (int u = 0; u < n; u++) {
            float su = S->s[u];
            r += (su > sv) || (su == sv && u < v);
        }
        S->newloc[v] = (r < k) ? (short)r : (short)-1;
        if (r < k) S->kept[r] = (short)v;
    }
    __syncthreads();
}

// pool xs rows [0,k) into harr (5 row-slices across 640 threads)
__device__ __forceinline__ void pool_xs(MegaSm* S, int k) {
    int tid = threadIdx.x;
    int d = tid & 127, sl = tid >> 7;    // 0..4
    float mx = -INFINITY, sm = 0.0f;
    for (int r = sl; r < k; r += 5) {
        float v = S->xs[r][d];
        mx = fmaxf(mx, v);
        sm += v;
    }
    S->pmax[sl][d] = mx;
    S->psum[sl][d] = sm;
    __syncthreads();
    if (tid < 128) {
        float m = S->pmax[0][tid];
        float t = S->psum[0][tid];
#pragma unroll
        for (int i = 1; i < 5; i++) {
            m = fmaxf(m, S->pmax[i][tid]);
            t += S->psum[i][tid];
        }
        S->harr[tid]       += m;
        S->harr[128 + tid] += t / (float)k;
    }
    __syncthreads();
}

// stage one 32-k chunk of the level weights into wst2[buf]
__device__ __forceinline__ void stage_chunk(
        MegaSm* S, int buf, const float* __restrict__ Wn,
        const float* __restrict__ Wr, int ci) {
    const float* Wg = (ci < 4) ? Wn : Wr;
    int kg = (ci * 32) & 127;
    int tid = threadIdx.x;
    for (int idx = tid; idx < 1024; idx += NT) {
        int r = idx >> 3, q = idx & 7;
        cp_async16(&S->u.wst2[buf][r][q * 4], &Wg[r * 128 + kg + q * 4]);
    }
    cp_commit();
}

// level GEMM (relu([ms|xs] @ [Wn|Wr]^T + bb)), 32x32 warp tiles, deep
// double-buffered weight staging (chunks 0,1 pre-staged by caller),
// fused score+topk+scatter+pool.
__device__ __forceinline__ void level_gemm_topk(
        MegaSm* S, int n, int k, float rn,
        const float* __restrict__ Wn, const float* __restrict__ Wr) {
    int tid = threadIdx.x, lane = tid & 31, w = tid >> 5;
    int rg = w >> 2, cf = w & 3;
    bool active = (rg < (n >> 5));

    float acc[2][4][4];
#pragma unroll
    for (int mt = 0; mt < 2; mt++)
#pragma unroll
        for (int nt = 0; nt < 4; nt++)
#pragma unroll
            for (int i = 0; i < 4; i++) acc[mt][nt][i] = 0.0f;

#pragma unroll 1
    for (int ci = 0; ci < 8; ci++) {
        if (ci < 7) cp_wait<1>(); else cp_wait<0>();
        __syncthreads();

        int nb = ci & 1;
        if (active) {
            int kc = ci * 32;
            const float (*A)[XSTR] = (kc < 128) ? S->ms : S->xs;
            int kg = kc & 127;
#pragma unroll
            for (int ks = 0; ks < 32; ks += 8) {
                uint32_t a[2][4];
#pragma unroll
                for (int mt = 0; mt < 2; mt++) {
                    int rb = rg * 32 + mt * 16 + (lane >> 2);
                    int c = kg + ks + (lane & 3);
                    a[mt][0] = __float_as_uint(A[rb][c]);
                    a[mt][1] = __float_as_uint(A[rb + 8][c]);
                    a[mt][2] = __float_as_uint(A[rb][c + 4]);
                    a[mt][3] = __float_as_uint(A[rb + 8][c + 4]);
                }
#pragma unroll
                for (int nt = 0; nt < 4; nt++) {
                    int nr = cf * 32 + nt * 8 + (lane >> 2);
                    int cc = ks + (lane & 3);
                    uint32_t b0 = __float_as_uint(S->u.wst2[nb][nr][cc]);
                    uint32_t b1 = __float_as_uint(S->u.wst2[nb][nr][cc + 4]);
                    mma_tf32(acc[0][nt], a[0][0], a[0][1], a[0][2], a[0][3], b0, b1);
                    mma_tf32(acc[1][nt], a[1][0], a[1][1], a[1][2], a[1][3], b0, b1);
                }
            }
        }
        __syncthreads();
        if (ci + 2 < 8) stage_chunk(S, nb, Wn, Wr, ci + 2);
    }

    if (active) {
#pragma unroll
        for (int mt = 0; mt < 2; mt++) {
            int r = rg * 32 + mt * 16 + (lane >> 2);
            float pd0 = 0.0f, pd1 = 0.0f;
#pragma unroll
            for (int nt = 0; nt < 4; nt++) {
                int col = cf * 32 + nt * 8 + 2 * (lane & 3);
                float v00 = fmaxf(acc[mt][nt][0] + S->bb[col],     0.0f);
                float v01 = fmaxf(acc[mt][nt][1] + S->bb[col + 1], 0.0f);
                float v10 = fmaxf(acc[mt][nt][2] + S->bb[col],     0.0f);
                float v11 = fmaxf(acc[mt][nt][3] + S->bb[col + 1], 0.0f);
                acc[mt][nt][0] = v00; acc[mt][nt][1] = v01;
                acc[mt][nt][2] = v10; acc[mt][nt][3] = v11;
                pd0 += v00 * S->ps[col] + v01 * S->ps[col + 1];
                pd1 += v10 * S->ps[col] + v11 * S->ps[col + 1];
            }
            pd0 += __shfl_xor_sync(0xffffffffu, pd0, 1);
            pd0 += __shfl_xor_sync(0xffffffffu, pd0, 2);
            pd1 += __shfl_xor_sync(0xffffffffu, pd1, 1);
            pd1 += __shfl_xor_sync(0xffffffffu, pd1, 2);
            if ((lane & 3) == 0) { S->sdp[cf][r] = pd0; S->sdp[cf][r + 8] = pd1; }
        }
    }
    __syncthreads();

    for (int v = tid; v < n; v += NT)
        S->s[v] = tanhf(((S->sdp[0][v] + S->sdp[1][v]) +
                         (S->sdp[2][v] + S->sdp[3][v])) * rn);
    __syncthreads();

    level_rank(S, n, k);

    if (active) {
#pragma unroll
        for (int mt = 0; mt < 2; mt++) {
            int r = rg * 32 + mt * 16 + (lane >> 2);
            int nl0 = S->newloc[r], nl1 = S->newloc[r + 8];
            float s0 = S->s[r], s1 = S->s[r + 8];
#pragma unroll
            for (int nt = 0; nt < 4; nt++) {
                int col = cf * 32 + nt * 8 + 2 * (lane & 3);
                if (nl0 >= 0)
                    *(float2*)&S->xs[nl0][col] =
                        make_float2(acc[mt][nt][0] * s0, acc[mt][nt][1] * s0);
                if (nl1 >= 0)
                    *(float2*)&S->xs[nl1][col] =
                        make_float2(acc[mt][nt][2] * s1, acc[mt][nt][3] * s1);
            }
        }
    }
    __syncthreads();

    pool_xs(S, k);
}

// ---------------- the single fused kernel ------------------------------------
__global__ __launch_bounds__(NT, 1) void mega_kernel(
        const int* __restrict__ node_ids,
        const int* __restrict__ edge_index,
        const float* __restrict__ emb,
        const float* __restrict__ w1n, const float* __restrict__ w1r,
        const float* __restrict__ b1,  const float* __restrict__ p1,
        const float* __restrict__ w2n, const float* __restrict__ w2r,
        const float* __restrict__ b2,  const float* __restrict__ p2,
        const float* __restrict__ w3n, const float* __restrict__ w3r,
        const float* __restrict__ b3,  const float* __restrict__ p3,
        const float* __restrict__ lw1, const float* __restrict__ lb1,
        const float* __restrict__ lw2, const float* __restrict__ lb2,
        const float* __restrict__ lw3, const float* __restrict__ lb3,
        float* __restrict__ out) {
    extern __shared__ char raw[];
    MegaSm* S = (MegaSm*)raw;

    int b = blockIdx.x, tid = threadIdx.x;
    int w = tid >> 5, lane = tid & 31;

    // edges -> smem (uint8 local indices)
    for (int e = tid; e < EPG; e += NT) {
        S->esrc[e] = (unsigned char)(edge_index[b*EPG + e] - b*NP);
        S->edst[e] = (unsigned char)(edge_index[E_TOT + b*EPG + e] - b*NP);
    }
    // 1/||p|| for the three pool vectors
    if (w < 3) {
        const float* pv = (w == 0) ? p1 : ((w == 1) ? p2 : p3);
        float v = pv[lane]*pv[lane] + pv[lane+32]*pv[lane+32]
                + pv[lane+64]*pv[lane+64] + pv[lane+96]*pv[lane+96];
#pragma unroll
        for (int o = 16; o; o >>= 1) v += __shfl_down_sync(0xffffffffu, v, o);
        if (lane == 0) S->rns[w] = 1.0f / sqrtf(v);
    }
    if (tid < 256) S->harr[tid] = 0.0f;
    if (tid < 128) { S->bb[tid] = b1[tid]; S->ps[tid] = p1[tid]; }

    // As1: zero everything; fill emb features into cols 9..17 for v<200
    for (int idx = tid; idx < 208*28; idx += NT) {
        int r = idx / 28, c = idx - r*28;
        float v = 0.0f;
        if (r < NP && c >= 9 && c < 18)
            v = emb[(size_t)node_ids[b*NP + r] * EMB + (c - 9)];
        S->u.c1.As1[r][c] = v;
    }
    // W1 stage [w1n | w1r | pad]
    for (int idx = tid; idx < 128*28; idx += NT) {
        int r = idx / 28, c = idx - r*28;
        float wv = 0.0f;
        if (c < 9)       wv = w1n[r*9 + c];
        else if (c < 18) wv = w1r[r*9 + (c - 9)];
        S->u.c1.W1s[r][c] = wv;
    }
    __syncthreads();

    // ---------- level-1 9-dim aggregation ----------
    edge_sort(S, NP, false);
    for (int v = w; v < NP; v += NW) {
        int e0 = S->off[v], e1 = S->off[v+1];
        float inv = (e1 > e0) ? 1.0f / (float)(e1 - e0) : 0.0f;
        if (lane < EMB) {
            float a = 0.0f;
            for (int e = e0; e < e1; e++)
                a += S->u.c1.As1[S->eord[e]][9 + lane];
            S->u.c1.As1[v][lane] = a * inv;
        }
    }
    __syncthreads();

    // ---------- conv1 pass 1: score dot only (26 tasks, K=24, 16x64) ----------
#pragma unroll
    for (int ti = 0; ti < 2; ti++) {
        int t = w + ti * NW;
        if (t < 26) {
            int rg = t >> 1, hf = t & 1;
            int rb = rg * 16 + (lane >> 2);
            float acc[8][4];
#pragma unroll
            for (int nt = 0; nt < 8; nt++)
#pragma unroll
                for (int i = 0; i < 4; i++) acc[nt][i] = 0.0f;
#pragma unroll
            for (int ks = 0; ks < 24; ks += 8) {
                int c = ks + (lane & 3);
                uint32_t a0 = __float_as_uint(S->u.c1.As1[rb][c]);
                uint32_t a1 = __float_as_uint(S->u.c1.As1[rb + 8][c]);
                uint32_t a2 = __float_as_uint(S->u.c1.As1[rb][c + 4]);
                uint32_t a3 = __float_as_uint(S->u.c1.As1[rb + 8][c + 4]);
#pragma unroll
                for (int nt = 0; nt < 8; nt++) {
                    int nr = hf * 64 + nt * 8 + (lane >> 2);
                    uint32_t b0 = __float_as_uint(S->u.c1.W1s[nr][c]);
                    uint32_t b1 = __float_as_uint(S->u.c1.W1s[nr][c + 4]);
                    mma_tf32(acc[nt], a0, a1, a2, a3, b0, b1);
                }
            }
            int r = rg * 16 + (lane >> 2);
            float pd0 = 0.0f, pd1 = 0.0f;
#pragma unroll
            for (int nt = 0; nt < 8; nt++) {
                int col = hf * 64 + nt * 8 + 2 * (lane & 3);
                pd0 += fmaxf(acc[nt][0] + S->bb[col],     0.0f) * S->ps[col]
                     + fmaxf(acc[nt][1] + S->bb[col + 1], 0.0f) * S->ps[col + 1];
                pd1 += fmaxf(acc[nt][2] + S->bb[col],     0.0f) * S->ps[col]
                     + fmaxf(acc[nt][3] + S->bb[col + 1], 0.0f) * S->ps[col + 1];
            }
            pd0 += __shfl_xor_sync(0xffffffffu, pd0, 1);
            pd0 += __shfl_xor_sync(0xffffffffu, pd0, 2);
            pd1 += __shfl_xor_sync(0xffffffffu, pd1, 1);
            pd1 += __shfl_xor_sync(0xffffffffu, pd1, 2);
            if ((lane & 3) == 0) { S->sdp[hf][r] = pd0; S->sdp[hf][r + 8] = pd1; }
        }
    }
    __syncthreads();

    for (int v = tid; v < NP; v += NT)
        S->s[v] = tanhf((S->sdp[0][v] + S->sdp[1][v]) * S->rns[0]);
    __syncthreads();

    level_rank(S, NP, K1);

    // ---------- conv1 pass 2: recompute kept rows, gain, write xs ----------
    {
        int rg = w >> 1, hf = w & 1;
        int r0 = rg * 16 + (lane >> 2);
        int k0 = S->kept[r0], k1 = S->kept[r0 + 8];
        float s0 = S->s[k0],  s1 = S->s[k1];
        float acc[8][4];
#pragma unroll
        for (int nt = 0; nt < 8; nt++)
#pragma unroll
            for (int i = 0; i < 4; i++) acc[nt][i] = 0.0f;
#pragma unroll
        for (int ks = 0; ks < 24; ks += 8) {
            int c = ks + (lane & 3);
            uint32_t a0 = __float_as_uint(S->u.c1.As1[k0][c]);
            uint32_t a1 = __float_as_uint(S->u.c1.As1[k1][c]);
            uint32_t a2 = __float_as_uint(S->u.c1.As1[k0][c + 4]);
            uint32_t a3 = __float_as_uint(S->u.c1.As1[k1][c + 4]);
#pragma unroll
            for (int nt = 0; nt < 8; nt++) {
                int nr = hf * 64 + nt * 8 + (lane >> 2);
                uint32_t b0 = __float_as_uint(S->u.c1.W1s[nr][c]);
                uint32_t b1 = __float_as_uint(S->u.c1.W1s[nr][c + 4]);
                mma_tf32(acc[nt], a0, a1, a2, a3, b0, b1);
            }
        }
#pragma unroll
        for (int nt = 0; nt < 8; nt++) {
            int col = hf * 64 + nt * 8 + 2 * (lane & 3);
            float v00 = fmaxf(acc[nt][0] + S->bb[col],     0.0f) * s0;
            float v01 = fmaxf(acc[nt][1] + S->bb[col + 1], 0.0f) * s0;
            float v10 = fmaxf(acc[nt][2] + S->bb[col],     0.0f) * s1;
            float v11 = fmaxf(acc[nt][3] + S->bb[col + 1], 0.0f) * s1;
            *(float2*)&S->xs[r0][col]     = make_float2(v00, v01);
            *(float2*)&S->xs[r0 + 8][col] = make_float2(v10, v11);
        }
    }
    __syncthreads();

    pool_xs(S, K1);

    // ---------- level 2 ----------
    if (tid < 128) { S->bb[tid] = b2[tid]; S->ps[tid] = p2[tid]; }
    __syncthreads();
    stage_chunk(S, 0, w2n, w2r, 0);      // prefetch W chunks under agg
    stage_chunk(S, 1, w2n, w2r, 1);
    level_agg(S, K1, true);              // fused remap (newloc from topk1)
    level_gemm_topk(S, K1, K2, S->rns[1], w2n, w2r);

    // ---------- level 3 ----------
    if (tid < 128) { S->bb[tid] = b3[tid]; S->ps[tid] = p3[tid]; }
    __syncthreads();
    stage_chunk(S, 0, w3n, w3r, 0);
    stage_chunk(S, 1, w3n, w3r, 1);
    level_agg(S, K2, true);              // fused remap (newloc from topk2)
    level_gemm_topk(S, K2, K3, S->rns[2], w3n, w3r);

    // ---------- MLP head (coalesced warp-cooperative) ----------
    for (int c = w; c < 128; c += NW) {
        float a = 0.0f;
#pragma unroll
        for (int j = 0; j < 8; j++)
            a += lw1[c*256 + j*32 + lane] * S->harr[j*32 + lane];
#pragma unroll
        for (int o = 16; o; o >>= 1) a += __shfl_xor_sync(0xffffffffu, a, o);
        if (lane == 0) S->h1[c] = fmaxf(a + lb1[c], 0.0f);
    }
    __syncthreads();
    for (int c = w; c < 64; c += NW) {
        float a = 0.0f;
#pragma unroll
        for (int j = 0; j < 4; j++)
            a += lw2[c*128 + j*32 + lane] * S->h1[j*32 + lane];
#pragma unroll
        for (int o = 16; o; o >>= 1) a += __shfl_xor_sync(0xffffffffu, a, o);
        if (lane == 0) S->h2[c] = fmaxf(a + lb2[c], 0.0f);
    }
    __syncthreads();
    if (w == 0) {
        float a = 0.0f;
#pragma unroll
        for (int j = 0; j < 2; j++)
            a += lw3[j*32 + lane] * S->h2[j*32 + lane];
#pragma unroll
        for (int o = 16; o; o >>= 1) a += __shfl_xor_sync(0xffffffffu, a, o);
        if (lane == 0) out[b] = 1.0f / (1.0f + expf(-(a + lb3[0])));
    }
}

// ---------------- launch ------------------------------------------------------
extern "C" void kernel_launch(void* const* d_in, const int* in_sizes, int n_in,
                              void* d_out, int out_size) {
    const int*   node_ids   = (const int*)d_in[0];
    const int*   edge_index = (const int*)d_in[1];
    const float* emb  = (const float*)d_in[3];
    const float* w1n  = (const float*)d_in[4];
    const float* w1r  = (const float*)d_in[5];
    const float* b1   = (const float*)d_in[6];
    const float* w2n  = (const float*)d_in[7];
    const float* w2r  = (const float*)d_in[8];
    const float* b2   = (const float*)d_in[9];
    const float* w3n  = (const float*)d_in[10];
    const float* w3r  = (const float*)d_in[11];
    const float* b3   = (const float*)d_in[12];
    const float* p1   = (const float*)d_in[13];
    const float* p2   = (const float*)d_in[14];
    const float* p3   = (const float*)d_in[15];
    const float* lw1  = (const float*)d_in[16];
    const float* lb1  = (const float*)d_in[17];
    const float* lw2  = (const float*)d_in[18];
    const float* lb2  = (const float*)d_in[19];
    const float* lw3  = (const float*)d_in[20];
    const float* lb3  = (const float*)d_in[21];
    float* out = (float*)d_out;

    static int smem_set = 0;
    if (!smem_set) {
        cudaFuncSetAttribute(mega_kernel,
                             cudaFuncAttributeMaxDynamicSharedMemorySize,
                             (int)sizeof(MegaSm));
        smem_set = 1;
    }

    mega_kernel<<<B, NT, sizeof(MegaSm)>>>(
        node_ids, edge_index, emb,
        w1n, w1r, b1, p1,
        w2n, w2r, b2, p2,
        w3n, w3r, b3, p3,
        lw1, lb1, lw2, lb2, lw3, lb3, out);
}

// round 9
// speedup vs baseline: 2.1451x; 1.0176x over previous
#include <cuda_runtime.h>
#include <math.h>
#include <stdint.h>

#define B    512
#define NP   200
#define EPG  2000
#define E_TOT (B*EPG)
#define HID  128
#define EMB  9
#define K1   160
#define K2   128
#define K3   103

#define NT   768           // threads
#define NW   24            // warps
#define INV_E 0xFFu
#define XSTR 132           // xs/ms row stride (floats)

// ---------------- async copy helpers -----------------------------------------
__device__ __forceinline__ void cp_async16(void* smem_dst, const void* gsrc) {
    uint32_t s = (uint32_t)__cvta_generic_to_shared(smem_dst);
    asm volatile("cp.async.ca.shared.global [%0], [%1], 16;\n" :: "r"(s), "l"(gsrc));
}
__device__ __forceinline__ void cp_commit() {
    asm volatile("cp.async.commit_group;\n" ::: "memory");
}
template<int N>
__device__ __forceinline__ void cp_wait() {
    asm volatile("cp.async.wait_group %0;\n" :: "n"(N) : "memory");
}

// ---------------- tf32 mma primitive -----------------------------------------
__device__ __forceinline__ void mma_tf32(float c[4], uint32_t a0, uint32_t a1,
                                         uint32_t a2, uint32_t a3,
                                         uint32_t b0, uint32_t b1) {
    asm volatile(
        "mma.sync.aligned.m16n8k8.row.col.f32.tf32.tf32.f32 "
        "{%0,%1,%2,%3}, {%4,%5,%6,%7}, {%8,%9}, {%0,%1,%2,%3};"
        : "+f"(c[0]), "+f"(c[1]), "+f"(c[2]), "+f"(c[3])
        : "r"(a0), "r"(a1), "r"(a2), "r"(a3), "r"(b0), "r"(b1));
}

// ---------------- mega kernel smem -------------------------------------------
struct MegaSm {
    float xs[160][XSTR];     // pooled features
    float ms[160][XSTR];     // neighbor means
    union {
        struct {             // conv1 phase
            float As1[208][28];   // [mean(9) | x(9) | pad] per node
            float W1s[128][28];   // [w1n | w1r | pad]
        } c1;
        float wst2[2][128][36];  // level-GEMM W k-chunk double buffer
    } u;
    float s[208];            // scores
    float sdp[4][208];       // deterministic 4-part score dot (conv1 uses 2)
    float bb[128];
    float ps[128];
    float harr[256];         // readout accumulator x1+x2+x3
    float pmax[6][128];
    float psum[6][128];
    float h1[128];
    float h2[64];
    float rns[3];
    int   hist[224];
    int   off[225];
    int   cur[224];
    int   wsum[8];
    short newloc[208];
    short kept[160];
    unsigned char esrc[EPG];
    unsigned char edst[EPG];
    unsigned char eord[EPG];
};

// parallel exclusive scan of hist[0..n) -> off/cur, off[n]=total
__device__ __forceinline__ void excl_scan(MegaSm* S, int n) {
    int tid = threadIdx.x, lane = tid & 31, w = tid >> 5;
    int npad = (n + 31) & ~31;
    if (tid < npad) {
        int h0 = S->hist[tid];
        int x = h0;
#pragma unroll
        for (int o = 1; o < 32; o <<= 1) {
            int y = __shfl_up_sync(0xffffffffu, x, o);
            if (lane >= o) x += y;
        }
        if (lane == 31) S->wsum[w] = x;
        S->off[tid] = x - h0;
    }
    __syncthreads();
    if (tid == 0) {
        int a = 0, nw = npad >> 5;
        for (int i = 0; i < nw; i++) { int t = S->wsum[i]; S->wsum[i] = a; a += t; }
        S->off[n] = a;
    }
    __syncthreads();
    if (tid < n) {
        int o = S->off[tid] + S->wsum[w];
        S->off[tid] = o;
        S->cur[tid] = o;
    }
    __syncthreads();
}

// counting sort of valid edges by dst into eord; optionally fuses the
// newloc remap (from the previous level's rank) into the histogram pass.
__device__ __forceinline__ void edge_sort(MegaSm* S, int n, bool do_remap) {
    int tid = threadIdx.x;
    int npad = (n + 31) & ~31;
    for (int i = tid; i < npad; i += NT) S->hist[i] = 0;
    __syncthreads();
    for (int e = tid; e < EPG; e += NT) {
        unsigned char sv = S->esrc[e];
        if (sv != INV_E) {
            if (do_remap) {
                short ns = S->newloc[sv];
                short nd = S->newloc[S->edst[e]];
                if (ns < 0 || nd < 0) { S->esrc[e] = (unsigned char)INV_E; }
                else {
                    S->esrc[e] = (unsigned char)ns;
                    S->edst[e] = (unsigned char)nd;
                    atomicAdd(&S->hist[nd], 1);
                }
            } else {
                atomicAdd(&S->hist[S->edst[e]], 1);
            }
        }
    }
    __syncthreads();
    excl_scan(S, n);
    for (int e = tid; e < EPG; e += NT) {
        unsigned char sv = S->esrc[e];
        if (sv != INV_E) {
            int p = atomicAdd(&S->cur[S->edst[e]], 1);
            S->eord[p] = sv;
        }
    }
    __syncthreads();
}

// 128-dim neighbor mean of xs into ms (float4 per lane)
__device__ __forceinline__ void level_agg(MegaSm* S, int n, bool do_remap) {
    edge_sort(S, n, do_remap);
    int tid = threadIdx.x, w = tid >> 5, lane = tid & 31;
    for (int v = w; v < n; v += NW) {
        int e0 = S->off[v], e1 = S->off[v+1];
        float inv = (e1 > e0) ? 1.0f / (float)(e1 - e0) : 0.0f;
        float4 a = make_float4(0.f, 0.f, 0.f, 0.f);
        float4 c = make_float4(0.f, 0.f, 0.f, 0.f);
        int e = e0;
        for (; e + 1 < e1; e += 2) {
            float4 p = *(const float4*)&S->xs[S->eord[e]][4*lane];
            float4 q = *(const float4*)&S->xs[S->eord[e+1]][4*lane];
            a.x += p.x; a.y += p.y; a.z += p.z; a.w += p.w;
            c.x += q.x; c.y += q.y; c.z += q.z; c.w += q.w;
        }
        if (e < e1) {
            float4 p = *(const float4*)&S->xs[S->eord[e]][4*lane];
            a.x += p.x; a.y += p.y; a.z += p.z; a.w += p.w;
        }
        *(float4*)&S->ms[v][4*lane] =
            make_float4((a.x + c.x) * inv, (a.y + c.y) * inv,
                        (a.z + c.z) * inv, (a.w + c.w) * inv);
    }
    __syncthreads();
}

// 3-way split rank: thread (v = tid&255, part = tid>>8) counts 1/3 of the
// u-range; integer partials combined via smem atomics (deterministic).
__device__ __forceinline__ void level_rank(MegaSm* S, int n, int k) {
    int tid = threadIdx.x;
    for (int i = tid; i < n; i += NT) S->hist[i] = 0;
    __syncthreads();
    int v = tid & 255;
    int part = tid >> 8;                 // 0..2 (768 = 3*256)
    if (v < n) {
        int chunk = (n + 2) / 3;
        int u0 = part * chunk;
        int u1 = min(n, u0 + chunk);
        float sv = S->s[v];
        int r = 0;
        for (int u = u0; u < u1; u++) {
            float su = S->s[u];
            r += (su > sv) || (su == sv && u < v);
        }
        atomicAdd(&S->hist[v], r);
    }
    __syncthreads();
    for (int v2 = tid; v2 < n; v2 += NT) {
        int r = S->hist[v2];
        S->newloc[v2] = (r < k) ? (short)r : (short)-1;
        if (r < k) S->kept[r] = (short)v2;
    }
    __syncthreads();
}

// pool xs rows [0,k) into harr (6 row-slices across 768 threads)
__device__ __forceinline__ void pool_xs(MegaSm* S, int k) {
    int tid = threadIdx.x;
    int d = tid & 127, sl = tid >> 7;    // 0..5
    float mx = -INFINITY, sm = 0.0f;
    for (int r = sl; r < k; r += 6) {
        float v = S->xs[r][d];
        mx = fmaxf(mx, v);
        sm += v;
    }
    S->pmax[sl][d] = mx;
    S->psum[sl][d] = sm;
    __syncthreads();
    if (tid < 128) {
        float m = S->pmax[0][tid];
        float t = S->psum[0][tid];
#pragma unroll
        for (int i = 1; i < 6; i++) {
            m = fmaxf(m, S->pmax[i][tid]);
            t += S->psum[i][tid];
        }
        S->harr[tid]       += m;
        S->harr[128 + tid] += t / (float)k;
    }
    __syncthreads();
}

// stage one 32-k chunk of the level weights into wst2[buf]
__device__ __forceinline__ void stage_chunk(
        MegaSm* S, int buf, const float* __restrict__ Wn,
        const float* __restrict__ Wr, int ci) {
    const float* Wg = (ci < 4) ? Wn : Wr;
    int kg = (ci * 32) & 127;
    int tid = threadIdx.x;
    for (int idx = tid; idx < 1024; idx += NT) {
        int r = idx >> 3, q = idx & 7;
        cp_async16(&S->u.wst2[buf][r][q * 4], &Wg[r * 128 + kg + q * 4]);
    }
    cp_commit();
}

// level GEMM (relu([ms|xs] @ [Wn|Wr]^T + bb)), 32x32 warp tiles, deep
// double-buffered weight staging (chunks 0,1 pre-staged by caller),
// fused score+topk+scatter+pool.
__device__ __forceinline__ void level_gemm_topk(
        MegaSm* S, int n, int k, float rn,
        const float* __restrict__ Wn, const float* __restrict__ Wr) {
    int tid = threadIdx.x, lane = tid & 31, w = tid >> 5;
    int rg = w >> 2, cf = w & 3;
    bool active = (rg < (n >> 5));

    float acc[2][4][4];
#pragma unroll
    for (int mt = 0; mt < 2; mt++)
#pragma unroll
        for (int nt = 0; nt < 4; nt++)
#pragma unroll
            for (int i = 0; i < 4; i++) acc[mt][nt][i] = 0.0f;

#pragma unroll 1
    for (int ci = 0; ci < 8; ci++) {
        if (ci < 7) cp_wait<1>(); else cp_wait<0>();
        __syncthreads();

        int nb = ci & 1;
        if (active) {
            int kc = ci * 32;
            const float (*A)[XSTR] = (kc < 128) ? S->ms : S->xs;
            int kg = kc & 127;
#pragma unroll
            for (int ks = 0; ks < 32; ks += 8) {
                uint32_t a[2][4];
#pragma unroll
                for (int mt = 0; mt < 2; mt++) {
                    int rb = rg * 32 + mt * 16 + (lane >> 2);
                    int c = kg + ks + (lane & 3);
                    a[mt][0] = __float_as_uint(A[rb][c]);
                    a[mt][1] = __float_as_uint(A[rb + 8][c]);
                    a[mt][2] = __float_as_uint(A[rb][c + 4]);
                    a[mt][3] = __float_as_uint(A[rb + 8][c + 4]);
                }
#pragma unroll
                for (int nt = 0; nt < 4; nt++) {
                    int nr = cf * 32 + nt * 8 + (lane >> 2);
                    int cc = ks + (lane & 3);
                    uint32_t b0 = __float_as_uint(S->u.wst2[nb][nr][cc]);
                    uint32_t b1 = __float_as_uint(S->u.wst2[nb][nr][cc + 4]);
                    mma_tf32(acc[0][nt], a[0][0], a[0][1], a[0][2], a[0][3], b0, b1);
                    mma_tf32(acc[1][nt], a[1][0], a[1][1], a[1][2], a[1][3], b0, b1);
                }
            }
        }
        __syncthreads();
        if (ci + 2 < 8) stage_chunk(S, nb, Wn, Wr, ci + 2);
    }

    if (active) {
#pragma unroll
        for (int mt = 0; mt < 2; mt++) {
            int r = rg * 32 + mt * 16 + (lane >> 2);
            float pd0 = 0.0f, pd1 = 0.0f;
#pragma unroll
            for (int nt = 0; nt < 4; nt++) {
                int col = cf * 32 + nt * 8 + 2 * (lane & 3);
                float v00 = fmaxf(acc[mt][nt][0] + S->bb[col],     0.0f);
                float v01 = fmaxf(acc[mt][nt][1] + S->bb[col + 1], 0.0f);
                float v10 = fmaxf(acc[mt][nt][2] + S->bb[col],     0.0f);
                float v11 = fmaxf(acc[mt][nt][3] + S->bb[col + 1], 0.0f);
                acc[mt][nt][0] = v00; acc[mt][nt][1] = v01;
                acc[mt][nt][2] = v10; acc[mt][nt][3] = v11;
                pd0 += v00 * S->ps[col] + v01 * S->ps[col + 1];
                pd1 += v10 * S->ps[col] + v11 * S->ps[col + 1];
            }
            pd0 += __shfl_xor_sync(0xffffffffu, pd0, 1);
            pd0 += __shfl_xor_sync(0xffffffffu, pd0, 2);
            pd1 += __shfl_xor_sync(0xffffffffu, pd1, 1);
            pd1 += __shfl_xor_sync(0xffffffffu, pd1, 2);
            if ((lane & 3) == 0) { S->sdp[cf][r] = pd0; S->sdp[cf][r + 8] = pd1; }
        }
    }
    __syncthreads();

    for (int v = tid; v < n; v += NT)
        S->s[v] = tanhf(((S->sdp[0][v] + S->sdp[1][v]) +
                         (S->sdp[2][v] + S->sdp[3][v])) * rn);
    __syncthreads();

    level_rank(S, n, k);

    if (active) {
#pragma unroll
        for (int mt = 0; mt < 2; mt++) {
            int r = rg * 32 + mt * 16 + (lane >> 2);
            int nl0 = S->newloc[r], nl1 = S->newloc[r + 8];
            float s0 = S->s[r], s1 = S->s[r + 8];
#pragma unroll
            for (int nt = 0; nt < 4; nt++) {
                int col = cf * 32 + nt * 8 + 2 * (lane & 3);
                if (nl0 >= 0)
                    *(float2*)&S->xs[nl0][col] =
                        make_float2(acc[mt][nt][0] * s0, acc[mt][nt][1] * s0);
                if (nl1 >= 0)
                    *(float2*)&S->xs[nl1][col] =
                        make_float2(acc[mt][nt][2] * s1, acc[mt][nt][3] * s1);
            }
        }
    }
    __syncthreads();

    pool_xs(S, k);
}

// ---------------- the single fused kernel ------------------------------------
__global__ __launch_bounds__(NT, 1) void mega_kernel(
        const int* __restrict__ node_ids,
        const int* __restrict__ edge_index,
        const float* __restrict__ emb,
        const float* __restrict__ w1n, const float* __restrict__ w1r,
        const float* __restrict__ b1,  const float* __restrict__ p1,
        const float* __restrict__ w2n, const float* __restrict__ w2r,
        const float* __restrict__ b2,  const float* __restrict__ p2,
        const float* __restrict__ w3n, const float* __restrict__ w3r,
        const float* __restrict__ b3,  const float* __restrict__ p3,
        const float* __restrict__ lw1, const float* __restrict__ lb1,
        const float* __restrict__ lw2, const float* __restrict__ lb2,
        const float* __restrict__ lw3, const float* __restrict__ lb3,
        float* __restrict__ out) {
    extern __shared__ char raw[];
    MegaSm* S = (MegaSm*)raw;

    int b = blockIdx.x, tid = threadIdx.x;
    int w = tid >> 5, lane = tid & 31;

    // edges -> smem (uint8 local indices)
    for (int e = tid; e < EPG; e += NT) {
        S->esrc[e] = (unsigned char)(edge_index[b*EPG + e] - b*NP);
        S->edst[e] = (unsigned char)(edge_index[E_TOT + b*EPG + e] - b*NP);
    }
    // 1/||p|| for the three pool vectors
    if (w < 3) {
        const float* pv = (w == 0) ? p1 : ((w == 1) ? p2 : p3);
        float v = pv[lane]*pv[lane] + pv[lane+32]*pv[lane+32]
                + pv[lane+64]*pv[lane+64] + pv[lane+96]*pv[lane+96];
#pragma unroll
        for (int o = 16; o; o >>= 1) v += __shfl_down_sync(0xffffffffu, v, o);
        if (lane == 0) S->rns[w] = 1.0f / sqrtf(v);
    }
    if (tid < 256) S->harr[tid] = 0.0f;
    if (tid < 128) { S->bb[tid] = b1[tid]; S->ps[tid] = p1[tid]; }

    // As1: zero everything; fill emb features into cols 9..17 for v<200
    for (int idx = tid; idx < 208*28; idx += NT) {
        int r = idx / 28, c = idx - r*28;
        float v = 0.0f;
        if (r < NP && c >= 9 && c < 18)
            v = emb[(size_t)node_ids[b*NP + r] * EMB + (c - 9)];
        S->u.c1.As1[r][c] = v;
    }
    // W1 stage [w1n | w1r | pad]
    for (int idx = tid; idx < 128*28; idx += NT) {
        int r = idx / 28, c = idx - r*28;
        float wv = 0.0f;
        if (c < 9)       wv = w1n[r*9 + c];
        else if (c < 18) wv = w1r[r*9 + (c - 9)];
        S->u.c1.W1s[r][c] = wv;
    }
    __syncthreads();

    // ---------- level-1 9-dim aggregation ----------
    edge_sort(S, NP, false);
    for (int v = w; v < NP; v += NW) {
        int e0 = S->off[v], e1 = S->off[v+1];
        float inv = (e1 > e0) ? 1.0f / (float)(e1 - e0) : 0.0f;
        if (lane < EMB) {
            float a = 0.0f;
            for (int e = e0; e < e1; e++)
                a += S->u.c1.As1[S->eord[e]][9 + lane];
            S->u.c1.As1[v][lane] = a * inv;
        }
    }
    __syncthreads();

    // ---------- conv1 pass 1: score dot only (26 tasks, K=24, 16x64) ----------
#pragma unroll
    for (int ti = 0; ti < 2; ti++) {
        int t = w + ti * NW;
        if (t < 26) {
            int rg = t >> 1, hf = t & 1;
            int rb = rg * 16 + (lane >> 2);
            float acc[8][4];
#pragma unroll
            for (int nt = 0; nt < 8; nt++)
#pragma unroll
                for (int i = 0; i < 4; i++) acc[nt][i] = 0.0f;
#pragma unroll
            for (int ks = 0; ks < 24; ks += 8) {
                int c = ks + (lane & 3);
                uint32_t a0 = __float_as_uint(S->u.c1.As1[rb][c]);
                uint32_t a1 = __float_as_uint(S->u.c1.As1[rb + 8][c]);
                uint32_t a2 = __float_as_uint(S->u.c1.As1[rb][c + 4]);
                uint32_t a3 = __float_as_uint(S->u.c1.As1[rb + 8][c + 4]);
#pragma unroll
                for (int nt = 0; nt < 8; nt++) {
                    int nr = hf * 64 + nt * 8 + (lane >> 2);
                    uint32_t b0 = __float_as_uint(S->u.c1.W1s[nr][c]);
                    uint32_t b1 = __float_as_uint(S->u.c1.W1s[nr][c + 4]);
                    mma_tf32(acc[nt], a0, a1, a2, a3, b0, b1);
                }
            }
            int r = rg * 16 + (lane >> 2);
            float pd0 = 0.0f, pd1 = 0.0f;
#pragma unroll
            for (int nt = 0; nt < 8; nt++) {
                int col = hf * 64 + nt * 8 + 2 * (lane & 3);
                pd0 += fmaxf(acc[nt][0] + S->bb[col],     0.0f) * S->ps[col]
                     + fmaxf(acc[nt][1] + S->bb[col + 1], 0.0f) * S->ps[col + 1];
                pd1 += fmaxf(acc[nt][2] + S->bb[col],     0.0f) * S->ps[col]
                     + fmaxf(acc[nt][3] + S->bb[col + 1], 0.0f) * S->ps[col + 1];
            }
            pd0 += __shfl_xor_sync(0xffffffffu, pd0, 1);
            pd0 += __shfl_xor_sync(0xffffffffu, pd0, 2);
            pd1 += __shfl_xor_sync(0xffffffffu, pd1, 1);
            pd1 += __shfl_xor_sync(0xffffffffu, pd1, 2);
            if ((lane & 3) == 0) { S->sdp[hf][r] = pd0; S->sdp[hf][r + 8] = pd1; }
        }
    }
    __syncthreads();

    for (int v = tid; v < NP; v += NT)
        S->s[v] = tanhf((S->sdp[0][v] + S->sdp[1][v]) * S->rns[0]);
    __syncthreads();

    level_rank(S, NP, K1);

    // ---------- conv1 pass 2: recompute kept rows, gain, write xs ----------
    if (w < 20) {
        int rg = w >> 1, hf = w & 1;
        int r0 = rg * 16 + (lane >> 2);
        int k0 = S->kept[r0], k1 = S->kept[r0 + 8];
        float s0 = S->s[k0],  s1 = S->s[k1];
        float acc[8][4];
#pragma unroll
        for (int nt = 0; nt < 8; nt++)
#pragma unroll
            for (int i = 0; i < 4; i++) acc[nt][i] = 0.0f;
#pragma unroll
        for (int ks = 0; ks < 24; ks += 8) {
            int c = ks + (lane & 3);
            uint32_t a0 = __float_as_uint(S->u.c1.As1[k0][c]);
            uint32_t a1 = __float_as_uint(S->u.c1.As1[k1][c]);
            uint32_t a2 = __float_as_uint(S->u.c1.As1[k0][c + 4]);
            uint32_t a3 = __float_as_uint(S->u.c1.As1[k1][c + 4]);
#pragma unroll
            for (int nt = 0; nt < 8; nt++) {
                int nr = hf * 64 + nt * 8 + (lane >> 2);
                uint32_t b0 = __float_as_uint(S->u.c1.W1s[nr][c]);
                uint32_t b1 = __float_as_uint(S->u.c1.W1s[nr][c + 4]);
                mma_tf32(acc[nt], a0, a1, a2, a3, b0, b1);
            }
        }
#pragma unroll
        for (int nt = 0; nt < 8; nt++) {
            int col = hf * 64 + nt * 8 + 2 * (lane & 3);
            float v00 = fmaxf(acc[nt][0] + S->bb[col],     0.0f) * s0;
            float v01 = fmaxf(acc[nt][1] + S->bb[col + 1], 0.0f) * s0;
            float v10 = fmaxf(acc[nt][2] + S->bb[col],     0.0f) * s1;
            float v11 = fmaxf(acc[nt][3] + S->bb[col + 1], 0.0f) * s1;
            *(float2*)&S->xs[r0][col]     = make_float2(v00, v01);
            *(float2*)&S->xs[r0 + 8][col] = make_float2(v10, v11);
        }
    }
    __syncthreads();

    pool_xs(S, K1);

    // ---------- level 2 ----------
    if (tid < 128) { S->bb[tid] = b2[tid]; S->ps[tid] = p2[tid]; }
    __syncthreads();
    stage_chunk(S, 0, w2n, w2r, 0);      // prefetch W chunks under agg
    stage_chunk(S, 1, w2n, w2r, 1);
    level_agg(S, K1, true);              // fused remap (newloc from topk1)
    level_gemm_topk(S, K1, K2, S->rns[1], w2n, w2r);

    // ---------- level 3 ----------
    if (tid < 128) { S->bb[tid] = b3[tid]; S->ps[tid] = p3[tid]; }
    __syncthreads();
    stage_chunk(S, 0, w3n, w3r, 0);
    stage_chunk(S, 1, w3n, w3r, 1);
    level_agg(S, K2, true);              // fused remap (newloc from topk2)
    level_gemm_topk(S, K2, K3, S->rns[2], w3n, w3r);

    // ---------- MLP head (coalesced warp-cooperative) ----------
    for (int c = w; c < 128; c += NW) {
        float a = 0.0f;
#pragma unroll
        for (int j = 0; j < 8; j++)
            a += lw1[c*256 + j*32 + lane] * S->harr[j*32 + lane];
#pragma unroll
        for (int o = 16; o; o >>= 1) a += __shfl_xor_sync(0xffffffffu, a, o);
        if (lane == 0) S->h1[c] = fmaxf(a + lb1[c], 0.0f);
    }
    __syncthreads();
    for (int c = w; c < 64; c += NW) {
        float a = 0.0f;
#pragma unroll
        for (int j = 0; j < 4; j++)
            a += lw2[c*128 + j*32 + lane] * S->h1[j*32 + lane];
#pragma unroll
        for (int o = 16; o; o >>= 1) a += __shfl_xor_sync(0xffffffffu, a, o);
        if (lane == 0) S->h2[c] = fmaxf(a + lb2[c], 0.0f);
    }
    __syncthreads();
    if (w == 0) {
        float a = 0.0f;
#pragma unroll
        for (int j = 0; j < 2; j++)
            a += lw3[j*32 + lane] * S->h2[j*32 + lane];
#pragma unroll
        for (int o = 16; o; o >>= 1) a += __shfl_xor_sync(0xffffffffu, a, o);
        if (lane == 0) out[b] = 1.0f / (1.0f + expf(-(a + lb3[0])));
    }
}

// ---------------- launch ------------------------------------------------------
extern "C" void kernel_launch(void* const* d_in, const int* in_sizes, int n_in,
                              void* d_out, int out_size) {
    const int*   node_ids   = (const int*)d_in[0];
    const int*   edge_index = (const int*)d_in[1];
    const float* emb  = (const float*)d_in[3];
    const float* w1n  = (const float*)d_in[4];
    const float* w1r  = (const float*)d_in[5];
    const float* b1   = (const float*)d_in[6];
    const float* w2n  = (const float*)d_in[7];
    const float* w2r  = (const float*)d_in[8];
    const float* b2   = (const float*)d_in[9];
    const float* w3n  = (const float*)d_in[10];
    const float* w3r  = (const float*)d_in[11];
    const float* b3   = (const float*)d_in[12];
    const float* p1   = (const float*)d_in[13];
    const float* p2   = (const float*)d_in[14];
    const float* p3   = (const float*)d_in[15];
    const float* lw1  = (const float*)d_in[16];
    const float* lb1  = (const float*)d_in[17];
    const float* lw2  = (const float*)d_in[18];
    const float* lb2  = (const float*)d_in[19];
    const float* lw3  = (const float*)d_in[20];
    const float* lb3  = (const float*)d_in[21];
    float* out = (float*)d_out;

    static int smem_set = 0;
    if (!smem_set) {
        cudaFuncSetAttribute(mega_kernel,
                             cudaFuncAttributeMaxDynamicSharedMemorySize,
                             (int)sizeof(MegaSm));
        smem_set = 1;
    }

    mega_kernel<<<B, NT, sizeof(MegaSm)>>>(
        node_ids, edge_index, emb,
        w1n, w1r, b1, p1,
        w2n, w2r, b2, p2,
        w3n, w3r, b3, p3,
        lw1, lb1, lw2, lb2, lw3, lb3, out);
}

// round 10
// speedup vs baseline: 2.1473x; 1.0010x over previous
#include <cuda_runtime.h>
#include <math.h>
#include <stdint.h>

#define B    512
#define NP   200
#define EPG  2000
#define E_TOT (B*EPG)
#define HID  128
#define EMB  9
#define K1   160
#define K2   128
#define K3   103

#define NT   768           // threads
#define NW   24            // warps
#define INV_E 0xFFu
#define XSTR 132           // xs/ms row stride (floats)

// ---------------- async copy helpers -----------------------------------------
__device__ __forceinline__ void cp_async16(void* smem_dst, const void* gsrc) {
    uint32_t s = (uint32_t)__cvta_generic_to_shared(smem_dst);
    asm volatile("cp.async.ca.shared.global [%0], [%1], 16;\n" :: "r"(s), "l"(gsrc));
}
__device__ __forceinline__ void cp_commit() {
    asm volatile("cp.async.commit_group;\n" ::: "memory");
}
template<int N>
__device__ __forceinline__ void cp_wait() {
    asm volatile("cp.async.wait_group %0;\n" :: "n"(N) : "memory");
}

// ---------------- tf32 mma primitive -----------------------------------------
__device__ __forceinline__ void mma_tf32(float c[4], uint32_t a0, uint32_t a1,
                                         uint32_t a2, uint32_t a3,
                                         uint32_t b0, uint32_t b1) {
    asm volatile(
        "mma.sync.aligned.m16n8k8.row.col.f32.tf32.tf32.f32 "
        "{%0,%1,%2,%3}, {%4,%5,%6,%7}, {%8,%9}, {%0,%1,%2,%3};"
        : "+f"(c[0]), "+f"(c[1]), "+f"(c[2]), "+f"(c[3])
        : "r"(a0), "r"(a1), "r"(a2), "r"(a3), "r"(b0), "r"(b1));
}

// ---------------- mega kernel smem -------------------------------------------
struct MegaSm {
    float xs[160][XSTR];     // pooled features
    float ms[160][XSTR];     // neighbor means
    union {
        struct {             // conv1 phase
            float As1[208][28];   // [mean(9) | x(9) | pad] per node
            float W1s[128][28];   // [w1n | w1r | pad]
        } c1;
        float wst2[2][128][36];  // level-GEMM W k-chunk double buffer
    } u;
    float s[208];            // scores (n is always a multiple of 4)
    float sdp[4][208];       // deterministic 4-part score dot (conv1 uses 2)
    float bb[128];
    float ps[128];
    float harr[256];         // readout accumulator x1+x2+x3
    float pmax[6][128];
    float psum[6][128];
    float h1[128];
    float h2[64];
    float rns[3];
    int   hist[224];
    int   off[225];
    int   cur[224];
    int   wsum[8];
    short newloc[208];
    short kept[160];
    unsigned char esrc[EPG];
    unsigned char edst[EPG];
    unsigned char eord[EPG];
};

// parallel exclusive scan of hist[0..n) -> off/cur, off[n]=total
__device__ __forceinline__ void excl_scan(MegaSm* S, int n) {
    int tid = threadIdx.x, lane = tid & 31, w = tid >> 5;
    int npad = (n + 31) & ~31;
    if (tid < npad) {
        int h0 = S->hist[tid];
        int x = h0;
#pragma unroll
        for (int o = 1; o < 32; o <<= 1) {
            int y = __shfl_up_sync(0xffffffffu, x, o);
            if (lane >= o) x += y;
        }
        if (lane == 31) S->wsum[w] = x;
        S->off[tid] = x - h0;
    }
    __syncthreads();
    if (tid == 0) {
        int a = 0, nw = npad >> 5;
        for (int i = 0; i < nw; i++) { int t = S->wsum[i]; S->wsum[i] = a; a += t; }
        S->off[n] = a;
    }
    __syncthreads();
    if (tid < n) {
        int o = S->off[tid] + S->wsum[w];
        S->off[tid] = o;
        S->cur[tid] = o;
    }
    __syncthreads();
}

// counting sort of valid edges by dst into eord; optionally fuses the
// newloc remap (from the previous level's rank) into the histogram pass.
__device__ __forceinline__ void edge_sort(MegaSm* S, int n, bool do_remap) {
    int tid = threadIdx.x;
    int npad = (n + 31) & ~31;
    for (int i = tid; i < npad; i += NT) S->hist[i] = 0;
    __syncthreads();
    for (int e = tid; e < EPG; e += NT) {
        unsigned char sv = S->esrc[e];
        if (sv != INV_E) {
            if (do_remap) {
                short ns = S->newloc[sv];
                short nd = S->newloc[S->edst[e]];
                if (ns < 0 || nd < 0) { S->esrc[e] = (unsigned char)INV_E; }
                else {
                    S->esrc[e] = (unsigned char)ns;
                    S->edst[e] = (unsigned char)nd;
                    atomicAdd(&S->hist[nd], 1);
                }
            } else {
                atomicAdd(&S->hist[S->edst[e]], 1);
            }
        }
    }
    __syncthreads();
    excl_scan(S, n);
    for (int e = tid; e < EPG; e += NT) {
        unsigned char sv = S->esrc[e];
        if (sv != INV_E) {
            int p = atomicAdd(&S->cur[S->edst[e]], 1);
            S->eord[p] = sv;
        }
    }
    __syncthreads();
}

// 128-dim neighbor mean of xs into ms (float4 per lane)
__device__ __forceinline__ void level_agg(MegaSm* S, int n, bool do_remap) {
    edge_sort(S, n, do_remap);
    int tid = threadIdx.x, w = tid >> 5, lane = tid & 31;
    for (int v = w; v < n; v += NW) {
        int e0 = S->off[v], e1 = S->off[v+1];
        float inv = (e1 > e0) ? 1.0f / (float)(e1 - e0) : 0.0f;
        float4 a = make_float4(0.f, 0.f, 0.f, 0.f);
        float4 c = make_float4(0.f, 0.f, 0.f, 0.f);
        int e = e0;
        for (; e + 1 < e1; e += 2) {
            float4 p = *(const float4*)&S->xs[S->eord[e]][4*lane];
            float4 q = *(const float4*)&S->xs[S->eord[e+1]][4*lane];
            a.x += p.x; a.y += p.y; a.z += p.z; a.w += p.w;
            c.x += q.x; c.y += q.y; c.z += q.z; c.w += q.w;
        }
        if (e < e1) {
            float4 p = *(const float4*)&S->xs[S->eord[e]][4*lane];
            a.x += p.x; a.y += p.y; a.z += p.z; a.w += p.w;
        }
        *(float4*)&S->ms[v][4*lane] =
            make_float4((a.x + c.x) * inv, (a.y + c.y) * inv,
                        (a.z + c.z) * inv, (a.w + c.w) * inv);
    }
    __syncthreads();
}

// 3-way split rank with float4 inner loads (chunk forced to a multiple of 4;
// n is always a multiple of 4 here). Integer partials via smem atomics.
__device__ __forceinline__ void level_rank(MegaSm* S, int n, int k) {
    int tid = threadIdx.x;
    for (int i = tid; i < n; i += NT) S->hist[i] = 0;
    __syncthreads();
    int v = tid & 255;
    int part = tid >> 8;                 // 0..2 (768 = 3*256)
    if (v < n) {
        int chunk = (((n + 2) / 3) + 3) & ~3;
        int u0 = part * chunk;
        int u1 = min(n, u0 + chunk);
        float sv = S->s[v];
        int r = 0;
        int u = u0;
        for (; u + 4 <= u1; u += 4) {
            float4 s4 = *(const float4*)&S->s[u];
            r += (s4.x > sv) || (s4.x == sv && (u + 0) < v);
            r += (s4.y > sv) || (s4.y == sv && (u + 1) < v);
            r += (s4.z > sv) || (s4.z == sv && (u + 2) < v);
            r += (s4.w > sv) || (s4.w == sv && (u + 3) < v);
        }
        for (; u < u1; u++) {
            float su = S->s[u];
            r += (su > sv) || (su == sv && u < v);
        }
        atomicAdd(&S->hist[v], r);
    }
    __syncthreads();
    for (int v2 = tid; v2 < n; v2 += NT) {
        int r = S->hist[v2];
        S->newloc[v2] = (r < k) ? (short)r : (short)-1;
        if (r < k) S->kept[r] = (short)v2;
    }
    __syncthreads();
}

// pool xs rows [0,k) into harr (6 row-slices across 768 threads).
// NOTE: no trailing sync — harr/pmax/psum are next touched only after
// later barriers (audited); caller must sync before reading harr broadly.
__device__ __forceinline__ void pool_xs(MegaSm* S, int k) {
    int tid = threadIdx.x;
    int d = tid & 127, sl = tid >> 7;    // 0..5
    float mx = -INFINITY, sm = 0.0f;
    for (int r = sl; r < k; r += 6) {
        float v = S->xs[r][d];
        mx = fmaxf(mx, v);
        sm += v;
    }
    S->pmax[sl][d] = mx;
    S->psum[sl][d] = sm;
    __syncthreads();
    if (tid < 128) {
        float m = S->pmax[0][tid];
        float t = S->psum[0][tid];
#pragma unroll
        for (int i = 1; i < 6; i++) {
            m = fmaxf(m, S->pmax[i][tid]);
            t += S->psum[i][tid];
        }
        S->harr[tid]       += m;
        S->harr[128 + tid] += t / (float)k;
    }
}

// stage one 32-k chunk of the level weights into wst2[buf]
__device__ __forceinline__ void stage_chunk(
        MegaSm* S, int buf, const float* __restrict__ Wn,
        const float* __restrict__ Wr, int ci) {
    const float* Wg = (ci < 4) ? Wn : Wr;
    int kg = (ci * 32) & 127;
    int tid = threadIdx.x;
    for (int idx = tid; idx < 1024; idx += NT) {
        int r = idx >> 3, q = idx & 7;
        cp_async16(&S->u.wst2[buf][r][q * 4], &Wg[r * 128 + kg + q * 4]);
    }
    cp_commit();
}

// level GEMM (relu([ms|xs] @ [Wn|Wr]^T + bb)), 32x32 warp tiles, deep
// double-buffered weight staging (chunks 0,1 pre-staged by caller),
// fused score+topk+scatter+pool.
__device__ __forceinline__ void level_gemm_topk(
        MegaSm* S, int n, int k, float rn,
        const float* __restrict__ Wn, const float* __restrict__ Wr) {
    int tid = threadIdx.x, lane = tid & 31, w = tid >> 5;
    int rg = w >> 2, cf = w & 3;
    bool active = (rg < (n >> 5));

    float acc[2][4][4];
#pragma unroll
    for (int mt = 0; mt < 2; mt++)
#pragma unroll
        for (int nt = 0; nt < 4; nt++)
#pragma unroll
            for (int i = 0; i < 4; i++) acc[mt][nt][i] = 0.0f;

#pragma unroll 1
    for (int ci = 0; ci < 8; ci++) {
        if (ci < 7) cp_wait<1>(); else cp_wait<0>();
        __syncthreads();

        int nb = ci & 1;
        if (active) {
            int kc = ci * 32;
            const float (*A)[XSTR] = (kc < 128) ? S->ms : S->xs;
            int kg = kc & 127;
#pragma unroll
            for (int ks = 0; ks < 32; ks += 8) {
                uint32_t a[2][4];
#pragma unroll
                for (int mt = 0; mt < 2; mt++) {
                    int rb = rg * 32 + mt * 16 + (lane >> 2);
                    int c = kg + ks + (lane & 3);
                    a[mt][0] = __float_as_uint(A[rb][c]);
                    a[mt][1] = __float_as_uint(A[rb + 8][c]);
                    a[mt][2] = __float_as_uint(A[rb][c + 4]);
                    a[mt][3] = __float_as_uint(A[rb + 8][c + 4]);
                }
#pragma unroll
                for (int nt = 0; nt < 4; nt++) {
                    int nr = cf * 32 + nt * 8 + (lane >> 2);
                    int cc = ks + (lane & 3);
                    uint32_t b0 = __float_as_uint(S->u.wst2[nb][nr][cc]);
                    uint32_t b1 = __float_as_uint(S->u.wst2[nb][nr][cc + 4]);
                    mma_tf32(acc[0][nt], a[0][0], a[0][1], a[0][2], a[0][3], b0, b1);
                    mma_tf32(acc[1][nt], a[1][0], a[1][1], a[1][2], a[1][3], b0, b1);
                }
            }
        }
        __syncthreads();
        if (ci + 2 < 8) stage_chunk(S, nb, Wn, Wr, ci + 2);
    }

    if (active) {
#pragma unroll
        for (int mt = 0; mt < 2; mt++) {
            int r = rg * 32 + mt * 16 + (lane >> 2);
            float pd0 = 0.0f, pd1 = 0.0f;
#pragma unroll
            for (int nt = 0; nt < 4; nt++) {
                int col = cf * 32 + nt * 8 + 2 * (lane & 3);
                float v00 = fmaxf(acc[mt][nt][0] + S->bb[col],     0.0f);
                float v01 = fmaxf(acc[mt][nt][1] + S->bb[col + 1], 0.0f);
                float v10 = fmaxf(acc[mt][nt][2] + S->bb[col],     0.0f);
                float v11 = fmaxf(acc[mt][nt][3] + S->bb[col + 1], 0.0f);
                acc[mt][nt][0] = v00; acc[mt][nt][1] = v01;
                acc[mt][nt][2] = v10; acc[mt][nt][3] = v11;
                pd0 += v00 * S->ps[col] + v01 * S->ps[col + 1];
                pd1 += v10 * S->ps[col] + v11 * S->ps[col + 1];
            }
            pd0 += __shfl_xor_sync(0xffffffffu, pd0, 1);
            pd0 += __shfl_xor_sync(0xffffffffu, pd0, 2);
            pd1 += __shfl_xor_sync(0xffffffffu, pd1, 1);
            pd1 += __shfl_xor_sync(0xffffffffu, pd1, 2);
            if ((lane & 3) == 0) { S->sdp[cf][r] = pd0; S->sdp[cf][r + 8] = pd1; }
        }
    }
    __syncthreads();

    for (int v = tid; v < n; v += NT)
        S->s[v] = tanhf(((S->sdp[0][v] + S->sdp[1][v]) +
                         (S->sdp[2][v] + S->sdp[3][v])) * rn);
    __syncthreads();

    level_rank(S, n, k);

    if (active) {
#pragma unroll
        for (int mt = 0; mt < 2; mt++) {
            int r = rg * 32 + mt * 16 + (lane >> 2);
            int nl0 = S->newloc[r], nl1 = S->newloc[r + 8];
            float s0 = S->s[r], s1 = S->s[r + 8];
#pragma unroll
            for (int nt = 0; nt < 4; nt++) {
                int col = cf * 32 + nt * 8 + 2 * (lane & 3);
                if (nl0 >= 0)
                    *(float2*)&S->xs[nl0][col] =
                        make_float2(acc[mt][nt][0] * s0, acc[mt][nt][1] * s0);
                if (nl1 >= 0)
                    *(float2*)&S->xs[nl1][col] =
                        make_float2(acc[mt][nt][2] * s1, acc[mt][nt][3] * s1);
            }
        }
    }
    __syncthreads();

    pool_xs(S, k);
}

// ---------------- the single fused kernel ------------------------------------
__global__ __launch_bounds__(NT, 1) void mega_kernel(
        const int* __restrict__ node_ids,
        const int* __restrict__ edge_index,
        const float* __restrict__ emb,
        const float* __restrict__ w1n, const float* __restrict__ w1r,
        const float* __restrict__ b1,  const float* __restrict__ p1,
        const float* __restrict__ w2n, const float* __restrict__ w2r,
        const float* __restrict__ b2,  const float* __restrict__ p2,
        const float* __restrict__ w3n, const float* __restrict__ w3r,
        const float* __restrict__ b3,  const float* __restrict__ p3,
        const float* __restrict__ lw1, const float* __restrict__ lb1,
        const float* __restrict__ lw2, const float* __restrict__ lb2,
        const float* __restrict__ lw3, const float* __restrict__ lb3,
        float* __restrict__ out) {
    extern __shared__ char raw[];
    MegaSm* S = (MegaSm*)raw;

    int b = blockIdx.x, tid = threadIdx.x;
    int w = tid >> 5, lane = tid & 31;

    // edges -> smem (uint8 local indices)
    for (int e = tid; e < EPG; e += NT) {
        S->esrc[e] = (unsigned char)(edge_index[b*EPG + e] - b*NP);
        S->edst[e] = (unsigned char)(edge_index[E_TOT + b*EPG + e] - b*NP);
    }
    // 1/||p|| for the three pool vectors
    if (w < 3) {
        const float* pv = (w == 0) ? p1 : ((w == 1) ? p2 : p3);
        float v = pv[lane]*pv[lane] + pv[lane+32]*pv[lane+32]
                + pv[lane+64]*pv[lane+64] + pv[lane+96]*pv[lane+96];
#pragma unroll
        for (int o = 16; o; o >>= 1) v += __shfl_down_sync(0xffffffffu, v, o);
        if (lane == 0) S->rns[w] = 1.0f / sqrtf(v);
    }
    if (tid < 256) S->harr[tid] = 0.0f;
    if (tid < 128) { S->bb[tid] = b1[tid]; S->ps[tid] = p1[tid]; }

    // As1: zero everything; fill emb features into cols 9..17 for v<200
    for (int idx = tid; idx < 208*28; idx += NT) {
        int r = idx / 28, c = idx - r*28;
        float v = 0.0f;
        if (r < NP && c >= 9 && c < 18)
            v = emb[(size_t)node_ids[b*NP + r] * EMB + (c - 9)];
        S->u.c1.As1[r][c] = v;
    }
    // W1 stage [w1n | w1r | pad]
    for (int idx = tid; idx < 128*28; idx += NT) {
        int r = idx / 28, c = idx - r*28;
        float wv = 0.0f;
        if (c < 9)       wv = w1n[r*9 + c];
        else if (c < 18) wv = w1r[r*9 + (c - 9)];
        S->u.c1.W1s[r][c] = wv;
    }
    __syncthreads();

    // ---------- level-1 9-dim aggregation ----------
    edge_sort(S, NP, false);
    for (int v = w; v < NP; v += NW) {
        int e0 = S->off[v], e1 = S->off[v+1];
        float inv = (e1 > e0) ? 1.0f / (float)(e1 - e0) : 0.0f;
        if (lane < EMB) {
            float a = 0.0f;
            for (int e = e0; e < e1; e++)
                a += S->u.c1.As1[S->eord[e]][9 + lane];
            S->u.c1.As1[v][lane] = a * inv;
        }
    }
    __syncthreads();

    // ---------- conv1 pass 1: score dot only (26 tasks, K=24, 16x64) ----------
#pragma unroll
    for (int ti = 0; ti < 2; ti++) {
        int t = w + ti * NW;
        if (t < 26) {
            int rg = t >> 1, hf = t & 1;
            int rb = rg * 16 + (lane >> 2);
            float acc[8][4];
#pragma unroll
            for (int nt = 0; nt < 8; nt++)
#pragma unroll
                for (int i = 0; i < 4; i++) acc[nt][i] = 0.0f;
#pragma unroll
            for (int ks = 0; ks < 24; ks += 8) {
                int c = ks + (lane & 3);
                uint32_t a0 = __float_as_uint(S->u.c1.As1[rb][c]);
                uint32_t a1 = __float_as_uint(S->u.c1.As1[rb + 8][c]);
                uint32_t a2 = __float_as_uint(S->u.c1.As1[rb][c + 4]);
                uint32_t a3 = __float_as_uint(S->u.c1.As1[rb + 8][c + 4]);
#pragma unroll
                for (int nt = 0; nt < 8; nt++) {
                    int nr = hf * 64 + nt * 8 + (lane >> 2);
                    uint32_t b0 = __float_as_uint(S->u.c1.W1s[nr][c]);
                    uint32_t b1 = __float_as_uint(S->u.c1.W1s[nr][c + 4]);
                    mma_tf32(acc[nt], a0, a1, a2, a3, b0, b1);
                }
            }
            int r = rg * 16 + (lane >> 2);
            float pd0 = 0.0f, pd1 = 0.0f;
#pragma unroll
            for (int nt = 0; nt < 8; nt++) {
                int col = hf * 64 + nt * 8 + 2 * (lane & 3);
                pd0 += fmaxf(acc[nt][0] + S->bb[col],     0.0f) * S->ps[col]
                     + fmaxf(acc[nt][1] + S->bb[col + 1], 0.0f) * S->ps[col + 1];
                pd1 += fmaxf(acc[nt][2] + S->bb[col],     0.0f) * S->ps[col]
                     + fmaxf(acc[nt][3] + S->bb[col + 1], 0.0f) * S->ps[col + 1];
            }
            pd0 += __shfl_xor_sync(0xffffffffu, pd0, 1);
            pd0 += __shfl_xor_sync(0xffffffffu, pd0, 2);
            pd1 += __shfl_xor_sync(0xffffffffu, pd1, 1);
            pd1 += __shfl_xor_sync(0xffffffffu, pd1, 2);
            if ((lane & 3) == 0) { S->sdp[hf][r] = pd0; S->sdp[hf][r + 8] = pd1; }
        }
    }
    __syncthreads();

    for (int v = tid; v < NP; v += NT)
        S->s[v] = tanhf((S->sdp[0][v] + S->sdp[1][v]) * S->rns[0]);
    __syncthreads();

    level_rank(S, NP, K1);

    // ---------- conv1 pass 2: recompute kept rows, gain, write xs ----------
    if (w < 20) {
        int rg = w >> 1, hf = w & 1;
        int r0 = rg * 16 + (lane >> 2);
        int k0 = S->kept[r0], k1 = S->kept[r0 + 8];
        float s0 = S->s[k0],  s1 = S->s[k1];
        float acc[8][4];
#pragma unroll
        for (int nt = 0; nt < 8; nt++)
#pragma unroll
            for (int i = 0; i < 4; i++) acc[nt][i] = 0.0f;
#pragma unroll
        for (int ks = 0; ks < 24; ks += 8) {
            int c = ks + (lane & 3);
            uint32_t a0 = __float_as_uint(S->u.c1.As1[k0][c]);
            uint32_t a1 = __float_as_uint(S->u.c1.As1[k1][c]);
            uint32_t a2 = __float_as_uint(S->u.c1.As1[k0][c + 4]);
            uint32_t a3 = __float_as_uint(S->u.c1.As1[k1][c + 4]);
#pragma unroll
            for (int nt = 0; nt < 8; nt++) {
                int nr = hf * 64 + nt * 8 + (lane >> 2);
                uint32_t b0 = __float_as_uint(S->u.c1.W1s[nr][c]);
                uint32_t b1 = __float_as_uint(S->u.c1.W1s[nr][c + 4]);
                mma_tf32(acc[nt], a0, a1, a2, a3, b0, b1);
            }
        }
#pragma unroll
        for (int nt = 0; nt < 8; nt++) {
            int col = hf * 64 + nt * 8 + 2 * (lane & 3);
            float v00 = fmaxf(acc[nt][0] + S->bb[col],     0.0f) * s0;
            float v01 = fmaxf(acc[nt][1] + S->bb[col + 1], 0.0f) * s0;
            float v10 = fmaxf(acc[nt][2] + S->bb[col],     0.0f) * s1;
            float v11 = fmaxf(acc[nt][3] + S->bb[col + 1], 0.0f) * s1;
            *(float2*)&S->xs[r0][col]     = make_float2(v00, v01);
            *(float2*)&S->xs[r0 + 8][col] = make_float2(v10, v11);
        }
    }
    __syncthreads();

    pool_xs(S, K1);

    // ---------- level 2 ----------
    if (tid < 128) { S->bb[tid] = b2[tid]; S->ps[tid] = p2[tid]; }
    stage_chunk(S, 0, w2n, w2r, 0);      // prefetch W chunks under agg
    stage_chunk(S, 1, w2n, w2r, 1);
    level_agg(S, K1, true);              // fused remap (newloc from topk1)
    level_gemm_topk(S, K1, K2, S->rns[1], w2n, w2r);

    // ---------- level 3 ----------
    if (tid < 128) { S->bb[tid] = b3[tid]; S->ps[tid] = p3[tid]; }
    stage_chunk(S, 0, w3n, w3r, 0);
    stage_chunk(S, 1, w3n, w3r, 1);
    level_agg(S, K2, true);              // fused remap (newloc from topk2)
    level_gemm_topk(S, K2, K3, S->rns[2], w3n, w3r);

    __syncthreads();                     // harr visibility for the MLP head

    // ---------- MLP head (coalesced warp-cooperative, float4) ----------
    {
        float4 h0 = *(const float4*)&S->harr[lane * 4];
        float4 h1v = *(const float4*)&S->harr[128 + lane * 4];
        for (int c = w; c < 128; c += NW) {
            const float4* w4 = (const float4*)(lw1 + c * 256);
            float4 w0 = w4[lane], w1v = w4[lane + 32];
            float a = w0.x*h0.x + w0.y*h0.y + w0.z*h0.z + w0.w*h0.w
                    + w1v.x*h1v.x + w1v.y*h1v.y + w1v.z*h1v.z + w1v.w*h1v.w;
#pragma unroll
            for (int o = 16; o; o >>= 1) a += __shfl_xor_sync(0xffffffffu, a, o);
            if (lane == 0) S->h1[c] = fmaxf(a + lb1[c], 0.0f);
        }
    }
    __syncthreads();
    {
        float4 g0 = *(const float4*)&S->h1[lane * 4];
        for (int c = w; c < 64; c += NW) {
            float4 w0 = ((const float4*)(lw2 + c * 128))[lane];
            float a = w0.x*g0.x + w0.y*g0.y + w0.z*g0.z + w0.w*g0.w;
#pragma unroll
            for (int o = 16; o; o >>= 1) a += __shfl_xor_sync(0xffffffffu, a, o);
            if (lane == 0) S->h2[c] = fmaxf(a + lb2[c], 0.0f);
        }
    }
    __syncthreads();
    if (w == 0) {
        float a = 0.0f;
#pragma unroll
        for (int j = 0; j < 2; j++)
            a += lw3[j*32 + lane] * S->h2[j*32 + lane];
#pragma unroll
        for (int o = 16; o; o >>= 1) a += __shfl_xor_sync(0xffffffffu, a, o);
        if (lane == 0) out[b] = 1.0f / (1.0f + expf(-(a + lb3[0])));
    }
}

// ---------------- launch ------------------------------------------------------
extern "C" void kernel_launch(void* const* d_in, const int* in_sizes, int n_in,
                              void* d_out, int out_size) {
    const int*   node_ids   = (const int*)d_in[0];
    const int*   edge_index = (const int*)d_in[1];
    const float* emb  = (const float*)d_in[3];
    const float* w1n  = (const float*)d_in[4];
    const float* w1r  = (const float*)d_in[5];
    const float* b1   = (const float*)d_in[6];
    const float* w2n  = (const float*)d_in[7];
    const float* w2r  = (const float*)d_in[8];
    const float* b2   = (const float*)d_in[9];
    const float* w3n  = (const float*)d_in[10];
    const float* w3r  = (const float*)d_in[11];
    const float* b3   = (const float*)d_in[12];
    const float* p1   = (const float*)d_in[13];
    const float* p2   = (const float*)d_in[14];
    const float* p3   = (const float*)d_in[15];
    const float* lw1  = (const float*)d_in[16];
    const float* lb1  = (const float*)d_in[17];
    const float* lw2  = (const float*)d_in[18];
    const float* lb2  = (const float*)d_in[19];
    const float* lw3  = (const float*)d_in[20];
    const float* lb3  = (const float*)d_in[21];
    float* out = (float*)d_out;

    static int smem_set = 0;
    if (!smem_set) {
        cudaFuncSetAttribute(mega_kernel,
                             cudaFuncAttributeMaxDynamicSharedMemorySize,
                             (int)sizeof(MegaSm));
        smem_set = 1;
    }

    mega_kernel<<<B, NT, sizeof(MegaSm)>>>(
        node_ids, edge_index, emb,
        w1n, w1r, b1, p1,
        w2n, w2r, b2, p2,
        w3n, w3r, b3, p3,
        lw1, lb1, lw2, lb2, lw3, lb3, out);
}

// round 11
// speedup vs baseline: 2.1488x; 1.0007x over previous
#include <cuda_runtime.h>
#include <math.h>
#include <stdint.h>

#define B    512
#define NP   200
#define EPG  2000
#define E_TOT (B*EPG)
#define HID  128
#define EMB  9
#define K1   160
#define K2   128
#define K3   103

#define NT   768           // threads
#define NW   24            // warps
#define INV_E 0xFFu
#define XSTR 132           // xs/ms row stride (floats)

// ---------------- async copy helpers -----------------------------------------
__device__ __forceinline__ void cp_async16(void* smem_dst, const void* gsrc) {
    uint32_t s = (uint32_t)__cvta_generic_to_shared(smem_dst);
    asm volatile("cp.async.ca.shared.global [%0], [%1], 16;\n" :: "r"(s), "l"(gsrc));
}
__device__ __forceinline__ void cp_commit() {
    asm volatile("cp.async.commit_group;\n" ::: "memory");
}
template<int N>
__device__ __forceinline__ void cp_wait() {
    asm volatile("cp.async.wait_group %0;\n" :: "n"(N) : "memory");
}

// ---------------- tf32 mma primitive -----------------------------------------
__device__ __forceinline__ void mma_tf32(float c[4], uint32_t a0, uint32_t a1,
                                         uint32_t a2, uint32_t a3,
                                         uint32_t b0, uint32_t b1) {
    asm volatile(
        "mma.sync.aligned.m16n8k8.row.col.f32.tf32.tf32.f32 "
        "{%0,%1,%2,%3}, {%4,%5,%6,%7}, {%8,%9}, {%0,%1,%2,%3};"
        : "+f"(c[0]), "+f"(c[1]), "+f"(c[2]), "+f"(c[3])
        : "r"(a0), "r"(a1), "r"(a2), "r"(a3), "r"(b0), "r"(b1));
}

// ---------------- mega kernel smem -------------------------------------------
struct MegaSm {
    float xs[160][XSTR];     // pooled features
    float ms[160][XSTR];     // neighbor means
    union {
        struct {             // conv1 phase
            float As1[208][28];   // [mean(9) | x(9) | pad] per node
            float W1s[128][28];   // [w1n | w1r | pad]
        } c1;
        float wst2[2][128][36];  // level-GEMM W k-chunk double buffer
    } u;
    float s[208];            // scores (n is always a multiple of 4)
    float sdp[4][208];       // deterministic 4-part score dot (conv1 uses 2)
    float bb[128];
    float ps[128];
    float harr[256];         // readout accumulator x1+x2+x3
    float pmax[6][128];
    float psum[6][128];
    float h1[128];
    float h2[64];
    float rns[3];
    int   hist[224];
    int   off[225];
    int   cur[224];
    int   wsum[8];
    short newloc[208];
    short kept[160];
    unsigned char esrc[EPG];
    unsigned char edst[EPG];
    unsigned char eord[EPG];
};

// parallel exclusive scan of hist[0..n) -> off/cur, off[n]=total
__device__ __forceinline__ void excl_scan(MegaSm* S, int n) {
    int tid = threadIdx.x, lane = tid & 31, w = tid >> 5;
    int npad = (n + 31) & ~31;
    if (tid < npad) {
        int h0 = S->hist[tid];
        int x = h0;
#pragma unroll
        for (int o = 1; o < 32; o <<= 1) {
            int y = __shfl_up_sync(0xffffffffu, x, o);
            if (lane >= o) x += y;
        }
        if (lane == 31) S->wsum[w] = x;
        S->off[tid] = x - h0;
    }
    __syncthreads();
    if (tid == 0) {
        int a = 0, nw = npad >> 5;
        for (int i = 0; i < nw; i++) { int t = S->wsum[i]; S->wsum[i] = a; a += t; }
        S->off[n] = a;
    }
    __syncthreads();
    if (tid < n) {
        int o = S->off[tid] + S->wsum[w];
        S->off[tid] = o;
        S->cur[tid] = o;
    }
    __syncthreads();
}

// counting sort of valid edges by dst into eord; optionally fuses the
// newloc remap (from the previous level's rank) into the histogram pass.
__device__ __forceinline__ void edge_sort(MegaSm* S, int n, bool do_remap) {
    int tid = threadIdx.x;
    int npad = (n + 31) & ~31;
    for (int i = tid; i < npad; i += NT) S->hist[i] = 0;
    __syncthreads();
    for (int e = tid; e < EPG; e += NT) {
        unsigned char sv = S->esrc[e];
        if (sv != INV_E) {
            if (do_remap) {
                short ns = S->newloc[sv];
                short nd = S->newloc[S->edst[e]];
                if (ns < 0 || nd < 0) { S->esrc[e] = (unsigned char)INV_E; }
                else {
                    S->esrc[e] = (unsigned char)ns;
                    S->edst[e] = (unsigned char)nd;
                    atomicAdd(&S->hist[nd], 1);
                }
            } else {
                atomicAdd(&S->hist[S->edst[e]], 1);
            }
        }
    }
    __syncthreads();
    excl_scan(S, n);
    for (int e = tid; e < EPG; e += NT) {
        unsigned char sv = S->esrc[e];
        if (sv != INV_E) {
            int p = atomicAdd(&S->cur[S->edst[e]], 1);
            S->eord[p] = sv;
        }
    }
    __syncthreads();
}

// 128-dim neighbor mean of xs into ms (float4 per lane)
__device__ __forceinline__ void level_agg(MegaSm* S, int n, bool do_remap) {
    edge_sort(S, n, do_remap);
    int tid = threadIdx.x, w = tid >> 5, lane = tid & 31;
    for (int v = w; v < n; v += NW) {
        int e0 = S->off[v], e1 = S->off[v+1];
        float inv = (e1 > e0) ? 1.0f / (float)(e1 - e0) : 0.0f;
        float4 a = make_float4(0.f, 0.f, 0.f, 0.f);
        float4 c = make_float4(0.f, 0.f, 0.f, 0.f);
        int e = e0;
        for (; e + 1 < e1; e += 2) {
            float4 p = *(const float4*)&S->xs[S->eord[e]][4*lane];
            float4 q = *(const float4*)&S->xs[S->eord[e+1]][4*lane];
            a.x += p.x; a.y += p.y; a.z += p.z; a.w += p.w;
            c.x += q.x; c.y += q.y; c.z += q.z; c.w += q.w;
        }
        if (e < e1) {
            float4 p = *(const float4*)&S->xs[S->eord[e]][4*lane];
            a.x += p.x; a.y += p.y; a.z += p.z; a.w += p.w;
        }
        *(float4*)&S->ms[v][4*lane] =
            make_float4((a.x + c.x) * inv, (a.y + c.y) * inv,
                        (a.z + c.z) * inv, (a.w + c.w) * inv);
    }
    __syncthreads();
}

// 3-way split rank with float4 inner loads (chunk forced to a multiple of 4;
// n is always a multiple of 4 here). Integer partials via smem atomics.
__device__ __forceinline__ void level_rank(MegaSm* S, int n, int k) {
    int tid = threadIdx.x;
    for (int i = tid; i < n; i += NT) S->hist[i] = 0;
    __syncthreads();
    int v = tid & 255;
    int part = tid >> 8;                 // 0..2 (768 = 3*256)
    if (v < n) {
        int chunk = (((n + 2) / 3) + 3) & ~3;
        int u0 = part * chunk;
        int u1 = min(n, u0 + chunk);
        float sv = S->s[v];
        int r = 0;
        int u = u0;
        for (; u + 4 <= u1; u += 4) {
            float4 s4 = *(const float4*)&S->s[u];
            r += (s4.x > sv) || (s4.x == sv && (u + 0) < v);
            r += (s4.y > sv) || (s4.y == sv && (u + 1) < v);
            r += (s4.z > sv) || (s4.z == sv && (u + 2) < v);
            r += (s4.w > sv) || (s4.w == sv && (u + 3) < v);
        }
        for (; u < u1; u++) {
            float su = S->s[u];
            r += (su > sv) || (su == sv && u < v);
        }
        atomicAdd(&S->hist[v], r);
    }
    __syncthreads();
    for (int v2 = tid; v2 < n; v2 += NT) {
        int r = S->hist[v2];
        S->newloc[v2] = (r < k) ? (short)r : (short)-1;
        if (r < k) S->kept[r] = (short)v2;
    }
    __syncthreads();
}

// pool xs rows [0,k) into harr (6 row-slices across 768 threads).
// NOTE: no trailing sync — harr/pmax/psum are next touched only after
// later barriers (audited); caller must sync before reading harr broadly.
__device__ __forceinline__ void pool_xs(MegaSm* S, int k) {
    int tid = threadIdx.x;
    int d = tid & 127, sl = tid >> 7;    // 0..5
    float mx = -INFINITY, sm = 0.0f;
    for (int r = sl; r < k; r += 6) {
        float v = S->xs[r][d];
        mx = fmaxf(mx, v);
        sm += v;
    }
    S->pmax[sl][d] = mx;
    S->psum[sl][d] = sm;
    __syncthreads();
    if (tid < 128) {
        float m = S->pmax[0][tid];
        float t = S->psum[0][tid];
#pragma unroll
        for (int i = 1; i < 6; i++) {
            m = fmaxf(m, S->pmax[i][tid]);
            t += S->psum[i][tid];
        }
        S->harr[tid]       += m;
        S->harr[128 + tid] += t / (float)k;
    }
}

// stage one 32-k chunk of the level weights into wst2[buf]
__device__ __forceinline__ void stage_chunk(
        MegaSm* S, int buf, const float* __restrict__ Wn,
        const float* __restrict__ Wr, int ci) {
    const float* Wg = (ci < 4) ? Wn : Wr;
    int kg = (ci * 32) & 127;
    int tid = threadIdx.x;
    for (int idx = tid; idx < 1024; idx += NT) {
        int r = idx >> 3, q = idx & 7;
        cp_async16(&S->u.wst2[buf][r][q * 4], &Wg[r * 128 + kg + q * 4]);
    }
    cp_commit();
}

// level GEMM (relu([ms|xs] @ [Wn|Wr]^T + bb)), 32x32 warp tiles, deep
// double-buffered weight staging (chunks 0,1 pre-staged by caller),
// fused score+topk+scatter+pool.
__device__ __forceinline__ void level_gemm_topk(
        MegaSm* S, int n, int k, float rn,
        const float* __restrict__ Wn, const float* __restrict__ Wr) {
    int tid = threadIdx.x, lane = tid & 31, w = tid >> 5;
    int rg = w >> 2, cf = w & 3;
    bool active = (rg < (n >> 5));

    float acc[2][4][4];
#pragma unroll
    for (int mt = 0; mt < 2; mt++)
#pragma unroll
        for (int nt = 0; nt < 4; nt++)
#pragma unroll
            for (int i = 0; i < 4; i++) acc[mt][nt][i] = 0.0f;

#pragma unroll 1
    for (int ci = 0; ci < 8; ci++) {
        if (ci < 7) cp_wait<1>(); else cp_wait<0>();
        __syncthreads();

        int nb = ci & 1;
        if (active) {
            int kc = ci * 32;
            const float (*A)[XSTR] = (kc < 128) ? S->ms : S->xs;
            int kg = kc & 127;
#pragma unroll
            for (int ks = 0; ks < 32; ks += 8) {
                uint32_t a[2][4];
#pragma unroll
                for (int mt = 0; mt < 2; mt++) {
                    int rb = rg * 32 + mt * 16 + (lane >> 2);
                    int c = kg + ks + (lane & 3);
                    a[mt][0] = __float_as_uint(A[rb][c]);
                    a[mt][1] = __float_as_uint(A[rb + 8][c]);
                    a[mt][2] = __float_as_uint(A[rb][c + 4]);
                    a[mt][3] = __float_as_uint(A[rb + 8][c + 4]);
                }
#pragma unroll
                for (int nt = 0; nt < 4; nt++) {
                    int nr = cf * 32 + nt * 8 + (lane >> 2);
                    int cc = ks + (lane & 3);
                    uint32_t b0 = __float_as_uint(S->u.wst2[nb][nr][cc]);
                    uint32_t b1 = __float_as_uint(S->u.wst2[nb][nr][cc + 4]);
                    mma_tf32(acc[0][nt], a[0][0], a[0][1], a[0][2], a[0][3], b0, b1);
                    mma_tf32(acc[1][nt], a[1][0], a[1][1], a[1][2], a[1][3], b0, b1);
                }
            }
        }
        __syncthreads();
        if (ci + 2 < 8) stage_chunk(S, nb, Wn, Wr, ci + 2);
    }

    if (active) {
#pragma unroll
        for (int mt = 0; mt < 2; mt++) {
            int r = rg * 32 + mt * 16 + (lane >> 2);
            float pd0 = 0.0f, pd1 = 0.0f;
#pragma unroll
            for (int nt = 0; nt < 4; nt++) {
                int col = cf * 32 + nt * 8 + 2 * (lane & 3);
                float v00 = fmaxf(acc[mt][nt][0] + S->bb[col],     0.0f);
                float v01 = fmaxf(acc[mt][nt][1] + S->bb[col + 1], 0.0f);
                float v10 = fmaxf(acc[mt][nt][2] + S->bb[col],     0.0f);
                float v11 = fmaxf(acc[mt][nt][3] + S->bb[col + 1], 0.0f);
                acc[mt][nt][0] = v00; acc[mt][nt][1] = v01;
                acc[mt][nt][2] = v10; acc[mt][nt][3] = v11;
                pd0 += v00 * S->ps[col] + v01 * S->ps[col + 1];
                pd1 += v10 * S->ps[col] + v11 * S->ps[col + 1];
            }
            pd0 += __shfl_xor_sync(0xffffffffu, pd0, 1);
            pd0 += __shfl_xor_sync(0xffffffffu, pd0, 2);
            pd1 += __shfl_xor_sync(0xffffffffu, pd1, 1);
            pd1 += __shfl_xor_sync(0xffffffffu, pd1, 2);
            if ((lane & 3) == 0) { S->sdp[cf][r] = pd0; S->sdp[cf][r + 8] = pd1; }
        }
    }
    __syncthreads();

    for (int v = tid; v < n; v += NT)
        S->s[v] = tanhf(((S->sdp[0][v] + S->sdp[1][v]) +
                         (S->sdp[2][v] + S->sdp[3][v])) * rn);
    __syncthreads();

    level_rank(S, n, k);

    if (active) {
#pragma unroll
        for (int mt = 0; mt < 2; mt++) {
            int r = rg * 32 + mt * 16 + (lane >> 2);
            int nl0 = S->newloc[r], nl1 = S->newloc[r + 8];
            float s0 = S->s[r], s1 = S->s[r + 8];
#pragma unroll
            for (int nt = 0; nt < 4; nt++) {
                int col = cf * 32 + nt * 8 + 2 * (lane & 3);
                if (nl0 >= 0)
                    *(float2*)&S->xs[nl0][col] =
                        make_float2(acc[mt][nt][0] * s0, acc[mt][nt][1] * s0);
                if (nl1 >= 0)
                    *(float2*)&S->xs[nl1][col] =
                        make_float2(acc[mt][nt][2] * s1, acc[mt][nt][3] * s1);
            }
        }
    }
    __syncthreads();

    pool_xs(S, k);
}

// ---------------- the single fused kernel ------------------------------------
__global__ __launch_bounds__(NT, 1) void mega_kernel(
        const int* __restrict__ node_ids,
        const int* __restrict__ edge_index,
        const float* __restrict__ emb,
        const float* __restrict__ w1n, const float* __restrict__ w1r,
        const float* __restrict__ b1,  const float* __restrict__ p1,
        const float* __restrict__ w2n, const float* __restrict__ w2r,
        const float* __restrict__ b2,  const float* __restrict__ p2,
        const float* __restrict__ w3n, const float* __restrict__ w3r,
        const float* __restrict__ b3,  const float* __restrict__ p3,
        const float* __restrict__ lw1, const float* __restrict__ lb1,
        const float* __restrict__ lw2, const float* __restrict__ lb2,
        const float* __restrict__ lw3, const float* __restrict__ lb3,
        float* __restrict__ out) {
    extern __shared__ char raw[];
    MegaSm* S = (MegaSm*)raw;

    int b = blockIdx.x, tid = threadIdx.x;
    int w = tid >> 5, lane = tid & 31;

    // edges -> smem (uint8 local indices)
    for (int e = tid; e < EPG; e += NT) {
        S->esrc[e] = (unsigned char)(edge_index[b*EPG + e] - b*NP);
        S->edst[e] = (unsigned char)(edge_index[E_TOT + b*EPG + e] - b*NP);
    }
    // 1/||p|| for the three pool vectors
    if (w < 3) {
        const float* pv = (w == 0) ? p1 : ((w == 1) ? p2 : p3);
        float v = pv[lane]*pv[lane] + pv[lane+32]*pv[lane+32]
                + pv[lane+64]*pv[lane+64] + pv[lane+96]*pv[lane+96];
#pragma unroll
        for (int o = 16; o; o >>= 1) v += __shfl_down_sync(0xffffffffu, v, o);
        if (lane == 0) S->rns[w] = 1.0f / sqrtf(v);
    }
    if (tid < 256) S->harr[tid] = 0.0f;
    if (tid < 128) { S->bb[tid] = b1[tid]; S->ps[tid] = p1[tid]; }

    // As1: zero everything; fill emb features into cols 9..17 for v<200
    for (int idx = tid; idx < 208*28; idx += NT) {
        int r = idx / 28, c = idx - r*28;
        float v = 0.0f;
        if (r < NP && c >= 9 && c < 18)
            v = emb[(size_t)node_ids[b*NP + r] * EMB + (c - 9)];
        S->u.c1.As1[r][c] = v;
    }
    // W1 stage [w1n | w1r | pad]
    for (int idx = tid; idx < 128*28; idx += NT) {
        int r = idx / 28, c = idx - r*28;
        float wv = 0.0f;
        if (c < 9)       wv = w1n[r*9 + c];
        else if (c < 18) wv = w1r[r*9 + (c - 9)];
        S->u.c1.W1s[r][c] = wv;
    }
    __syncthreads();

    // ---------- level-1 9-dim aggregation ----------
    edge_sort(S, NP, false);
    for (int v = w; v < NP; v += NW) {
        int e0 = S->off[v], e1 = S->off[v+1];
        float inv = (e1 > e0) ? 1.0f / (float)(e1 - e0) : 0.0f;
        if (lane < EMB) {
            float a = 0.0f;
            for (int e = e0; e < e1; e++)
                a += S->u.c1.As1[S->eord[e]][9 + lane];
            S->u.c1.As1[v][lane] = a * inv;
        }
    }
    __syncthreads();

    // ---------- conv1 pass 1: score dot only (26 tasks, K=24, 16x64) ----------
#pragma unroll
    for (int ti = 0; ti < 2; ti++) {
        int t = w + ti * NW;
        if (t < 26) {
            int rg = t >> 1, hf = t & 1;
            int rb = rg * 16 + (lane >> 2);
            float acc[8][4];
#pragma unroll
            for (int nt = 0; nt < 8; nt++)
#pragma unroll
                for (int i = 0; i < 4; i++) acc[nt][i] = 0.0f;
#pragma unroll
            for (int ks = 0; ks < 24; ks += 8) {
                int c = ks + (lane & 3);
                uint32_t a0 = __float_as_uint(S->u.c1.As1[rb][c]);
                uint32_t a1 = __float_as_uint(S->u.c1.As1[rb + 8][c]);
                uint32_t a2 = __float_as_uint(S->u.c1.As1[rb][c + 4]);
                uint32_t a3 = __float_as_uint(S->u.c1.As1[rb + 8][c + 4]);
#pragma unroll
                for (int nt = 0; nt < 8; nt++) {
                    int nr = hf * 64 + nt * 8 + (lane >> 2);
                    uint32_t b0 = __float_as_uint(S->u.c1.W1s[nr][c]);
                    uint32_t b1 = __float_as_uint(S->u.c1.W1s[nr][c + 4]);
                    mma_tf32(acc[nt], a0, a1, a2, a3, b0, b1);
                }
            }
            int r = rg * 16 + (lane >> 2);
            float pd0 = 0.0f, pd1 = 0.0f;
#pragma unroll
            for (int nt = 0; nt < 8; nt++) {
                int col = hf * 64 + nt * 8 + 2 * (lane & 3);
                pd0 += fmaxf(acc[nt][0] + S->bb[col],     0.0f) * S->ps[col]
                     + fmaxf(acc[nt][1] + S->bb[col + 1], 0.0f) * S->ps[col + 1];
                pd1 += fmaxf(acc[nt][2] + S->bb[col],     0.0f) * S->ps[col]
                     + fmaxf(acc[nt][3] + S->bb[col + 1], 0.0f) * S->ps[col + 1];
            }
            pd0 += __shfl_xor_sync(0xffffffffu, pd0, 1);
            pd0 += __shfl_xor_sync(0xffffffffu, pd0, 2);
            pd1 += __shfl_xor_sync(0xffffffffu, pd1, 1);
            pd1 += __shfl_xor_sync(0xffffffffu, pd1, 2);
            if ((lane & 3) == 0) { S->sdp[hf][r] = pd0; S->sdp[hf][r + 8] = pd1; }
        }
    }
    __syncthreads();

    for (int v = tid; v < NP; v += NT)
        S->s[v] = tanhf((S->sdp[0][v] + S->sdp[1][v]) * S->rns[0]);
    __syncthreads();

    level_rank(S, NP, K1);

    // ---------- conv1 pass 2: recompute kept rows, gain, write xs ----------
    if (w < 20) {
        int rg = w >> 1, hf = w & 1;
        int r0 = rg * 16 + (lane >> 2);
        int k0 = S->kept[r0], k1 = S->kept[r0 + 8];
        float s0 = S->s[k0],  s1 = S->s[k1];
        float acc[8][4];
#pragma unroll
        for (int nt = 0; nt < 8; nt++)
#pragma unroll
            for (int i = 0; i < 4; i++) acc[nt][i] = 0.0f;
#pragma unroll
        for (int ks = 0; ks < 24; ks += 8) {
            int c = ks + (lane & 3);
            uint32_t a0 = __float_as_uint(S->u.c1.As1[k0][c]);
            uint32_t a1 = __float_as_uint(S->u.c1.As1[k1][c]);
            uint32_t a2 = __float_as_uint(S->u.c1.As1[k0][c + 4]);
            uint32_t a3 = __float_as_uint(S->u.c1.As1[k1][c + 4]);
#pragma unroll
            for (int nt = 0; nt < 8; nt++) {
                int nr = hf * 64 + nt * 8 + (lane >> 2);
                uint32_t b0 = __float_as_uint(S->u.c1.W1s[nr][c]);
                uint32_t b1 = __float_as_uint(S->u.c1.W1s[nr][c + 4]);
                mma_tf32(acc[nt], a0, a1, a2, a3, b0, b1);
            }
        }
#pragma unroll
        for (int nt = 0; nt < 8; nt++) {
            int col = hf * 64 + nt * 8 + 2 * (lane & 3);
            float v00 = fmaxf(acc[nt][0] + S->bb[col],     0.0f) * s0;
            float v01 = fmaxf(acc[nt][1] + S->bb[col + 1], 0.0f) * s0;
            float v10 = fmaxf(acc[nt][2] + S->bb[col],     0.0f) * s1;
            float v11 = fmaxf(acc[nt][3] + S->bb[col + 1], 0.0f) * s1;
            *(float2*)&S->xs[r0][col]     = make_float2(v00, v01);
            *(float2*)&S->xs[r0 + 8][col] = make_float2(v10, v11);
        }
    }
    __syncthreads();

    pool_xs(S, K1);

    // ---------- level 2 ----------
    if (tid < 128) { S->bb[tid] = b2[tid]; S->ps[tid] = p2[tid]; }
    stage_chunk(S, 0, w2n, w2r, 0);      // prefetch W chunks under agg
    stage_chunk(S, 1, w2n, w2r, 1);
    level_agg(S, K1, true);              // fused remap (newloc from topk1)
    level_gemm_topk(S, K1, K2, S->rns[1], w2n, w2r);

    // ---------- level 3 ----------
    if (tid < 128) { S->bb[tid] = b3[tid]; S->ps[tid] = p3[tid]; }
    stage_chunk(S, 0, w3n, w3r, 0);
    stage_chunk(S, 1, w3n, w3r, 1);
    level_agg(S, K2, true);              // fused remap (newloc from topk2)
    level_gemm_topk(S, K2, K3, S->rns[2], w3n, w3r);

    __syncthreads();                     // harr visibility for the MLP head

    // ---------- MLP head (coalesced warp-cooperative, float4) ----------
    {
        float4 h0 = *(const float4*)&S->harr[lane * 4];
        float4 h1v = *(const float4*)&S->harr[128 + lane * 4];
        for (int c = w; c < 128; c += NW) {
            const float4* w4 = (const float4*)(lw1 + c * 256);
            float4 w0 = w4[lane], w1v = w4[lane + 32];
            float a = w0.x*h0.x + w0.y*h0.y + w0.z*h0.z + w0.w*h0.w
                    + w1v.x*h1v.x + w1v.y*h1v.y + w1v.z*h1v.z + w1v.w*h1v.w;
#pragma unroll
            for (int o = 16; o; o >>= 1) a += __shfl_xor_sync(0xffffffffu, a, o);
            if (lane == 0) S->h1[c] = fmaxf(a + lb1[c], 0.0f);
        }
    }
    __syncthreads();
    {
        float4 g0 = *(const float4*)&S->h1[lane * 4];
        for (int c = w; c < 64; c += NW) {
            float4 w0 = ((const float4*)(lw2 + c * 128))[lane];
            float a = w0.x*g0.x + w0.y*g0.y + w0.z*g0.z + w0.w*g0.w;
#pragma unroll
            for (int o = 16; o; o >>= 1) a += __shfl_xor_sync(0xffffffffu, a, o);
            if (lane == 0) S->h2[c] = fmaxf(a + lb2[c], 0.0f);
        }
    }
    __syncthreads();
    if (w == 0) {
        float a = 0.0f;
#pragma unroll
        for (int j = 0; j < 2; j++)
            a += lw3[j*32 + lane] * S->h2[j*32 + lane];
#pragma unroll
        for (int o = 16; o; o >>= 1) a += __shfl_xor_sync(0xffffffffu, a, o);
        if (lane == 0) out[b] = 1.0f / (1.0f + expf(-(a + lb3[0])));
    }
}

// ---------------- launch ------------------------------------------------------
extern "C" void kernel_launch(void* const* d_in, const int* in_sizes, int n_in,
                              void* d_out, int out_size) {
    const int*   node_ids   = (const int*)d_in[0];
    const int*   edge_index = (const int*)d_in[1];
    const float* emb  = (const float*)d_in[3];
    const float* w1n  = (const float*)d_in[4];
    const float* w1r  = (const float*)d_in[5];
    const float* b1   = (const float*)d_in[6];
    const float* w2n  = (const float*)d_in[7];
    const float* w2r  = (const float*)d_in[8];
    const float* b2   = (const float*)d_in[9];
    const float* w3n  = (const float*)d_in[10];
    const float* w3r  = (const float*)d_in[11];
    const float* b3   = (const float*)d_in[12];
    const float* p1   = (const float*)d_in[13];
    const float* p2   = (const float*)d_in[14];
    const float* p3   = (const float*)d_in[15];
    const float* lw1  = (const float*)d_in[16];
    const float* lb1  = (const float*)d_in[17];
    const float* lw2  = (const float*)d_in[18];
    const float* lb2  = (const float*)d_in[19];
    const float* lw3  = (const float*)d_in[20];
    const float* lb3  = (const float*)d_in[21];
    float* out = (float*)d_out;

    static int smem_set = 0;
    if (!smem_set) {
        cudaFuncSetAttribute(mega_kernel,
                             cudaFuncAttributeMaxDynamicSharedMemorySize,
                             (int)sizeof(MegaSm));
        smem_set = 1;
    }

    mega_kernel<<<B, NT, sizeof(MegaSm)>>>(
        node_ids, edge_index, emb,
        w1n, w1r, b1, p1,
        w2n, w2r, b2, p2,
        w3n, w3r, b3, p3,
        lw1, lb1, lw2, lb2, lw3, lb3, out);
}

// round 12
// speedup vs baseline: 2.1848x; 1.0167x over previous
#include <cuda_runtime.h>
#include <math.h>
#include <stdint.h>

#define B    512
#define NP   200
#define EPG  2000
#define E_TOT (B*EPG)
#define HID  128
#define EMB  9
#define K1   160
#define K2   128
#define K3   103

#define NT   768           // threads
#define NW   24            // warps
#define INV_E 0xFFu
#define XSTR 132           // xs/ms row stride (floats)

// ---------------- async copy helpers -----------------------------------------
__device__ __forceinline__ void cp_async16(void* smem_dst, const void* gsrc) {
    uint32_t s = (uint32_t)__cvta_generic_to_shared(smem_dst);
    asm volatile("cp.async.ca.shared.global [%0], [%1], 16;\n" :: "r"(s), "l"(gsrc));
}
__device__ __forceinline__ void cp_commit() {
    asm volatile("cp.async.commit_group;\n" ::: "memory");
}
template<int N>
__device__ __forceinline__ void cp_wait() {
    asm volatile("cp.async.wait_group %0;\n" :: "n"(N) : "memory");
}

// ---------------- tf32 mma primitive -----------------------------------------
__device__ __forceinline__ void mma_tf32(float c[4], uint32_t a0, uint32_t a1,
                                         uint32_t a2, uint32_t a3,
                                         uint32_t b0, uint32_t b1) {
    asm volatile(
        "mma.sync.aligned.m16n8k8.row.col.f32.tf32.tf32.f32 "
        "{%0,%1,%2,%3}, {%4,%5,%6,%7}, {%8,%9}, {%0,%1,%2,%3};"
        : "+f"(c[0]), "+f"(c[1]), "+f"(c[2]), "+f"(c[3])
        : "r"(a0), "r"(a1), "r"(a2), "r"(a3), "r"(b0), "r"(b1));
}

// ---------------- mega kernel smem -------------------------------------------
struct MegaSm {
    float xs[160][XSTR];     // pooled features (current space)
    float ms[160][XSTR];     // neighbor means (current space)
    union {
        struct {             // conv1 phase
            float As1[208][28];   // [mean(9) | x(9) | pad] per node
            float W1s[128][28];   // [w1n | w1r | pad]
        } c1;
        float wst2[2][128][36];  // level-GEMM W k-chunk double buffer
    } u;
    float s[208];            // scores (n is always a multiple of 4)
    float sdp[4][208];       // deterministic 4-part score dot (conv1 uses 2)
    float bb[128];
    float ps[128];
    float harr[256];         // readout accumulator x1+x2+x3
    float pmax[6][128];
    float psum[6][128];
    float h1[128];
    float h2[64];
    float rns[3];
    int   hist[224];
    int   off[225];          // ORIGINAL-space CSR offsets (built once)
    int   cur[224];
    int   wsum[8];
    short newloc[208];
    short kept[160];
    short o2c[208];          // orig -> current (composed across topks), -1 dead
    short c2o[2][160];       // current -> orig per level (0: after topk1)
    unsigned char esrc[EPG];
    unsigned char edst[EPG];
    unsigned char eord[EPG]; // srcs sorted by ORIGINAL dst (built once)
};

// parallel exclusive scan of hist[0..n) -> off/cur, off[n]=total
__device__ __forceinline__ void excl_scan(MegaSm* S, int n) {
    int tid = threadIdx.x, lane = tid & 31, w = tid >> 5;
    int npad = (n + 31) & ~31;
    if (tid < npad) {
        int h0 = S->hist[tid];
        int x = h0;
#pragma unroll
        for (int o = 1; o < 32; o <<= 1) {
            int y = __shfl_up_sync(0xffffffffu, x, o);
            if (lane >= o) x += y;
        }
        if (lane == 31) S->wsum[w] = x;
        S->off[tid] = x - h0;
    }
    __syncthreads();
    if (tid == 0) {
        int a = 0, nw = npad >> 5;
        for (int i = 0; i < nw; i++) { int t = S->wsum[i]; S->wsum[i] = a; a += t; }
        S->off[n] = a;
    }
    __syncthreads();
    if (tid < n) {
        int o = S->off[tid] + S->wsum[w];
        S->off[tid] = o;
        S->cur[tid] = o;
    }
    __syncthreads();
}

// one-time counting sort of edges by ORIGINAL dst into eord
__device__ __forceinline__ void edge_sort_once(MegaSm* S) {
    int tid = threadIdx.x;
    for (int i = tid; i < 224; i += NT) S->hist[i] = 0;
    __syncthreads();
    for (int e = tid; e < EPG; e += NT)
        atomicAdd(&S->hist[S->edst[e]], 1);
    __syncthreads();
    excl_scan(S, NP);
    for (int e = tid; e < EPG; e += NT) {
        int p = atomicAdd(&S->cur[S->edst[e]], 1);
        S->eord[p] = S->esrc[e];
    }
    __syncthreads();
}

// 128-dim neighbor mean at levels 2/3: iterate original edge lists of kept
// nodes, skip edges whose source died (o2c < 0). No per-level sort/remap.
__device__ __forceinline__ void level_agg2(MegaSm* S, int n, const short* c2o) {
    __syncthreads();     // o2c/c2o/xs visibility
    int tid = threadIdx.x, w = tid >> 5, lane = tid & 31;
    for (int v = w; v < n; v += NW) {
        int ov = c2o[v];
        int e0 = S->off[ov], e1 = S->off[ov + 1];
        float4 a = make_float4(0.f, 0.f, 0.f, 0.f);
        int cnt = 0;
        for (int e = e0; e < e1; e++) {
            int cs = S->o2c[S->eord[e]];
            if (cs >= 0) {
                float4 p = *(const float4*)&S->xs[cs][4*lane];
                a.x += p.x; a.y += p.y; a.z += p.z; a.w += p.w;
                cnt++;
            }
        }
        float inv = (cnt > 0) ? 1.0f / (float)cnt : 0.0f;
        *(float4*)&S->ms[v][4*lane] =
            make_float4(a.x * inv, a.y * inv, a.z * inv, a.w * inv);
    }
    __syncthreads();
}

// 3-way split rank with float4 inner loads
__device__ __forceinline__ void level_rank(MegaSm* S, int n, int k) {
    int tid = threadIdx.x;
    for (int i = tid; i < n; i += NT) S->hist[i] = 0;
    __syncthreads();
    int v = tid & 255;
    int part = tid >> 8;                 // 0..2 (768 = 3*256)
    if (v < n) {
        int chunk = (((n + 2) / 3) + 3) & ~3;
        int u0 = part * chunk;
        int u1 = min(n, u0 + chunk);
        float sv = S->s[v];
        int r = 0;
        int u = u0;
        for (; u + 4 <= u1; u += 4) {
            float4 s4 = *(const float4*)&S->s[u];
            r += (s4.x > sv) || (s4.x == sv && (u + 0) < v);
            r += (s4.y > sv) || (s4.y == sv && (u + 1) < v);
            r += (s4.z > sv) || (s4.z == sv && (u + 2) < v);
            r += (s4.w > sv) || (s4.w == sv && (u + 3) < v);
        }
        for (; u < u1; u++) {
            float su = S->s[u];
            r += (su > sv) || (su == sv && u < v);
        }
        atomicAdd(&S->hist[v], r);
    }
    __syncthreads();
    for (int v2 = tid; v2 < n; v2 += NT) {
        int r = S->hist[v2];
        S->newloc[v2] = (r < k) ? (short)r : (short)-1;
        if (r < k) S->kept[r] = (short)v2;
    }
    __syncthreads();
}

// pool xs rows [0,k) into harr (6 row-slices). No trailing sync (audited).
__device__ __forceinline__ void pool_xs(MegaSm* S, int k) {
    int tid = threadIdx.x;
    int d = tid & 127, sl = tid >> 7;    // 0..5
    float mx = -INFINITY, sm = 0.0f;
    for (int r = sl; r < k; r += 6) {
        float v = S->xs[r][d];
        mx = fmaxf(mx, v);
        sm += v;
    }
    S->pmax[sl][d] = mx;
    S->psum[sl][d] = sm;
    __syncthreads();
    if (tid < 128) {
        float m = S->pmax[0][tid];
        float t = S->psum[0][tid];
#pragma unroll
        for (int i = 1; i < 6; i++) {
            m = fmaxf(m, S->pmax[i][tid]);
            t += S->psum[i][tid];
        }
        S->harr[tid]       += m;
        S->harr[128 + tid] += t / (float)k;
    }
}

// stage one 32-k chunk of the level weights into wst2[buf]
__device__ __forceinline__ void stage_chunk(
        MegaSm* S, int buf, const float* __restrict__ Wn,
        const float* __restrict__ Wr, int ci) {
    const float* Wg = (ci < 4) ? Wn : Wr;
    int kg = (ci * 32) & 127;
    int tid = threadIdx.x;
    for (int idx = tid; idx < 1024; idx += NT) {
        int r = idx >> 3, q = idx & 7;
        cp_async16(&S->u.wst2[buf][r][q * 4], &Wg[r * 128 + kg + q * 4]);
    }
    cp_commit();
}

// level GEMM, single sync per k-chunk (depth-1 cp.async prefetch; chunk 0
// pre-staged by caller). Fused score+topk+scatter+pool.
__device__ __forceinline__ void level_gemm_topk(
        MegaSm* S, int n, int k, float rn,
        const float* __restrict__ Wn, const float* __restrict__ Wr) {
    int tid = threadIdx.x, lane = tid & 31, w = tid >> 5;
    int rg = w >> 2, cf = w & 3;
    bool active = (rg < (n >> 5));

    float acc[2][4][4];
#pragma unroll
    for (int mt = 0; mt < 2; mt++)
#pragma unroll
        for (int nt = 0; nt < 4; nt++)
#pragma unroll
            for (int i = 0; i < 4; i++) acc[mt][nt][i] = 0.0f;

#pragma unroll 1
    for (int ci = 0; ci < 8; ci++) {
        cp_wait<0>();
        __syncthreads();   // chunk ci visible; all warps done with buf (ci+1)&1
        if (ci < 7) stage_chunk(S, (ci + 1) & 1, Wn, Wr, ci + 1);

        int nb = ci & 1;
        if (active) {
            int kc = ci * 32;
            const float (*A)[XSTR] = (kc < 128) ? S->ms : S->xs;
            int kg = kc & 127;
#pragma unroll
            for (int ks = 0; ks < 32; ks += 8) {
                uint32_t a[2][4];
#pragma unroll
                for (int mt = 0; mt < 2; mt++) {
                    int rb = rg * 32 + mt * 16 + (lane >> 2);
                    int c = kg + ks + (lane & 3);
                    a[mt][0] = __float_as_uint(A[rb][c]);
                    a[mt][1] = __float_as_uint(A[rb + 8][c]);
                    a[mt][2] = __float_as_uint(A[rb][c + 4]);
                    a[mt][3] = __float_as_uint(A[rb + 8][c + 4]);
                }
#pragma unroll
                for (int nt = 0; nt < 4; nt++) {
                    int nr = cf * 32 + nt * 8 + (lane >> 2);
                    int cc = ks + (lane & 3);
                    uint32_t b0 = __float_as_uint(S->u.wst2[nb][nr][cc]);
                    uint32_t b1 = __float_as_uint(S->u.wst2[nb][nr][cc + 4]);
                    mma_tf32(acc[0][nt], a[0][0], a[0][1], a[0][2], a[0][3], b0, b1);
                    mma_tf32(acc[1][nt], a[1][0], a[1][1], a[1][2], a[1][3], b0, b1);
                }
            }
        }
    }

    if (active) {
#pragma unroll
        for (int mt = 0; mt < 2; mt++) {
            int r = rg * 32 + mt * 16 + (lane >> 2);
            float pd0 = 0.0f, pd1 = 0.0f;
#pragma unroll
            for (int nt = 0; nt < 4; nt++) {
                int col = cf * 32 + nt * 8 + 2 * (lane & 3);
                float v00 = fmaxf(acc[mt][nt][0] + S->bb[col],     0.0f);
                float v01 = fmaxf(acc[mt][nt][1] + S->bb[col + 1], 0.0f);
                float v10 = fmaxf(acc[mt][nt][2] + S->bb[col],     0.0f);
                float v11 = fmaxf(acc[mt][nt][3] + S->bb[col + 1], 0.0f);
                acc[mt][nt][0] = v00; acc[mt][nt][1] = v01;
                acc[mt][nt][2] = v10; acc[mt][nt][3] = v11;
                pd0 += v00 * S->ps[col] + v01 * S->ps[col + 1];
                pd1 += v10 * S->ps[col] + v11 * S->ps[col + 1];
            }
            pd0 += __shfl_xor_sync(0xffffffffu, pd0, 1);
            pd0 += __shfl_xor_sync(0xffffffffu, pd0, 2);
            pd1 += __shfl_xor_sync(0xffffffffu, pd1, 1);
            pd1 += __shfl_xor_sync(0xffffffffu, pd1, 2);
            if ((lane & 3) == 0) { S->sdp[cf][r] = pd0; S->sdp[cf][r + 8] = pd1; }
        }
    }
    __syncthreads();

    for (int v = tid; v < n; v += NT)
        S->s[v] = tanhf(((S->sdp[0][v] + S->sdp[1][v]) +
                         (S->sdp[2][v] + S->sdp[3][v])) * rn);
    __syncthreads();

    level_rank(S, n, k);

    if (active) {
#pragma unroll
        for (int mt = 0; mt < 2; mt++) {
            int r = rg * 32 + mt * 16 + (lane >> 2);
            int nl0 = S->newloc[r], nl1 = S->newloc[r + 8];
            float s0 = S->s[r], s1 = S->s[r + 8];
#pragma unroll
            for (int nt = 0; nt < 4; nt++) {
                int col = cf * 32 + nt * 8 + 2 * (lane & 3);
                if (nl0 >= 0)
                    *(float2*)&S->xs[nl0][col] =
                        make_float2(acc[mt][nt][0] * s0, acc[mt][nt][1] * s0);
                if (nl1 >= 0)
                    *(float2*)&S->xs[nl1][col] =
                        make_float2(acc[mt][nt][2] * s1, acc[mt][nt][3] * s1);
            }
        }
    }
    __syncthreads();

    pool_xs(S, k);
}

// ---------------- the single fused kernel ------------------------------------
__global__ __launch_bounds__(NT, 1) void mega_kernel(
        const int* __restrict__ node_ids,
        const int* __restrict__ edge_index,
        const float* __restrict__ emb,
        const float* __restrict__ w1n, const float* __restrict__ w1r,
        const float* __restrict__ b1,  const float* __restrict__ p1,
        const float* __restrict__ w2n, const float* __restrict__ w2r,
        const float* __restrict__ b2,  const float* __restrict__ p2,
        const float* __restrict__ w3n, const float* __restrict__ w3r,
        const float* __restrict__ b3,  const float* __restrict__ p3,
        const float* __restrict__ lw1, const float* __restrict__ lb1,
        const float* __restrict__ lw2, const float* __restrict__ lb2,
        const float* __restrict__ lw3, const float* __restrict__ lb3,
        float* __restrict__ out) {
    extern __shared__ char raw[];
    MegaSm* S = (MegaSm*)raw;

    int b = blockIdx.x, tid = threadIdx.x;
    int w = tid >> 5, lane = tid & 31;

    // edges -> smem (uint8 original indices)
    for (int e = tid; e < EPG; e += NT) {
        S->esrc[e] = (unsigned char)(edge_index[b*EPG + e] - b*NP);
        S->edst[e] = (unsigned char)(edge_index[E_TOT + b*EPG + e] - b*NP);
    }
    // 1/||p|| for the three pool vectors
    if (w < 3) {
        const float* pv = (w == 0) ? p1 : ((w == 1) ? p2 : p3);
        float v = pv[lane]*pv[lane] + pv[lane+32]*pv[lane+32]
                + pv[lane+64]*pv[lane+64] + pv[lane+96]*pv[lane+96];
#pragma unroll
        for (int o = 16; o; o >>= 1) v += __shfl_down_sync(0xffffffffu, v, o);
        if (lane == 0) S->rns[w] = 1.0f / sqrtf(v);
    }
    if (tid < 256) S->harr[tid] = 0.0f;
    if (tid < 128) { S->bb[tid] = b1[tid]; S->ps[tid] = p1[tid]; }

    // As1: zero everything; fill emb features into cols 9..17 for v<200
    for (int idx = tid; idx < 208*28; idx += NT) {
        int r = idx / 28, c = idx - r*28;
        float v = 0.0f;
        if (r < NP && c >= 9 && c < 18)
            v = emb[(size_t)node_ids[b*NP + r] * EMB + (c - 9)];
        S->u.c1.As1[r][c] = v;
    }
    // W1 stage [w1n | w1r | pad]
    for (int idx = tid; idx < 128*28; idx += NT) {
        int r = idx / 28, c = idx - r*28;
        float wv = 0.0f;
        if (c < 9)       wv = w1n[r*9 + c];
        else if (c < 18) wv = w1r[r*9 + (c - 9)];
        S->u.c1.W1s[r][c] = wv;
    }
    __syncthreads();

    // ---------- one-time edge sort + level-1 9-dim aggregation ----------
    edge_sort_once(S);
    for (int v = w; v < NP; v += NW) {
        int e0 = S->off[v], e1 = S->off[v+1];
        float inv = (e1 > e0) ? 1.0f / (float)(e1 - e0) : 0.0f;
        if (lane < EMB) {
            float a = 0.0f;
            for (int e = e0; e < e1; e++)
                a += S->u.c1.As1[S->eord[e]][9 + lane];
            S->u.c1.As1[v][lane] = a * inv;
        }
    }
    __syncthreads();

    // ---------- conv1 pass 1: score dot only (26 tasks, K=24, 16x64) ----------
#pragma unroll
    for (int ti = 0; ti < 2; ti++) {
        int t = w + ti * NW;
        if (t < 26) {
            int rg = t >> 1, hf = t & 1;
            int rb = rg * 16 + (lane >> 2);
            float acc[8][4];
#pragma unroll
            for (int nt = 0; nt < 8; nt++)
#pragma unroll
                for (int i = 0; i < 4; i++) acc[nt][i] = 0.0f;
#pragma unroll
            for (int ks = 0; ks < 24; ks += 8) {
                int c = ks + (lane & 3);
                uint32_t a0 = __float_as_uint(S->u.c1.As1[rb][c]);
                uint32_t a1 = __float_as_uint(S->u.c1.As1[rb + 8][c]);
                uint32_t a2 = __float_as_uint(S->u.c1.As1[rb][c + 4]);
                uint32_t a3 = __float_as_uint(S->u.c1.As1[rb + 8][c + 4]);
#pragma unroll
                for (int nt = 0; nt < 8; nt++) {
                    int nr = hf * 64 + nt * 8 + (lane >> 2);
                    uint32_t b0 = __float_as_uint(S->u.c1.W1s[nr][c]);
                    uint32_t b1 = __float_as_uint(S->u.c1.W1s[nr][c + 4]);
                    mma_tf32(acc[nt], a0, a1, a2, a3, b0, b1);
                }
            }
            int r = rg * 16 + (lane >> 2);
            float pd0 = 0.0f, pd1 = 0.0f;
#pragma unroll
            for (int nt = 0; nt < 8; nt++) {
                int col = hf * 64 + nt * 8 + 2 * (lane & 3);
                pd0 += fmaxf(acc[nt][0] + S->bb[col],     0.0f) * S->ps[col]
                     + fmaxf(acc[nt][1] + S->bb[col + 1], 0.0f) * S->ps[col + 1];
                pd1 += fmaxf(acc[nt][2] + S->bb[col],     0.0f) * S->ps[col]
                     + fmaxf(acc[nt][3] + S->bb[col + 1], 0.0f) * S->ps[col + 1];
            }
            pd0 += __shfl_xor_sync(0xffffffffu, pd0, 1);
            pd0 += __shfl_xor_sync(0xffffffffu, pd0, 2);
            pd1 += __shfl_xor_sync(0xffffffffu, pd1, 1);
            pd1 += __shfl_xor_sync(0xffffffffu, pd1, 2);
            if ((lane & 3) == 0) { S->sdp[hf][r] = pd0; S->sdp[hf][r + 8] = pd1; }
        }
    }
    __syncthreads();

    for (int v = tid; v < NP; v += NT)
        S->s[v] = tanhf((S->sdp[0][v] + S->sdp[1][v]) * S->rns[0]);
    __syncthreads();

    level_rank(S, NP, K1);

    // init composed maps (level-1 current == original space)
    for (int ov = tid; ov < NP; ov += NT) S->o2c[ov] = S->newloc[ov];
    for (int r = tid; r < K1; r += NT)   S->c2o[0][r] = S->kept[r];

    // ---------- conv1 pass 2: recompute kept rows, gain, write xs ----------
    if (w < 20) {
        int rg = w >> 1, hf = w & 1;
        int r0 = rg * 16 + (lane >> 2);
        int k0 = S->kept[r0], k1 = S->kept[r0 + 8];
        float s0 = S->s[k0],  s1 = S->s[k1];
        float acc[8][4];
#pragma unroll
        for (int nt = 0; nt < 8; nt++)
#pragma unroll
            for (int i = 0; i < 4; i++) acc[nt][i] = 0.0f;
#pragma unroll
        for (int ks = 0; ks < 24; ks += 8) {
            int c = ks + (lane & 3);
            uint32_t a0 = __float_as_uint(S->u.c1.As1[k0][c]);
            uint32_t a1 = __float_as_uint(S->u.c1.As1[k1][c]);
            uint32_t a2 = __float_as_uint(S->u.c1.As1[k0][c + 4]);
            uint32_t a3 = __float_as_uint(S->u.c1.As1[k1][c + 4]);
#pragma unroll
            for (int nt = 0; nt < 8; nt++) {
                int nr = hf * 64 + nt * 8 + (lane >> 2);
                uint32_t b0 = __float_as_uint(S->u.c1.W1s[nr][c]);
                uint32_t b1 = __float_as_uint(S->u.c1.W1s[nr][c + 4]);
                mma_tf32(acc[nt], a0, a1, a2, a3, b0, b1);
            }
        }
#pragma unroll
        for (int nt = 0; nt < 8; nt++) {
            int col = hf * 64 + nt * 8 + 2 * (lane & 3);
            float v00 = fmaxf(acc[nt][0] + S->bb[col],     0.0f) * s0;
            float v01 = fmaxf(acc[nt][1] + S->bb[col + 1], 0.0f) * s0;
            float v10 = fmaxf(acc[nt][2] + S->bb[col],     0.0f) * s1;
            float v11 = fmaxf(acc[nt][3] + S->bb[col + 1], 0.0f) * s1;
            *(float2*)&S->xs[r0][col]     = make_float2(v00, v01);
            *(float2*)&S->xs[r0 + 8][col] = make_float2(v10, v11);
        }
    }
    __syncthreads();

    pool_xs(S, K1);

    // ---------- level 2 ----------
    if (tid < 128) { S->bb[tid] = b2[tid]; S->ps[tid] = p2[tid]; }
    stage_chunk(S, 0, w2n, w2r, 0);      // prefetch chunk 0 under agg
    level_agg2(S, K1, S->c2o[0]);
    level_gemm_topk(S, K1, K2, S->rns[1], w2n, w2r);

    // compose maps with topk2 result (newloc/kept in K1-current space)
    for (int r = tid; r < K2; r += NT) S->c2o[1][r] = S->c2o[0][S->kept[r]];
    for (int ov = tid; ov < NP; ov += NT) {
        short c = S->o2c[ov];
        S->o2c[ov] = (c >= 0) ? S->newloc[c] : (short)-1;
    }

    // ---------- level 3 ----------
    if (tid < 128) { S->bb[tid] = b3[tid]; S->ps[tid] = p3[tid]; }
    stage_chunk(S, 0, w3n, w3r, 0);
    level_agg2(S, K2, S->c2o[1]);        // leading sync covers compose writes
    level_gemm_topk(S, K2, K3, S->rns[2], w3n, w3r);

    __syncthreads();                     // harr visibility for the MLP head

    // ---------- MLP head (coalesced warp-cooperative, float4) ----------
    {
        float4 h0 = *(const float4*)&S->harr[lane * 4];
        float4 h1v = *(const float4*)&S->harr[128 + lane * 4];
        for (int c = w; c < 128; c += NW) {
            const float4* w4 = (const float4*)(lw1 + c * 256);
            float4 w0 = w4[lane], w1v = w4[lane + 32];
            float a = w0.x*h0.x + w0.y*h0.y + w0.z*h0.z + w0.w*h0.w
                    + w1v.x*h1v.x + w1v.y*h1v.y + w1v.z*h1v.z + w1v.w*h1v.w;
#pragma unroll
            for (int o = 16; o; o >>= 1) a += __shfl_xor_sync(0xffffffffu, a, o);
            if (lane == 0) S->h1[c] = fmaxf(a + lb1[c], 0.0f);
        }
    }
    __syncthreads();
    {
        float4 g0 = *(const float4*)&S->h1[lane * 4];
        for (int c = w; c < 64; c += NW) {
            float4 w0 = ((const float4*)(lw2 + c * 128))[lane];
            float a = w0.x*g0.x + w0.y*g0.y + w0.z*g0.z + w0.w*g0.w;
#pragma unroll
            for (int o = 16; o; o >>= 1) a += __shfl_xor_sync(0xffffffffu, a, o);
            if (lane == 0) S->h2[c] = fmaxf(a + lb2[c], 0.0f);
        }
    }
    __syncthreads();
    if (w == 0) {
        float a = 0.0f;
#pragma unroll
        for (int j = 0; j < 2; j++)
            a += lw3[j*32 + lane] * S->h2[j*32 + lane];
#pragma unroll
        for (int o = 16; o; o >>= 1) a += __shfl_xor_sync(0xffffffffu, a, o);
        if (lane == 0) out[b] = 1.0f / (1.0f + expf(-(a + lb3[0])));
    }
}

// ---------------- launch ------------------------------------------------------
extern "C" void kernel_launch(void* const* d_in, const int* in_sizes, int n_in,
                              void* d_out, int out_size) {
    const int*   node_ids   = (const int*)d_in[0];
    const int*   edge_index = (const int*)d_in[1];
    const float* emb  = (const float*)d_in[3];
    const float* w1n  = (const float*)d_in[4];
    const float* w1r  = (const float*)d_in[5];
    const float* b1   = (const float*)d_in[6];
    const float* w2n  = (const float*)d_in[7];
    const float* w2r  = (const float*)d_in[8];
    const float* b2   = (const float*)d_in[9];
    const float* w3n  = (const float*)d_in[10];
    const float* w3r  = (const float*)d_in[11];
    const float* b3   = (const float*)d_in[12];
    const float* p1   = (const float*)d_in[13];
    const float* p2   = (const float*)d_in[14];
    const float* p3   = (const float*)d_in[15];
    const float* lw1  = (const float*)d_in[16];
    const float* lb1  = (const float*)d_in[17];
    const float* lw2  = (const float*)d_in[18];
    const float* lb2  = (const float*)d_in[19];
    const float* lw3  = (const float*)d_in[20];
    const float* lb3  = (const float*)d_in[21];
    float* out = (float*)d_out;

    static int smem_set = 0;
    if (!smem_set) {
        cudaFuncSetAttribute(mega_kernel,
                             cudaFuncAttributeMaxDynamicSharedMemorySize,
                             (int)sizeof(MegaSm));
        smem_set = 1;
    }

    mega_kernel<<<B, NT, sizeof(MegaSm)>>>(
        node_ids, edge_index, emb,
        w1n, w1r, b1, p1,
        w2n, w2r, b2, p2,
        w3n, w3r, b3, p3,
        lw1, lb1, lw2, lb2, lw3, lb3, out);
}

// round 13
// speedup vs baseline: 2.2683x; 1.0382x over previous
#include <cuda_runtime.h>
#include <math.h>
#include <stdint.h>

#define B    512
#define NP   200
#define EPG  2000
#define E_TOT (B*EPG)
#define HID  128
#define EMB  9
#define K1   160
#define K2   128
#define K3   103

#define NT   768           // threads
#define NW   24            // warps
#define INV_E 0xFFu
#define XSTR 132           // xs/ms row stride (floats)

// ---------------- async copy helpers -----------------------------------------
__device__ __forceinline__ void cp_async16(void* smem_dst, const void* gsrc) {
    uint32_t s = (uint32_t)__cvta_generic_to_shared(smem_dst);
    asm volatile("cp.async.ca.shared.global [%0], [%1], 16;\n" :: "r"(s), "l"(gsrc));
}
__device__ __forceinline__ void cp_commit() {
    asm volatile("cp.async.commit_group;\n" ::: "memory");
}
template<int N>
__device__ __forceinline__ void cp_wait() {
    asm volatile("cp.async.wait_group %0;\n" :: "n"(N) : "memory");
}

// ---------------- tf32 mma + ldmatrix primitives ------------------------------
__device__ __forceinline__ void mma_tf32(float c[4], uint32_t a0, uint32_t a1,
                                         uint32_t a2, uint32_t a3,
                                         uint32_t b0, uint32_t b1) {
    asm volatile(
        "mma.sync.aligned.m16n8k8.row.col.f32.tf32.tf32.f32 "
        "{%0,%1,%2,%3}, {%4,%5,%6,%7}, {%8,%9}, {%0,%1,%2,%3};"
        : "+f"(c[0]), "+f"(c[1]), "+f"(c[2]), "+f"(c[3])
        : "r"(a0), "r"(a1), "r"(a2), "r"(a3), "r"(b0), "r"(b1));
}
__device__ __forceinline__ void ldsm4(uint32_t r[4], uint32_t addr) {
    asm volatile("ldmatrix.sync.aligned.m8n8.x4.shared.b16 {%0,%1,%2,%3}, [%4];"
        : "=r"(r[0]), "=r"(r[1]), "=r"(r[2]), "=r"(r[3]) : "r"(addr));
}
__device__ __forceinline__ uint32_t smem_u32(const void* p) {
    return (uint32_t)__cvta_generic_to_shared(p);
}

// ---------------- mega kernel smem -------------------------------------------
struct MegaSm {
    float xs[160][XSTR];     // pooled features (current space)
    float ms[160][XSTR];     // neighbor means (current space)
    union {
        struct {             // conv1 phase
            float As1[208][28];   // [mean(9) | x(9) | pad] per node
            float W1s[128][28];   // [w1n | w1r | pad]
        } c1;
        float wst2[2][128][36];  // level-GEMM W k-chunk double buffer
    } u;
    float s[208];            // scores (n is always a multiple of 4)
    float sdp[4][208];       // deterministic 4-part score dot (conv1 uses 2)
    float bb[128];
    float ps[128];
    float harr[256];         // readout accumulator x1+x2+x3
    float pmax[6][128];
    float psum[6][128];
    float h1[128];
    float h2[64];
    float rns[3];
    int   hist[224];
    int   off[225];          // ORIGINAL-space CSR offsets (built once)
    int   cur[224];
    int   wsum[8];
    short newloc[208];
    short kept[160];
    short o2c[208];          // orig -> current (composed across topks), -1 dead
    short c2o[2][160];       // current -> orig per level (0: after topk1)
    unsigned char esrc[EPG];
    unsigned char edst[EPG];
    unsigned char eord[EPG]; // srcs sorted by ORIGINAL dst (built once)
};

// parallel exclusive scan of hist[0..n) -> off/cur, off[n]=total
__device__ __forceinline__ void excl_scan(MegaSm* S, int n) {
    int tid = threadIdx.x, lane = tid & 31, w = tid >> 5;
    int npad = (n + 31) & ~31;
    if (tid < npad) {
        int h0 = S->hist[tid];
        int x = h0;
#pragma unroll
        for (int o = 1; o < 32; o <<= 1) {
            int y = __shfl_up_sync(0xffffffffu, x, o);
            if (lane >= o) x += y;
        }
        if (lane == 31) S->wsum[w] = x;
        S->off[tid] = x - h0;
    }
    __syncthreads();
    if (tid == 0) {
        int a = 0, nw = npad >> 5;
        for (int i = 0; i < nw; i++) { int t = S->wsum[i]; S->wsum[i] = a; a += t; }
        S->off[n] = a;
    }
    __syncthreads();
    if (tid < n) {
        int o = S->off[tid] + S->wsum[w];
        S->off[tid] = o;
        S->cur[tid] = o;
    }
    __syncthreads();
}

// one-time counting sort of edges by ORIGINAL dst into eord
__device__ __forceinline__ void edge_sort_once(MegaSm* S) {
    int tid = threadIdx.x;
    for (int i = tid; i < 224; i += NT) S->hist[i] = 0;
    __syncthreads();
    for (int e = tid; e < EPG; e += NT)
        atomicAdd(&S->hist[S->edst[e]], 1);
    __syncthreads();
    excl_scan(S, NP);
    for (int e = tid; e < EPG; e += NT) {
        int p = atomicAdd(&S->cur[S->edst[e]], 1);
        S->eord[p] = S->esrc[e];
    }
    __syncthreads();
}

// 128-dim neighbor mean at levels 2/3: iterate original edge lists of kept
// nodes, skip edges whose source died (o2c < 0). No per-level sort/remap.
__device__ __forceinline__ void level_agg2(MegaSm* S, int n, const short* c2o) {
    __syncthreads();     // o2c/c2o/xs visibility
    int tid = threadIdx.x, w = tid >> 5, lane = tid & 31;
    for (int v = w; v < n; v += NW) {
        int ov = c2o[v];
        int e0 = S->off[ov], e1 = S->off[ov + 1];
        float4 a = make_float4(0.f, 0.f, 0.f, 0.f);
        int cnt = 0;
        for (int e = e0; e < e1; e++) {
            int cs = S->o2c[S->eord[e]];
            if (cs >= 0) {
                float4 p = *(const float4*)&S->xs[cs][4*lane];
                a.x += p.x; a.y += p.y; a.z += p.z; a.w += p.w;
                cnt++;
            }
        }
        float inv = (cnt > 0) ? 1.0f / (float)cnt : 0.0f;
        *(float4*)&S->ms[v][4*lane] =
            make_float4(a.x * inv, a.y * inv, a.z * inv, a.w * inv);
    }
    __syncthreads();
}

// 3-way split rank with float4 inner loads
__device__ __forceinline__ void level_rank(MegaSm* S, int n, int k) {
    int tid = threadIdx.x;
    for (int i = tid; i < n; i += NT) S->hist[i] = 0;
    __syncthreads();
    int v = tid & 255;
    int part = tid >> 8;                 // 0..2 (768 = 3*256)
    if (v < n) {
        int chunk = (((n + 2) / 3) + 3) & ~3;
        int u0 = part * chunk;
        int u1 = min(n, u0 + chunk);
        float sv = S->s[v];
        int r = 0;
        int u = u0;
        for (; u + 4 <= u1; u += 4) {
            float4 s4 = *(const float4*)&S->s[u];
            r += (s4.x > sv) || (s4.x == sv && (u + 0) < v);
            r += (s4.y > sv) || (s4.y == sv && (u + 1) < v);
            r += (s4.z > sv) || (s4.z == sv && (u + 2) < v);
            r += (s4.w > sv) || (s4.w == sv && (u + 3) < v);
        }
        for (; u < u1; u++) {
            float su = S->s[u];
            r += (su > sv) || (su == sv && u < v);
        }
        atomicAdd(&S->hist[v], r);
    }
    __syncthreads();
    for (int v2 = tid; v2 < n; v2 += NT) {
        int r = S->hist[v2];
        S->newloc[v2] = (r < k) ? (short)r : (short)-1;
        if (r < k) S->kept[r] = (short)v2;
    }
    __syncthreads();
}

// pool xs rows [0,k) into harr (6 row-slices). No trailing sync (audited).
__device__ __forceinline__ void pool_xs(MegaSm* S, int k) {
    int tid = threadIdx.x;
    int d = tid & 127, sl = tid >> 7;    // 0..5
    float mx = -INFINITY, sm = 0.0f;
    for (int r = sl; r < k; r += 6) {
        float v = S->xs[r][d];
        mx = fmaxf(mx, v);
        sm += v;
    }
    S->pmax[sl][d] = mx;
    S->psum[sl][d] = sm;
    __syncthreads();
    if (tid < 128) {
        float m = S->pmax[0][tid];
        float t = S->psum[0][tid];
#pragma unroll
        for (int i = 1; i < 6; i++) {
            m = fmaxf(m, S->pmax[i][tid]);
            t += S->psum[i][tid];
        }
        S->harr[tid]       += m;
        S->harr[128 + tid] += t / (float)k;
    }
}

// stage one 32-k chunk of the level weights into wst2[buf]
__device__ __forceinline__ void stage_chunk(
        MegaSm* S, int buf, const float* __restrict__ Wn,
        const float* __restrict__ Wr, int ci) {
    const float* Wg = (ci < 4) ? Wn : Wr;
    int kg = (ci * 32) & 127;
    int tid = threadIdx.x;
    for (int idx = tid; idx < 1024; idx += NT) {
        int r = idx >> 3, q = idx & 7;
        cp_async16(&S->u.wst2[buf][r][q * 4], &Wg[r * 128 + kg + q * 4]);
    }
    cp_commit();
}

// level GEMM, single sync per k-chunk, LDSM fragment loads.
// Fused score+topk+scatter+pool.
__device__ __forceinline__ void level_gemm_topk(
        MegaSm* S, int n, int k, float rn,
        const float* __restrict__ Wn, const float* __restrict__ Wr) {
    int tid = threadIdx.x, lane = tid & 31, w = tid >> 5;
    int rg = w >> 2, cf = w & 3;
    bool active = (rg < (n >> 5));

    // ldmatrix lane roles
    int t8    = lane >> 3;                       // tile index 0..3
    int lane7 = lane & 7;
    int aRow  = rg * 32 + (t8 & 1) * 8 + lane7;  // A: tiles 0/2 rows, 1/3 rows+8
    int aColO = (t8 >> 1) * 4;                   // A: tiles 2,3 at col+4
    int bRow  = cf * 32 + (t8 >> 1) * 8 + lane7; // B: tile pair rows
    int bColO = (t8 & 1) * 4;                    // B: tiles 1,3 at col+4

    float acc[2][4][4];
#pragma unroll
    for (int mt = 0; mt < 2; mt++)
#pragma unroll
        for (int nt = 0; nt < 4; nt++)
#pragma unroll
            for (int i = 0; i < 4; i++) acc[mt][nt][i] = 0.0f;

#pragma unroll 1
    for (int ci = 0; ci < 8; ci++) {
        cp_wait<0>();
        __syncthreads();   // chunk ci visible; all warps done with buf (ci+1)&1
        if (ci < 7) stage_chunk(S, (ci + 1) & 1, Wn, Wr, ci + 1);

        int nb = ci & 1;
        if (active) {
            int kc = ci * 32;
            const float (*A)[XSTR] = (kc < 128) ? S->ms : S->xs;
            int kg = kc & 127;
            uint32_t aA = smem_u32(&A[aRow][kg + aColO]);
            uint32_t aB = smem_u32(&S->u.wst2[nb][bRow][bColO]);
#pragma unroll
            for (int ks = 0; ks < 32; ks += 8) {
                uint32_t am0[4], am1[4], bp0[4], bp1[4];
                ldsm4(am0, aA + ks * 4);
                ldsm4(am1, aA + 16 * XSTR * 4 + ks * 4);
                ldsm4(bp0, aB + ks * 4);
                ldsm4(bp1, aB + 16 * 36 * 4 + ks * 4);
                mma_tf32(acc[0][0], am0[0], am0[1], am0[2], am0[3], bp0[0], bp0[1]);
                mma_tf32(acc[0][1], am0[0], am0[1], am0[2], am0[3], bp0[2], bp0[3]);
                mma_tf32(acc[0][2], am0[0], am0[1], am0[2], am0[3], bp1[0], bp1[1]);
                mma_tf32(acc[0][3], am0[0], am0[1], am0[2], am0[3], bp1[2], bp1[3]);
                mma_tf32(acc[1][0], am1[0], am1[1], am1[2], am1[3], bp0[0], bp0[1]);
                mma_tf32(acc[1][1], am1[0], am1[1], am1[2], am1[3], bp0[2], bp0[3]);
                mma_tf32(acc[1][2], am1[0], am1[1], am1[2], am1[3], bp1[0], bp1[1]);
                mma_tf32(acc[1][3], am1[0], am1[1], am1[2], am1[3], bp1[2], bp1[3]);
            }
        }
    }

    if (active) {
#pragma unroll
        for (int mt = 0; mt < 2; mt++) {
            int r = rg * 32 + mt * 16 + (lane >> 2);
            float pd0 = 0.0f, pd1 = 0.0f;
#pragma unroll
            for (int nt = 0; nt < 4; nt++) {
                int col = cf * 32 + nt * 8 + 2 * (lane & 3);
                float v00 = fmaxf(acc[mt][nt][0] + S->bb[col],     0.0f);
                float v01 = fmaxf(acc[mt][nt][1] + S->bb[col + 1], 0.0f);
                float v10 = fmaxf(acc[mt][nt][2] + S->bb[col],     0.0f);
                float v11 = fmaxf(acc[mt][nt][3] + S->bb[col + 1], 0.0f);
                acc[mt][nt][0] = v00; acc[mt][nt][1] = v01;
                acc[mt][nt][2] = v10; acc[mt][nt][3] = v11;
                pd0 += v00 * S->ps[col] + v01 * S->ps[col + 1];
                pd1 += v10 * S->ps[col] + v11 * S->ps[col + 1];
            }
            pd0 += __shfl_xor_sync(0xffffffffu, pd0, 1);
            pd0 += __shfl_xor_sync(0xffffffffu, pd0, 2);
            pd1 += __shfl_xor_sync(0xffffffffu, pd1, 1);
            pd1 += __shfl_xor_sync(0xffffffffu, pd1, 2);
            if ((lane & 3) == 0) { S->sdp[cf][r] = pd0; S->sdp[cf][r + 8] = pd1; }
        }
    }
    __syncthreads();

    for (int v = tid; v < n; v += NT)
        S->s[v] = tanhf(((S->sdp[0][v] + S->sdp[1][v]) +
                         (S->sdp[2][v] + S->sdp[3][v])) * rn);
    __syncthreads();

    level_rank(S, n, k);

    if (active) {
#pragma unroll
        for (int mt = 0; mt < 2; mt++) {
            int r = rg * 32 + mt * 16 + (lane >> 2);
            int nl0 = S->newloc[r], nl1 = S->newloc[r + 8];
            float s0 = S->s[r], s1 = S->s[r + 8];
#pragma unroll
            for (int nt = 0; nt < 4; nt++) {
                int col = cf * 32 + nt * 8 + 2 * (lane & 3);
                if (nl0 >= 0)
                    *(float2*)&S->xs[nl0][col] =
                        make_float2(acc[mt][nt][0] * s0, acc[mt][nt][1] * s0);
                if (nl1 >= 0)
                    *(float2*)&S->xs[nl1][col] =
                        make_float2(acc[mt][nt][2] * s1, acc[mt][nt][3] * s1);
            }
        }
    }
    __syncthreads();

    pool_xs(S, k);
}

// ---------------- the single fused kernel ------------------------------------
__global__ __launch_bounds__(NT, 1) void mega_kernel(
        const int* __restrict__ node_ids,
        const int* __restrict__ edge_index,
        const float* __restrict__ emb,
        const float* __restrict__ w1n, const float* __restrict__ w1r,
        const float* __restrict__ b1,  const float* __restrict__ p1,
        const float* __restrict__ w2n, const float* __restrict__ w2r,
        const float* __restrict__ b2,  const float* __restrict__ p2,
        const float* __restrict__ w3n, const float* __restrict__ w3r,
        const float* __restrict__ b3,  const float* __restrict__ p3,
        const float* __restrict__ lw1, const float* __restrict__ lb1,
        const float* __restrict__ lw2, const float* __restrict__ lb2,
        const float* __restrict__ lw3, const float* __restrict__ lb3,
        float* __restrict__ out) {
    extern __shared__ char raw[];
    MegaSm* S = (MegaSm*)raw;

    int b = blockIdx.x, tid = threadIdx.x;
    int w = tid >> 5, lane = tid & 31;

    // edges -> smem (uint8 original indices)
    for (int e = tid; e < EPG; e += NT) {
        S->esrc[e] = (unsigned char)(edge_index[b*EPG + e] - b*NP);
        S->edst[e] = (unsigned char)(edge_index[E_TOT + b*EPG + e] - b*NP);
    }
    // 1/||p|| for the three pool vectors
    if (w < 3) {
        const float* pv = (w == 0) ? p1 : ((w == 1) ? p2 : p3);
        float v = pv[lane]*pv[lane] + pv[lane+32]*pv[lane+32]
                + pv[lane+64]*pv[lane+64] + pv[lane+96]*pv[lane+96];
#pragma unroll
        for (int o = 16; o; o >>= 1) v += __shfl_down_sync(0xffffffffu, v, o);
        if (lane == 0) S->rns[w] = 1.0f / sqrtf(v);
    }
    if (tid < 256) S->harr[tid] = 0.0f;
    if (tid < 128) { S->bb[tid] = b1[tid]; S->ps[tid] = p1[tid]; }

    // As1: zero everything; fill emb features into cols 9..17 for v<200
    for (int idx = tid; idx < 208*28; idx += NT) {
        int r = idx / 28, c = idx - r*28;
        float v = 0.0f;
        if (r < NP && c >= 9 && c < 18)
            v = emb[(size_t)node_ids[b*NP + r] * EMB + (c - 9)];
        S->u.c1.As1[r][c] = v;
    }
    // W1 stage [w1n | w1r | pad]
    for (int idx = tid; idx < 128*28; idx += NT) {
        int r = idx / 28, c = idx - r*28;
        float wv = 0.0f;
        if (c < 9)       wv = w1n[r*9 + c];
        else if (c < 18) wv = w1r[r*9 + (c - 9)];
        S->u.c1.W1s[r][c] = wv;
    }
    __syncthreads();

    // ---------- one-time edge sort + level-1 9-dim aggregation ----------
    edge_sort_once(S);
    for (int v = w; v < NP; v += NW) {
        int e0 = S->off[v], e1 = S->off[v+1];
        float inv = (e1 > e0) ? 1.0f / (float)(e1 - e0) : 0.0f;
        if (lane < EMB) {
            float a = 0.0f;
            for (int e = e0; e < e1; e++)
                a += S->u.c1.As1[S->eord[e]][9 + lane];
            S->u.c1.As1[v][lane] = a * inv;
        }
    }
    __syncthreads();

    // ---------- conv1 pass 1: score dot only (26 tasks, K=24, LDSM) ----------
    {
        int t8    = lane >> 3;
        int lane7 = lane & 7;
        int aRowO = (t8 & 1) * 8 + lane7;
        int aColO = (t8 >> 1) * 4;
        int bRowO = (t8 >> 1) * 8 + lane7;
        int bColO = (t8 & 1) * 4;
#pragma unroll
        for (int ti = 0; ti < 2; ti++) {
            int t = w + ti * NW;
            if (t < 26) {
                int rg = t >> 1, hf = t & 1;
                float acc[8][4];
#pragma unroll
                for (int nt = 0; nt < 8; nt++)
#pragma unroll
                    for (int i = 0; i < 4; i++) acc[nt][i] = 0.0f;
                uint32_t aA = smem_u32(&S->u.c1.As1[rg * 16 + aRowO][aColO]);
                uint32_t aB = smem_u32(&S->u.c1.W1s[hf * 64 + bRowO][bColO]);
#pragma unroll
                for (int ks = 0; ks < 24; ks += 8) {
                    uint32_t am[4];
                    ldsm4(am, aA + ks * 4);
#pragma unroll
                    for (int p = 0; p < 4; p++) {
                        uint32_t bp[4];
                        ldsm4(bp, aB + p * 16 * 28 * 4 + ks * 4);
                        mma_tf32(acc[2*p],   am[0], am[1], am[2], am[3], bp[0], bp[1]);
                        mma_tf32(acc[2*p+1], am[0], am[1], am[2], am[3], bp[2], bp[3]);
                    }
                }
                int r = rg * 16 + (lane >> 2);
                float pd0 = 0.0f, pd1 = 0.0f;
#pragma unroll
                for (int nt = 0; nt < 8; nt++) {
                    int col = hf * 64 + nt * 8 + 2 * (lane & 3);
                    pd0 += fmaxf(acc[nt][0] + S->bb[col],     0.0f) * S->ps[col]
                         + fmaxf(acc[nt][1] + S->bb[col + 1], 0.0f) * S->ps[col + 1];
                    pd1 += fmaxf(acc[nt][2] + S->bb[col],     0.0f) * S->ps[col]
                         + fmaxf(acc[nt][3] + S->bb[col + 1], 0.0f) * S->ps[col + 1];
                }
                pd0 += __shfl_xor_sync(0xffffffffu, pd0, 1);
                pd0 += __shfl_xor_sync(0xffffffffu, pd0, 2);
                pd1 += __shfl_xor_sync(0xffffffffu, pd1, 1);
                pd1 += __shfl_xor_sync(0xffffffffu, pd1, 2);
                if ((lane & 3) == 0) { S->sdp[hf][r] = pd0; S->sdp[hf][r + 8] = pd1; }
            }
        }
    }
    __syncthreads();

    for (int v = tid; v < NP; v += NT)
        S->s[v] = tanhf((S->sdp[0][v] + S->sdp[1][v]) * S->rns[0]);
    __syncthreads();

    level_rank(S, NP, K1);

    // init composed maps (level-1 current == original space)
    for (int ov = tid; ov < NP; ov += NT) S->o2c[ov] = S->newloc[ov];
    for (int r = tid; r < K1; r += NT)   S->c2o[0][r] = S->kept[r];

    // ---------- conv1 pass 2: recompute kept rows, gain, write xs ----------
    if (w < 20) {
        int rg = w >> 1, hf = w & 1;
        int r0 = rg * 16 + (lane >> 2);
        int k0 = S->kept[r0], k1 = S->kept[r0 + 8];
        float s0 = S->s[k0],  s1 = S->s[k1];
        float acc[8][4];
#pragma unroll
        for (int nt = 0; nt < 8; nt++)
#pragma unroll
            for (int i = 0; i < 4; i++) acc[nt][i] = 0.0f;
#pragma unroll
        for (int ks = 0; ks < 24; ks += 8) {
            int c = ks + (lane & 3);
            uint32_t a0 = __float_as_uint(S->u.c1.As1[k0][c]);
            uint32_t a1 = __float_as_uint(S->u.c1.As1[k1][c]);
            uint32_t a2 = __float_as_uint(S->u.c1.As1[k0][c + 4]);
            uint32_t a3 = __float_as_uint(S->u.c1.As1[k1][c + 4]);
#pragma unroll
            for (int nt = 0; nt < 8; nt++) {
                int nr = hf * 64 + nt * 8 + (lane >> 2);
                uint32_t b0 = __float_as_uint(S->u.c1.W1s[nr][c]);
                uint32_t b1 = __float_as_uint(S->u.c1.W1s[nr][c + 4]);
                mma_tf32(acc[nt], a0, a1, a2, a3, b0, b1);
            }
        }
#pragma unroll
        for (int nt = 0; nt < 8; nt++) {
            int col = hf * 64 + nt * 8 + 2 * (lane & 3);
            float v00 = fmaxf(acc[nt][0] + S->bb[col],     0.0f) * s0;
            float v01 = fmaxf(acc[nt][1] + S->bb[col + 1], 0.0f) * s0;
            float v10 = fmaxf(acc[nt][2] + S->bb[col],     0.0f) * s1;
            float v11 = fmaxf(acc[nt][3] + S->bb[col + 1], 0.0f) * s1;
            *(float2*)&S->xs[r0][col]     = make_float2(v00, v01);
            *(float2*)&S->xs[r0 + 8][col] = make_float2(v10, v11);
        }
    }
    __syncthreads();

    pool_xs(S, K1);

    // ---------- level 2 ----------
    if (tid < 128) { S->bb[tid] = b2[tid]; S->ps[tid] = p2[tid]; }
    stage_chunk(S, 0, w2n, w2r, 0);      // prefetch chunk 0 under agg
    level_agg2(S, K1, S->c2o[0]);
    level_gemm_topk(S, K1, K2, S->rns[1], w2n, w2r);

    // compose maps with topk2 result (newloc/kept in K1-current space)
    for (int r = tid; r < K2; r += NT) S->c2o[1][r] = S->c2o[0][S->kept[r]];
    for (int ov = tid; ov < NP; ov += NT) {
        short c = S->o2c[ov];
        S->o2c[ov] = (c >= 0) ? S->newloc[c] : (short)-1;
    }

    // ---------- level 3 ----------
    if (tid < 128) { S->bb[tid] = b3[tid]; S->ps[tid] = p3[tid]; }
    stage_chunk(S, 0, w3n, w3r, 0);
    level_agg2(S, K2, S->c2o[1]);        // leading sync covers compose writes
    level_gemm_topk(S, K2, K3, S->rns[2], w3n, w3r);

    __syncthreads();                     // harr visibility for the MLP head

    // ---------- MLP head (coalesced warp-cooperative, float4) ----------
    {
        float4 h0 = *(const float4*)&S->harr[lane * 4];
        float4 h1v = *(const float4*)&S->harr[128 + lane * 4];
        for (int c = w; c < 128; c += NW) {
            const float4* w4 = (const float4*)(lw1 + c * 256);
            float4 w0 = w4[lane], w1v = w4[lane + 32];
            float a = w0.x*h0.x + w0.y*h0.y + w0.z*h0.z + w0.w*h0.w
                    + w1v.x*h1v.x + w1v.y*h1v.y + w1v.z*h1v.z + w1v.w*h1v.w;
#pragma unroll
            for (int o = 16; o; o >>= 1) a += __shfl_xor_sync(0xffffffffu, a, o);
            if (lane == 0) S->h1[c] = fmaxf(a + lb1[c], 0.0f);
        }
    }
    __syncthreads();
    {
        float4 g0 = *(const float4*)&S->h1[lane * 4];
        for (int c = w; c < 64; c += NW) {
            float4 w0 = ((const float4*)(lw2 + c * 128))[lane];
            float a = w0.x*g0.x + w0.y*g0.y + w0.z*g0.z + w0.w*g0.w;
#pragma unroll
            for (int o = 16; o; o >>= 1) a += __shfl_xor_sync(0xffffffffu, a, o);
            if (lane == 0) S->h2[c] = fmaxf(a + lb2[c], 0.0f);
        }
    }
    __syncthreads();
    if (w == 0) {
        float a = 0.0f;
#pragma unroll
        for (int j = 0; j < 2; j++)
            a += lw3[j*32 + lane] * S->h2[j*32 + lane];
#pragma unroll
        for (int o = 16; o; o >>= 1) a += __shfl_xor_sync(0xffffffffu, a, o);
        if (lane == 0) out[b] = 1.0f / (1.0f + expf(-(a + lb3[0])));
    }
}

// ---------------- launch ------------------------------------------------------
extern "C" void kernel_launch(void* const* d_in, const int* in_sizes, int n_in,
                              void* d_out, int out_size) {
    const int*   node_ids   = (const int*)d_in[0];
    const int*   edge_index = (const int*)d_in[1];
    const float* emb  = (const float*)d_in[3];
    const float* w1n  = (const float*)d_in[4];
    const float* w1r  = (const float*)d_in[5];
    const float* b1   = (const float*)d_in[6];
    const float* w2n  = (const float*)d_in[7];
    const float* w2r  = (const float*)d_in[8];
    const float* b2   = (const float*)d_in[9];
    const float* w3n  = (const float*)d_in[10];
    const float* w3r  = (const float*)d_in[11];
    const float* b3   = (const float*)d_in[12];
    const float* p1   = (const float*)d_in[13];
    const float* p2   = (const float*)d_in[14];
    const float* p3   = (const float*)d_in[15];
    const float* lw1  = (const float*)d_in[16];
    const float* lb1  = (const float*)d_in[17];
    const float* lw2  = (const float*)d_in[18];
    const float* lb2  = (const float*)d_in[19];
    const float* lw3  = (const float*)d_in[20];
    const float* lb3  = (const float*)d_in[21];
    float* out = (float*)d_out;

    static int smem_set = 0;
    if (!smem_set) {
        cudaFuncSetAttribute(mega_kernel,
                             cudaFuncAttributeMaxDynamicSharedMemorySize,
                             (int)sizeof(MegaSm));
        smem_set = 1;
    }

    mega_kernel<<<B, NT, sizeof(MegaSm)>>>(
        node_ids, edge_index, emb,
        w1n, w1r, b1, p1,
        w2n, w2r, b2, p2,
        w3n, w3r, b3, p3,
        lw1, lb1, lw2, lb2, lw3, lb3, out);
}